// round 4
// baseline (speedup 1.0000x reference)
#include <cuda_runtime.h>
#include <cuda_bf16.h>
#include <math.h>

// Problem constants
#define Bsz 256
#define Nn  128
#define Ff  133
#define KP  144          // Ff padded to multiple of 16
#define Hh  8
#define NHID 64
#define HID 300
#define FP_DIM 1489
#define KP1 1536         // FP_DIM padded
#define FSPLIT 8
#define FCHUNK 192       // KP1 / FSPLIT, multiple of 16
#define FP2 512
#define HD (Hh*NHID)     // 512
#define ALPHA 0.2f
#define NEGV (-9e15f)

// ---------------- scratch (device globals; no allocation allowed) ----------------
__device__ float g_Apad[(size_t)Bsz*Nn * KP];    // atom_feats zero-padded to K=144
__device__ float g_Wt  [KP * HD];                // W_heads transposed (KP, H*NHID)
__device__ float g_Wh  [(size_t)Bsz*Nn * HD];    // layer1 features [b,n,h*64+d]
__device__ float g_h   [(size_t)Bsz*Nn * HD];    // layer1 attention output
__device__ float g_Wh2 [(size_t)Bsz*Nn * HID];   // layer2 features [b,n,hid]
__device__ float g_P   [(size_t)Bsz*Nn * Nn];    // layer2 probs
__device__ float g_O   [(size_t)Bsz*Nn * HID];   // layer2 elu(attn@Wh2)
__device__ float g_gat [Bsz * HID];              // mean log_softmax per graph
__device__ float g_fppad[(size_t)Bsz * KP1];     // fp zero-padded
__device__ float g_w1pad[(size_t)KP1 * FP2];     // fc1_w zero-padded
__device__ float g_part[(size_t)FSPLIT * Bsz * FP2]; // fc1 split-K partials
__device__ float g_t1  [Bsz * FP2];              // fpn hidden (relu(fp@fc1))

// ---------------- helpers ----------------
__device__ __forceinline__ float warp_sum(float v) {
    #pragma unroll
    for (int o = 16; o; o >>= 1) v += __shfl_down_sync(0xffffffffu, v, o);
    return v;
}
__device__ __forceinline__ float warp_max(float v) {
    #pragma unroll
    for (int o = 16; o; o >>= 1) v = fmaxf(v, __shfl_down_sync(0xffffffffu, v, o));
    return v;
}

// ---------------- pad kernels ----------------------------------------------------
__global__ void pad_atoms(const float* __restrict__ src) {
    int t = blockIdx.x * blockDim.x + threadIdx.x;
    if (t >= Bsz * Nn * KP) return;
    int k = t % KP;
    int r = t / KP;
    g_Apad[t] = (k < Ff) ? src[(size_t)r * Ff + k] : 0.f;
}
__global__ void transpose_wheads(const float* __restrict__ W_heads) {
    int t = blockIdx.x * blockDim.x + threadIdx.x;
    if (t >= KP * HD) return;
    int f = t / HD;
    int r = t - f * HD;
    int h = r >> 6, d = r & 63;
    g_Wt[t] = (f < Ff) ? W_heads[((size_t)h * Ff + f) * NHID + d] : 0.f;
}
__global__ void pad_fp(const float* __restrict__ fp) {
    int t = blockIdx.x * blockDim.x + threadIdx.x;
    if (t >= Bsz * KP1) return;
    int k = t % KP1, r = t / KP1;
    g_fppad[t] = (k < FP_DIM) ? fp[(size_t)r * FP_DIM + k] : 0.f;
}
__global__ void pad_w1(const float* __restrict__ w) {
    int t = blockIdx.x * blockDim.x + threadIdx.x;
    if (t >= KP1 * FP2) return;
    int r = t / FP2;
    g_w1pad[t] = (r < FP_DIM) ? w[t] : 0.f;
}

// ============ gemm_db: double-buffered 128x128 tile, 8x8 accum ====================
// C = act(A(MxK,lda) @ B(KxN,ldb)), batched via blockIdx.z with element offsets.
// Requirements: M%128==0, K%16==0, lda/ldb/ldc %4==0. act: 0 none, 2 elu.
__global__ __launch_bounds__(256, 2) void gemm_db(
    const float* __restrict__ A, const float* __restrict__ B, float* __restrict__ C,
    int M, int N, int K, int lda, int ldb, int ldc,
    long long bA, long long bB, long long bC, int act)
{
    __shared__ float As[2][128][20];   // [m][k] (16 k + pad)
    __shared__ float Bs[2][16][132];   // [k][n] (128 n + pad)
    A += (long long)blockIdx.z * bA;
    B += (long long)blockIdx.z * bB;
    C += (long long)blockIdx.z * bC;

    const int tid = threadIdx.x;
    const int tx = tid & 15, ty = tid >> 4;
    const int row0 = blockIdx.y * 128, col0 = blockIdx.x * 128;

    const int ar  = tid >> 2;           // 0..63 (second chunk +64)
    const int aq  = (tid & 3) << 2;     // 0,4,8,12
    const int bk  = tid >> 5;           // 0..7 (second chunk +8)
    const int bc4 = (tid & 31) << 2;    // 0..124
    const int gc  = col0 + bc4;

    const int nsteps = K >> 4;
    float4 ra0, ra1, rb0, rb1;

    // ---- load step 0 ----
    {
        const int k0 = 0;
        ra0 = *(const float4*)(A + (size_t)(row0 + ar)      * lda + k0 + aq);
        ra1 = *(const float4*)(A + (size_t)(row0 + ar + 64) * lda + k0 + aq);
        if (gc + 4 <= N) {
            rb0 = *(const float4*)(B + (size_t)(k0 + bk)     * ldb + gc);
            rb1 = *(const float4*)(B + (size_t)(k0 + bk + 8) * ldb + gc);
        } else {
            float t0[4], t1[4];
            #pragma unroll
            for (int q = 0; q < 4; q++) {
                t0[q] = (gc + q < N) ? B[(size_t)(k0 + bk)     * ldb + gc + q] : 0.f;
                t1[q] = (gc + q < N) ? B[(size_t)(k0 + bk + 8) * ldb + gc + q] : 0.f;
            }
            rb0 = make_float4(t0[0], t0[1], t0[2], t0[3]);
            rb1 = make_float4(t1[0], t1[1], t1[2], t1[3]);
        }
    }
    *(float4*)&As[0][ar][aq]      = ra0;
    *(float4*)&As[0][ar + 64][aq] = ra1;
    *(float4*)&Bs[0][bk][bc4]     = rb0;
    *(float4*)&Bs[0][bk + 8][bc4] = rb1;
    __syncthreads();

    float acc[8][8] = {};
    for (int s = 0; s < nsteps; s++) {
        const int cur = s & 1;
        if (s + 1 < nsteps) {
            const int k0 = (s + 1) << 4;
            ra0 = *(const float4*)(A + (size_t)(row0 + ar)      * lda + k0 + aq);
            ra1 = *(const float4*)(A + (size_t)(row0 + ar + 64) * lda + k0 + aq);
            if (gc + 4 <= N) {
                rb0 = *(const float4*)(B + (size_t)(k0 + bk)     * ldb + gc);
                rb1 = *(const float4*)(B + (size_t)(k0 + bk + 8) * ldb + gc);
            } else {
                float t0[4], t1[4];
                #pragma unroll
                for (int q = 0; q < 4; q++) {
                    t0[q] = (gc + q < N) ? B[(size_t)(k0 + bk)     * ldb + gc + q] : 0.f;
                    t1[q] = (gc + q < N) ? B[(size_t)(k0 + bk + 8) * ldb + gc + q] : 0.f;
                }
                rb0 = make_float4(t0[0], t0[1], t0[2], t0[3]);
                rb1 = make_float4(t1[0], t1[1], t1[2], t1[3]);
            }
        }
        #pragma unroll
        for (int k = 0; k < 16; k++) {
            float a[8], b[8];
            #pragma unroll
            for (int i = 0; i < 8; i++) a[i] = As[cur][ty + 16 * i][k];
            #pragma unroll
            for (int j = 0; j < 8; j++) b[j] = Bs[cur][k][tx + 16 * j];
            #pragma unroll
            for (int i = 0; i < 8; i++)
                #pragma unroll
                for (int j = 0; j < 8; j++)
                    acc[i][j] = fmaf(a[i], b[j], acc[i][j]);
        }
        if (s + 1 < nsteps) {
            const int nxt = cur ^ 1;
            *(float4*)&As[nxt][ar][aq]      = ra0;
            *(float4*)&As[nxt][ar + 64][aq] = ra1;
            *(float4*)&Bs[nxt][bk][bc4]     = rb0;
            *(float4*)&Bs[nxt][bk + 8][bc4] = rb1;
            __syncthreads();
        }
    }

    #pragma unroll
    for (int i = 0; i < 8; i++) {
        const int r = row0 + ty + 16 * i;
        #pragma unroll
        for (int j = 0; j < 8; j++) {
            const int c = col0 + tx + 16 * j;
            if (c < N) {
                float v = acc[i][j];
                if (act == 2) v = (v > 0.f) ? v : expm1f(v);
                C[(size_t)r * ldc + c] = v;
            }
        }
    }
}

// ---------------- fc1 reduce ------------------------------------------------------
__global__ void fc1_reduce(const float* __restrict__ fc1_b) {
    int t = blockIdx.x * blockDim.x + threadIdx.x;
    if (t >= Bsz * FP2) return;
    float s = 0.f;
    #pragma unroll
    for (int z = 0; z < FSPLIT; z++) s += g_part[(size_t)z * Bsz * FP2 + t];
    g_t1[t] = fmaxf(s + fc1_b[t & (FP2 - 1)], 0.f);
}

// ---------------- gat1: fused scores + softmax + smem GEMM AV --------------------
// dyn smem: Ws[128*68] + Ps[128*132] + ss[128] + dd[128]
#define G1_SM ((128*68 + 128*132 + 256) * 4)
__global__ __launch_bounds__(256) void gat1_kernel(const float* __restrict__ a_heads,
                                                   const int* __restrict__ adj)
{
    extern __shared__ float sm[];
    float* Ws = sm;                 // [j*68 + d]
    float* Ps = Ws + 128 * 68;      // [i*132 + j]
    float* ss = Ps + 128 * 132;
    float* dd = ss + 128;

    const int b = blockIdx.x >> 3;
    const int h = blockIdx.x & 7;
    const int tid = threadIdx.x, warp = tid >> 5, lane = tid & 31;
    const float* whbase = g_Wh + ((size_t)b * Nn) * HD + h * NHID;

    for (int s = tid; s < 2048; s += 256) {
        int j = s >> 4, q = (s & 15) << 2;
        float4 v = *reinterpret_cast<const float4*>(whbase + (size_t)j * HD + q);
        *reinterpret_cast<float4*>(&Ws[j * 68 + q]) = v;
    }
    __syncthreads();

    const float* a1 = a_heads + h * (2 * NHID);
    const float* a2 = a1 + NHID;
    for (int j = warp; j < 128; j += 8) {
        float w0 = Ws[j * 68 + lane], w1 = Ws[j * 68 + lane + 32];
        float s1 = fmaf(w0, a1[lane], w1 * a1[lane + 32]);
        float s2 = fmaf(w0, a2[lane], w1 * a2[lane + 32]);
        s1 = warp_sum(s1); s2 = warp_sum(s2);
        if (lane == 0) { ss[j] = s1; dd[j] = s2; }
    }
    __syncthreads();

    const int* adjb = adj + (size_t)b * Nn * Nn;
    for (int i = warp; i < 128; i += 8) {
        const float si = ss[i];
        const int* ar = adjb + i * Nn;
        float ev[4];
        #pragma unroll
        for (int q = 0; q < 4; q++) {
            int j = lane + q * 32;
            float e = si + dd[j];
            e = (e > 0.f) ? e : ALPHA * e;
            ev[q] = (ar[j] > 0) ? e : NEGV;
        }
        float mx = fmaxf(fmaxf(ev[0], ev[1]), fmaxf(ev[2], ev[3]));
        mx = warp_max(mx);
        mx = __shfl_sync(0xffffffffu, mx, 0);
        float ls = 0.f;
        #pragma unroll
        for (int q = 0; q < 4; q++) { ev[q] = __expf(ev[q] - mx); ls += ev[q]; }
        ls = warp_sum(ls);
        ls = __shfl_sync(0xffffffffu, ls, 0);
        const float inv = 1.f / ls;
        #pragma unroll
        for (int q = 0; q < 4; q++) Ps[i * 132 + lane + 32 * q] = ev[q] * inv;
    }
    __syncthreads();

    // AV: O(128x64) = P(128x128) @ Ws(128x64), 8x4 accum per thread
    const int tx = tid & 15, ty = tid >> 4;
    float acc[8][4] = {};
    #pragma unroll 4
    for (int k = 0; k < 128; k++) {
        float a[8], bv[4];
        #pragma unroll
        for (int i = 0; i < 8; i++) a[i] = Ps[(ty + 16 * i) * 132 + k];
        #pragma unroll
        for (int j = 0; j < 4; j++) bv[j] = Ws[k * 68 + tx + 16 * j];
        #pragma unroll
        for (int i = 0; i < 8; i++)
            #pragma unroll
            for (int j = 0; j < 4; j++)
                acc[i][j] = fmaf(a[i], bv[j], acc[i][j]);
    }
    float* outb = g_h + ((size_t)b * Nn) * HD + h * NHID;
    #pragma unroll
    for (int i = 0; i < 8; i++) {
        int r = ty + 16 * i;
        #pragma unroll
        for (int j = 0; j < 4; j++) {
            int c = tx + 16 * j;
            float v = acc[i][j];
            v = (v > 0.f) ? v : expm1f(v);
            outb[(size_t)r * HD + c] = v;
        }
    }
}

// ---------------- gat2 scores + probs (merged) -----------------------------------
__global__ __launch_bounds__(256) void sp2_kernel(const float* __restrict__ a_out,
                                                  const int* __restrict__ adj)
{
    __shared__ float ss[128], dd[128];
    const int b = blockIdx.x;
    const int tid = threadIdx.x, warp = tid >> 5, lane = tid & 31;
    const float* W = g_Wh2 + (size_t)b * Nn * HID;

    for (int j = warp; j < 128; j += 8) {
        float s1 = 0.f, s2 = 0.f;
        #pragma unroll
        for (int t = 0; t < 10; t++) {
            int d = lane + 32 * t;
            if (d < HID) {
                float w = W[(size_t)j * HID + d];
                s1 = fmaf(w, a_out[d], s1);
                s2 = fmaf(w, a_out[HID + d], s2);
            }
        }
        s1 = warp_sum(s1); s2 = warp_sum(s2);
        if (lane == 0) { ss[j] = s1; dd[j] = s2; }
    }
    __syncthreads();

    for (int i = warp; i < 128; i += 8) {
        const float si = ss[i];
        const int* ar = adj + ((size_t)b * Nn + i) * Nn;
        float ev[4];
        #pragma unroll
        for (int q = 0; q < 4; q++) {
            int j = lane + q * 32;
            float e = si + dd[j];
            e = (e > 0.f) ? e : ALPHA * e;
            ev[q] = (ar[j] > 0) ? e : NEGV;
        }
        float mx = fmaxf(fmaxf(ev[0], ev[1]), fmaxf(ev[2], ev[3]));
        mx = warp_max(mx);
        mx = __shfl_sync(0xffffffffu, mx, 0);
        float ls = 0.f;
        #pragma unroll
        for (int q = 0; q < 4; q++) { ev[q] = __expf(ev[q] - mx); ls += ev[q]; }
        ls = warp_sum(ls);
        ls = __shfl_sync(0xffffffffu, ls, 0);
        const float inv = 1.f / ls;
        float* pr = g_P + ((size_t)b * Nn + i) * Nn;
        #pragma unroll
        for (int q = 0; q < 4; q++) pr[lane + 32 * q] = ev[q] * inv;
    }
}

// ---------------- gat2: log_softmax + mean ---------------------------------------
__global__ __launch_bounds__(256) void ls2_kernel()
{
    __shared__ float acc[8 * HID];
    const int b = blockIdx.x;
    const int tid = threadIdx.x, warp = tid >> 5, lane = tid & 31;
    for (int t = tid; t < 8 * HID; t += 256) acc[t] = 0.f;
    __syncthreads();

    const float* O = g_O + (size_t)b * Nn * HID;
    float* accw = acc + warp * HID;
    for (int i = warp; i < 128; i += 8) {
        float o[10];
        #pragma unroll
        for (int t = 0; t < 10; t++) {
            int d = lane + 32 * t;
            o[t] = (d < HID) ? O[(size_t)i * HID + d] : -1e30f;
        }
        float m = o[0];
        #pragma unroll
        for (int t = 1; t < 10; t++) m = fmaxf(m, o[t]);
        m = warp_max(m);
        m = __shfl_sync(0xffffffffu, m, 0);
        float se = 0.f;
        #pragma unroll
        for (int t = 0; t < 10; t++) se += __expf(o[t] - m);
        se = warp_sum(se);
        se = __shfl_sync(0xffffffffu, se, 0);
        const float lse = m + logf(se);
        #pragma unroll
        for (int t = 0; t < 10; t++) {
            int d = lane + 32 * t;
            if (d < HID) accw[d] += o[t] - lse;
        }
    }
    __syncthreads();
    for (int d = tid; d < HID; d += 256) {
        float s = 0.f;
        #pragma unroll
        for (int w = 0; w < 8; w++) s += acc[w * HID + d];
        g_gat[b * HID + d] = s * (1.f / 128.f);
    }
}

// ---------------- head: fc2 + fc_gat + fc_fpn + ffn1 + ffn2 + sigmoid ------------
#define HB 4
__global__ __launch_bounds__(256) void head_fused(
    const float* __restrict__ fc2_w, const float* __restrict__ fc2_b,
    const float* __restrict__ Wg,    const float* __restrict__ bg,
    const float* __restrict__ Wf,    const float* __restrict__ bf,
    const float* __restrict__ W1,    const float* __restrict__ b1,
    const float* __restrict__ w2,    const float* __restrict__ b2,
    float* __restrict__ out)
{
    __shared__ float t1s [HB][512];
    __shared__ float gats[HB][HID];
    __shared__ float fpns[HB][HID];
    __shared__ float us  [HB][HID];
    __shared__ float vs  [HB][HID];
    __shared__ float ys  [HB][HID];

    const int b0 = blockIdx.x * HB;
    const int tid = threadIdx.x;

    for (int t = tid; t < HB * 512; t += 256) {
        int r = t >> 9;
        t1s[r][t & 511] = g_t1[(size_t)(b0 + r) * FP2 + (t & 511)];
    }
    for (int t = tid; t < HB * HID; t += 256) {
        int r = t / HID, c = t - r * HID;
        gats[r][c] = g_gat[(size_t)(b0 + r) * HID + c];
    }
    __syncthreads();

    for (int c = tid; c < HID; c += 256) {
        float a[HB] = {};
        #pragma unroll 4
        for (int k = 0; k < 512; k++) {
            float w = fc2_w[(size_t)k * HID + c];
            #pragma unroll
            for (int r = 0; r < HB; r++) a[r] = fmaf(t1s[r][k], w, a[r]);
        }
        float bb = fc2_b[c];
        #pragma unroll
        for (int r = 0; r < HB; r++) fpns[r][c] = a[r] + bb;
    }
    __syncthreads();

    for (int c = tid; c < HID; c += 256) {
        float a[HB] = {}, e[HB] = {};
        #pragma unroll 4
        for (int k = 0; k < HID; k++) {
            float wg = Wg[(size_t)k * HID + c];
            float wf = Wf[(size_t)k * HID + c];
            #pragma unroll
            for (int r = 0; r < HB; r++) {
                a[r] = fmaf(gats[r][k], wg, a[r]);
                e[r] = fmaf(fpns[r][k], wf, e[r]);
            }
        }
        float bbg = bg[c], bbf = bf[c];
        #pragma unroll
        for (int r = 0; r < HB; r++) {
            us[r][c] = fmaxf(a[r] + bbg, 0.f);
            vs[r][c] = fmaxf(e[r] + bbf, 0.f);
        }
    }
    __syncthreads();

    for (int c = tid; c < HID; c += 256) {
        float a[HB] = {};
        #pragma unroll 4
        for (int k = 0; k < HID; k++) {
            float w = W1[(size_t)k * HID + c];
            #pragma unroll
            for (int r = 0; r < HB; r++) a[r] = fmaf(us[r][k], w, a[r]);
        }
        #pragma unroll 4
        for (int k = 0; k < HID; k++) {
            float w = W1[(size_t)(k + HID) * HID + c];
            #pragma unroll
            for (int r = 0; r < HB; r++) a[r] = fmaf(vs[r][k], w, a[r]);
        }
        float bb = b1[c];
        #pragma unroll
        for (int r = 0; r < HB; r++) ys[r][c] = fmaxf(a[r] + bb, 0.f);
    }
    __syncthreads();

    const int warp = tid >> 5, lane = tid & 31;
    if (warp < HB) {
        float s = 0.f;
        for (int k = lane; k < HID; k += 32) s = fmaf(ys[warp][k], w2[k], s);
        s = warp_sum(s);
        if (lane == 0) out[b0 + warp] = 1.f / (1.f + expf(-(s + b2[0])));
    }
}

// ---------------- launch ----------------
extern "C" void kernel_launch(void* const* d_in, const int* in_sizes, int n_in,
                              void* d_out, int out_size)
{
    const float* atom_feats = (const float*)d_in[0];
    const float* fp         = (const float*)d_in[1];
    const float* W_heads    = (const float*)d_in[2];
    const float* a_heads    = (const float*)d_in[3];
    const float* W_out      = (const float*)d_in[4];
    const float* a_out      = (const float*)d_in[5];
    const float* fc1_w      = (const float*)d_in[6];
    const float* fc1_b      = (const float*)d_in[7];
    const float* fc2_w      = (const float*)d_in[8];
    const float* fc2_b      = (const float*)d_in[9];
    const float* fc_gat_w   = (const float*)d_in[10];
    const float* fc_gat_b   = (const float*)d_in[11];
    const float* fc_fpn_w   = (const float*)d_in[12];
    const float* fc_fpn_b   = (const float*)d_in[13];
    const float* ffn_w1     = (const float*)d_in[14];
    const float* ffn_b1     = (const float*)d_in[15];
    const float* ffn_w2     = (const float*)d_in[16];
    const float* ffn_b2     = (const float*)d_in[17];
    const int*   adj        = (const int*)  d_in[18];
    float* out = (float*)d_out;

    float *pApad, *pWt, *pWh, *ph, *pWh2, *pP, *pO, *pFp, *pW1, *pPart;
    cudaGetSymbolAddress((void**)&pApad, g_Apad);
    cudaGetSymbolAddress((void**)&pWt,   g_Wt);
    cudaGetSymbolAddress((void**)&pWh,   g_Wh);
    cudaGetSymbolAddress((void**)&ph,    g_h);
    cudaGetSymbolAddress((void**)&pWh2,  g_Wh2);
    cudaGetSymbolAddress((void**)&pP,    g_P);
    cudaGetSymbolAddress((void**)&pO,    g_O);
    cudaGetSymbolAddress((void**)&pFp,   g_fppad);
    cudaGetSymbolAddress((void**)&pW1,   g_w1pad);
    cudaGetSymbolAddress((void**)&pPart, g_part);

    cudaFuncSetAttribute(gat1_kernel, cudaFuncAttributeMaxDynamicSharedMemorySize, G1_SM);

    // 1: pad A
    pad_atoms<<<(Bsz * Nn * KP + 255) / 256, 256>>>(atom_feats);
    // 2: transpose W_heads
    transpose_wheads<<<(KP * HD + 255) / 256, 256>>>(W_heads);
    // 3: K1  Wh = Apad(32768x144) @ Wt(144x512)
    gemm_db<<<dim3(HD / 128, (Bsz * Nn) / 128, 1), 256>>>(
        pApad, pWt, pWh, Bsz * Nn, HD, KP, KP, HD, HD, 0, 0, 0, 0);
    // 4: gat1  <-- ncu capture target (4th launch)
    gat1_kernel<<<Bsz * Hh, 256, G1_SM>>>(a_heads, adj);
    // 5,6: fp pads
    pad_fp<<<(Bsz * KP1 + 255) / 256, 256>>>(fp);
    pad_w1<<<(KP1 * FP2 + 255) / 256, 256>>>(fc1_w);
    // 7,8: fc1 split-K + reduce
    gemm_db<<<dim3(FP2 / 128, Bsz / 128, FSPLIT), 256>>>(
        pFp, pW1, pPart, Bsz, FP2, FCHUNK, KP1, FP2, FP2,
        (long long)FCHUNK, (long long)FCHUNK * FP2, (long long)Bsz * FP2, 0);
    fc1_reduce<<<(Bsz * FP2 + 255) / 256, 256>>>(fc1_b);
    // 9: K3  Wh2 = h(32768x512) @ W_out(512x300)
    gemm_db<<<dim3((HID + 127) / 128, (Bsz * Nn) / 128, 1), 256>>>(
        ph, W_out, pWh2, Bsz * Nn, HID, HD, HD, HID, HID, 0, 0, 0, 0);
    // 10: gat2 scores + probs
    sp2_kernel<<<Bsz, 256>>>(a_out, adj);
    // 11: gat2 AV batched GEMM + elu
    gemm_db<<<dim3((HID + 127) / 128, 1, Bsz), 256>>>(
        pP, pWh2, pO, Nn, HID, Nn, Nn, HID, HID,
        (long long)Nn * Nn, (long long)Nn * HID, (long long)Nn * HID, 2);
    // 12: gat2 log_softmax + mean
    ls2_kernel<<<Bsz, 256>>>();
    // 13: fused head
    head_fused<<<Bsz / HB, 256>>>(
        fc2_w, fc2_b, fc_gat_w, fc_gat_b, fc_fpn_w, fc_fpn_b,
        ffn_w1, ffn_b1, ffn_w2, ffn_b2, out);
}

// round 5
// speedup vs baseline: 1.6467x; 1.6467x over previous
#include <cuda_runtime.h>
#include <cuda_bf16.h>
#include <math.h>

// Problem constants
#define Bsz 256
#define Nn  128
#define Ff  133
#define KP  144          // Ff padded to multiple of 16
#define Hh  8
#define NHID 64
#define HID 300
#define FP_DIM 1489
#define KP1 1536         // FP_DIM padded
#define FSPLIT 8
#define FCHUNK 192       // KP1 / FSPLIT
#define FP2 512
#define HD (Hh*NHID)     // 512
#define ALPHA 0.2f
#define NEGV (-9e15f)

// ---------------- scratch (device globals; no allocation allowed) ----------------
__device__ float g_Apad[(size_t)Bsz*Nn * KP];
__device__ float g_Wt  [KP * HD];
__device__ float g_Wh  [(size_t)Bsz*Nn * HD];
__device__ float g_h   [(size_t)Bsz*Nn * HD];
__device__ float g_Wh2 [(size_t)Bsz*Nn * HID];
__device__ float g_P   [(size_t)Bsz*Nn * Nn];
__device__ float g_O   [(size_t)Bsz*Nn * HID];
__device__ float g_gat [Bsz * HID];
__device__ float g_fppad[(size_t)Bsz * KP1];
__device__ float g_w1pad[(size_t)KP1 * FP2];
__device__ float g_part[(size_t)FSPLIT * Bsz * FP2];
__device__ float g_t1  [Bsz * FP2];

// ---------------- f32x2 helpers ----------------
#define FMA2(acc, a, b) \
    asm("fma.rn.f32x2 %0, %1, %2, %0;" : "+l"(acc) : "l"(a), "l"(b))

__device__ __forceinline__ unsigned long long ld2(const float* p) {
    return *reinterpret_cast<const unsigned long long*>(p);
}
__device__ __forceinline__ unsigned long long dup2(float x) {
    unsigned long long r;
    asm("mov.b64 %0, {%1, %1};" : "=l"(r) : "r"(__float_as_uint(x)));
    return r;
}
__device__ __forceinline__ float lo32(unsigned long long v) {
    return __uint_as_float((unsigned)v);
}
__device__ __forceinline__ float hi32(unsigned long long v) {
    return __uint_as_float((unsigned)(v >> 32));
}

__device__ __forceinline__ float warp_sum(float v) {
    #pragma unroll
    for (int o = 16; o; o >>= 1) v += __shfl_down_sync(0xffffffffu, v, o);
    return v;
}
__device__ __forceinline__ float warp_max(float v) {
    #pragma unroll
    for (int o = 16; o; o >>= 1) v = fmaxf(v, __shfl_down_sync(0xffffffffu, v, o));
    return v;
}

// ---------------- pad kernels ----------------------------------------------------
__global__ void pad_atoms(const float* __restrict__ src) {
    int t = blockIdx.x * blockDim.x + threadIdx.x;
    if (t >= Bsz * Nn * KP) return;
    int k = t % KP;
    int r = t / KP;
    g_Apad[t] = (k < Ff) ? src[(size_t)r * Ff + k] : 0.f;
}
__global__ void transpose_wheads(const float* __restrict__ W_heads) {
    int t = blockIdx.x * blockDim.x + threadIdx.x;
    if (t >= KP * HD) return;
    int f = t / HD;
    int r = t - f * HD;
    int h = r >> 6, d = r & 63;
    g_Wt[t] = (f < Ff) ? W_heads[((size_t)h * Ff + f) * NHID + d] : 0.f;
}
__global__ void pad_fp(const float* __restrict__ fp) {
    int t = blockIdx.x * blockDim.x + threadIdx.x;
    if (t >= Bsz * KP1) return;
    int k = t % KP1, r = t / KP1;
    g_fppad[t] = (k < FP_DIM) ? fp[(size_t)r * FP_DIM + k] : 0.f;
}
__global__ void pad_w1(const float* __restrict__ w) {
    int t = blockIdx.x * blockDim.x + threadIdx.x;
    if (t >= KP1 * FP2) return;
    int r = t / FP2;
    g_w1pad[t] = (r < FP_DIM) ? w[t] : 0.f;
}

// ============ gemm_f2: 128x64 tile, f32x2 packed FMA, 8 rows x 4 cols/thread =====
// C = act(A(MxK,lda) @ B(KxN,ldb)); M%128==0, K%16==0, lda/ldb%4==0, ldc even.
// batched via blockIdx.z. act: 0 none, 2 elu.
__global__ __launch_bounds__(256) void gemm_f2(
    const float* __restrict__ A, const float* __restrict__ B, float* __restrict__ C,
    int M, int N, int K, int lda, int ldb, int ldc,
    long long bA, long long bB, long long bC, int act)
{
    __shared__ __align__(16) float As[16][132];   // [k][m] transposed
    __shared__ __align__(16) float Bd[16][136];   // [k][2n] duplicated cols (64 cols)
    A += (long long)blockIdx.z * bA;
    B += (long long)blockIdx.z * bB;
    C += (long long)blockIdx.z * bC;

    const int tid = threadIdx.x;
    const int tx = tid & 15, ty = tid >> 4;       // 16 x 16
    const int row0 = blockIdx.y * 128, col0 = blockIdx.x * 64;

    const int am  = tid >> 2;                     // 0..63 (+64 second)
    const int aq  = (tid & 3) << 2;               // 0,4,8,12
    const int bk  = tid >> 4;                     // 0..15
    const int bn4 = (tid & 15) << 2;              // 0..60
    const int gc  = col0 + bn4;

    unsigned long long acc[4][4];
    #pragma unroll
    for (int i = 0; i < 4; i++)
        #pragma unroll
        for (int j = 0; j < 4; j++) acc[i][j] = 0ull;

    for (int k0 = 0; k0 < K; k0 += 16) {
        // A fill: transpose into As[k][m]
        #pragma unroll
        for (int it = 0; it < 2; it++) {
            int m = am + it * 64;
            float4 v = *reinterpret_cast<const float4*>(A + (size_t)(row0 + m) * lda + k0 + aq);
            As[aq + 0][m] = v.x;
            As[aq + 1][m] = v.y;
            As[aq + 2][m] = v.z;
            As[aq + 3][m] = v.w;
        }
        // B fill: duplicated columns
        {
            float4 w;
            if (gc + 4 <= N) {
                w = *reinterpret_cast<const float4*>(B + (size_t)(k0 + bk) * ldb + gc);
            } else {
                w.x = (gc + 0 < N) ? B[(size_t)(k0 + bk) * ldb + gc + 0] : 0.f;
                w.y = (gc + 1 < N) ? B[(size_t)(k0 + bk) * ldb + gc + 1] : 0.f;
                w.z = (gc + 2 < N) ? B[(size_t)(k0 + bk) * ldb + gc + 2] : 0.f;
                w.w = (gc + 3 < N) ? B[(size_t)(k0 + bk) * ldb + gc + 3] : 0.f;
            }
            *reinterpret_cast<float4*>(&Bd[bk][2 * bn4])     = make_float4(w.x, w.x, w.y, w.y);
            *reinterpret_cast<float4*>(&Bd[bk][2 * bn4 + 4]) = make_float4(w.z, w.z, w.w, w.w);
        }
        __syncthreads();
        #pragma unroll
        for (int k = 0; k < 16; k++) {
            unsigned long long a2[4], b2[4];
            #pragma unroll
            for (int i = 0; i < 4; i++) a2[i] = ld2(&As[k][ty * 2 + 32 * i]);
            #pragma unroll
            for (int jj = 0; jj < 2; jj++) {
                ulonglong2 bb = *reinterpret_cast<const ulonglong2*>(&Bd[k][4 * tx + 64 * jj]);
                b2[2 * jj]     = bb.x;   // col 2tx+32jj   duplicated
                b2[2 * jj + 1] = bb.y;   // col 2tx+1+32jj duplicated
            }
            #pragma unroll
            for (int i = 0; i < 4; i++)
                #pragma unroll
                for (int j = 0; j < 4; j++)
                    FMA2(acc[i][j], a2[i], b2[j]);
        }
        __syncthreads();
    }

    // epilogue: rows r0 = row0+2ty+32i (lo), r0+1 (hi); cols c = col0+2tx+(j&1)+32(j>>1)
    #pragma unroll
    for (int i = 0; i < 4; i++) {
        const int r0 = row0 + 2 * ty + 32 * i;
        #pragma unroll
        for (int jj = 0; jj < 2; jj++) {
            const int c = col0 + 2 * tx + 32 * jj;
            if (c < N) {
                float v00 = lo32(acc[i][2 * jj]),     v10 = hi32(acc[i][2 * jj]);
                float v01 = lo32(acc[i][2 * jj + 1]), v11 = hi32(acc[i][2 * jj + 1]);
                if (act == 2) {
                    v00 = (v00 > 0.f) ? v00 : expm1f(v00);
                    v10 = (v10 > 0.f) ? v10 : expm1f(v10);
                    v01 = (v01 > 0.f) ? v01 : expm1f(v01);
                    v11 = (v11 > 0.f) ? v11 : expm1f(v11);
                }
                *reinterpret_cast<float2*>(C + (size_t)r0 * ldc + c)       = make_float2(v00, v01);
                *reinterpret_cast<float2*>(C + (size_t)(r0 + 1) * ldc + c) = make_float2(v10, v11);
            }
        }
    }
}

// ---------------- fc1 reduce ------------------------------------------------------
__global__ void fc1_reduce(const float* __restrict__ fc1_b) {
    int t = blockIdx.x * blockDim.x + threadIdx.x;
    if (t >= Bsz * FP2) return;
    float s = 0.f;
    #pragma unroll
    for (int z = 0; z < FSPLIT; z++) s += g_part[(size_t)z * Bsz * FP2 + t];
    g_t1[t] = fmaxf(s + fc1_b[t & (FP2 - 1)], 0.f);
}

// ---------------- gat1: scores + softmax + f32x2 smem GEMM AV --------------------
// dyn smem: Ws[128*68] + Pt[128*130] + ss[128] + dd[128] = 102,400 B
#define G1_SM ((128*68 + 128*130 + 256) * 4)
__global__ __launch_bounds__(256) void gat1_kernel(const float* __restrict__ a_heads,
                                                   const int* __restrict__ adj)
{
    extern __shared__ __align__(16) float sm[];
    float* Ws = sm;                 // [j*68 + d]
    float* Pt = Ws + 128 * 68;      // [j*130 + i]  transposed probs
    float* ss = Pt + 128 * 130;
    float* dd = ss + 128;

    const int b = blockIdx.x >> 3;
    const int h = blockIdx.x & 7;
    const int tid = threadIdx.x, warp = tid >> 5, lane = tid & 31;
    const float* whbase = g_Wh + ((size_t)b * Nn) * HD + h * NHID;

    for (int s = tid; s < 2048; s += 256) {
        int j = s >> 4, q = (s & 15) << 2;
        float4 v = *reinterpret_cast<const float4*>(whbase + (size_t)j * HD + q);
        *reinterpret_cast<float4*>(&Ws[j * 68 + q]) = v;
    }
    __syncthreads();

    const float* a1 = a_heads + h * (2 * NHID);
    const float* a2v = a1 + NHID;
    for (int j = warp; j < 128; j += 8) {
        float w0 = Ws[j * 68 + lane], w1 = Ws[j * 68 + lane + 32];
        float s1 = fmaf(w0, a1[lane], w1 * a1[lane + 32]);
        float s2 = fmaf(w0, a2v[lane], w1 * a2v[lane + 32]);
        s1 = warp_sum(s1); s2 = warp_sum(s2);
        if (lane == 0) { ss[j] = s1; dd[j] = s2; }
    }
    __syncthreads();

    const int* adjb = adj + (size_t)b * Nn * Nn;
    for (int i = warp; i < 128; i += 8) {
        const float si = ss[i];
        const int* ar = adjb + i * Nn;
        float ev[4];
        #pragma unroll
        for (int q = 0; q < 4; q++) {
            int j = lane + q * 32;
            float e = si + dd[j];
            e = (e > 0.f) ? e : ALPHA * e;
            ev[q] = (ar[j] > 0) ? e : NEGV;
        }
        float mx = fmaxf(fmaxf(ev[0], ev[1]), fmaxf(ev[2], ev[3]));
        mx = warp_max(mx);
        mx = __shfl_sync(0xffffffffu, mx, 0);
        float ls = 0.f;
        #pragma unroll
        for (int q = 0; q < 4; q++) { ev[q] = __expf(ev[q] - mx); ls += ev[q]; }
        ls = warp_sum(ls);
        ls = __shfl_sync(0xffffffffu, ls, 0);
        const float inv = 1.f / ls;
        #pragma unroll
        for (int q = 0; q < 4; q++) Pt[(lane + 32 * q) * 130 + i] = ev[q] * inv;
    }
    __syncthreads();

    // AV: O(128x64) = P(128x128) @ Ws(128x64) with f32x2 (rows packed in pairs)
    const int tx = tid & 15, ty = tid >> 4;
    unsigned long long acc[4][4];
    #pragma unroll
    for (int i = 0; i < 4; i++)
        #pragma unroll
        for (int j = 0; j < 4; j++) acc[i][j] = 0ull;

    #pragma unroll 4
    for (int k = 0; k < 128; k++) {
        unsigned long long a2[4], b2[4];
        #pragma unroll
        for (int i = 0; i < 4; i++) a2[i] = ld2(&Pt[k * 130 + 2 * ty + 32 * i]);
        #pragma unroll
        for (int jj = 0; jj < 4; jj++) b2[jj] = dup2(Ws[k * 68 + tx + 16 * jj]);
        #pragma unroll
        for (int i = 0; i < 4; i++)
            #pragma unroll
            for (int jj = 0; jj < 4; jj++)
                FMA2(acc[i][jj], a2[i], b2[jj]);
    }

    float* outb = g_h + ((size_t)b * Nn) * HD + h * NHID;
    #pragma unroll
    for (int i = 0; i < 4; i++) {
        const int r0 = 2 * ty + 32 * i;
        #pragma unroll
        for (int jj = 0; jj < 4; jj++) {
            const int c = tx + 16 * jj;
            float v0 = lo32(acc[i][jj]);
            float v1 = hi32(acc[i][jj]);
            v0 = (v0 > 0.f) ? v0 : expm1f(v0);
            v1 = (v1 > 0.f) ? v1 : expm1f(v1);
            outb[(size_t)r0 * HD + c]       = v0;
            outb[(size_t)(r0 + 1) * HD + c] = v1;
        }
    }
}

// ---------------- gat2 scores + probs (merged) -----------------------------------
__global__ __launch_bounds__(256) void sp2_kernel(const float* __restrict__ a_out,
                                                  const int* __restrict__ adj)
{
    __shared__ float ss[128], dd[128];
    const int b = blockIdx.x;
    const int tid = threadIdx.x, warp = tid >> 5, lane = tid & 31;
    const float* W = g_Wh2 + (size_t)b * Nn * HID;

    for (int j = warp; j < 128; j += 8) {
        float s1 = 0.f, s2 = 0.f;
        #pragma unroll
        for (int t = 0; t < 10; t++) {
            int d = lane + 32 * t;
            if (d < HID) {
                float w = W[(size_t)j * HID + d];
                s1 = fmaf(w, a_out[d], s1);
                s2 = fmaf(w, a_out[HID + d], s2);
            }
        }
        s1 = warp_sum(s1); s2 = warp_sum(s2);
        if (lane == 0) { ss[j] = s1; dd[j] = s2; }
    }
    __syncthreads();

    for (int i = warp; i < 128; i += 8) {
        const float si = ss[i];
        const int* ar = adj + ((size_t)b * Nn + i) * Nn;
        float ev[4];
        #pragma unroll
        for (int q = 0; q < 4; q++) {
            int j = lane + q * 32;
            float e = si + dd[j];
            e = (e > 0.f) ? e : ALPHA * e;
            ev[q] = (ar[j] > 0) ? e : NEGV;
        }
        float mx = fmaxf(fmaxf(ev[0], ev[1]), fmaxf(ev[2], ev[3]));
        mx = warp_max(mx);
        mx = __shfl_sync(0xffffffffu, mx, 0);
        float ls = 0.f;
        #pragma unroll
        for (int q = 0; q < 4; q++) { ev[q] = __expf(ev[q] - mx); ls += ev[q]; }
        ls = warp_sum(ls);
        ls = __shfl_sync(0xffffffffu, ls, 0);
        const float inv = 1.f / ls;
        float* pr = g_P + ((size_t)b * Nn + i) * Nn;
        #pragma unroll
        for (int q = 0; q < 4; q++) pr[lane + 32 * q] = ev[q] * inv;
    }
}

// ---------------- gat2: log_softmax + mean ---------------------------------------
__global__ __launch_bounds__(256) void ls2_kernel()
{
    __shared__ float acc[8 * HID];
    const int b = blockIdx.x;
    const int tid = threadIdx.x, warp = tid >> 5, lane = tid & 31;
    for (int t = tid; t < 8 * HID; t += 256) acc[t] = 0.f;
    __syncthreads();

    const float* O = g_O + (size_t)b * Nn * HID;
    float* accw = acc + warp * HID;
    for (int i = warp; i < 128; i += 8) {
        float o[10];
        #pragma unroll
        for (int t = 0; t < 10; t++) {
            int d = lane + 32 * t;
            o[t] = (d < HID) ? O[(size_t)i * HID + d] : -1e30f;
        }
        float m = o[0];
        #pragma unroll
        for (int t = 1; t < 10; t++) m = fmaxf(m, o[t]);
        m = warp_max(m);
        m = __shfl_sync(0xffffffffu, m, 0);
        float se = 0.f;
        #pragma unroll
        for (int t = 0; t < 10; t++) se += __expf(o[t] - m);
        se = warp_sum(se);
        se = __shfl_sync(0xffffffffu, se, 0);
        const float lse = m + logf(se);
        #pragma unroll
        for (int t = 0; t < 10; t++) {
            int d = lane + 32 * t;
            if (d < HID) accw[d] += o[t] - lse;
        }
    }
    __syncthreads();
    for (int d = tid; d < HID; d += 256) {
        float s = 0.f;
        #pragma unroll
        for (int w = 0; w < 8; w++) s += acc[w * HID + d];
        g_gat[b * HID + d] = s * (1.f / 128.f);
    }
}

// ---------------- head: fc2 + fc_gat + fc_fpn + ffn1 + ffn2 + sigmoid ------------
#define HB 4
__global__ __launch_bounds__(256) void head_fused(
    const float* __restrict__ fc2_w, const float* __restrict__ fc2_b,
    const float* __restrict__ Wg,    const float* __restrict__ bg,
    const float* __restrict__ Wf,    const float* __restrict__ bf,
    const float* __restrict__ W1,    const float* __restrict__ b1,
    const float* __restrict__ w2,    const float* __restrict__ b2,
    float* __restrict__ out)
{
    __shared__ float t1s [HB][512];
    __shared__ float gats[HB][HID];
    __shared__ float fpns[HB][HID];
    __shared__ float us  [HB][HID];
    __shared__ float vs  [HB][HID];
    __shared__ float ys  [HB][HID];

    const int b0 = blockIdx.x * HB;
    const int tid = threadIdx.x;

    for (int t = tid; t < HB * 512; t += 256) {
        int r = t >> 9;
        t1s[r][t & 511] = g_t1[(size_t)(b0 + r) * FP2 + (t & 511)];
    }
    for (int t = tid; t < HB * HID; t += 256) {
        int r = t / HID, c = t - r * HID;
        gats[r][c] = g_gat[(size_t)(b0 + r) * HID + c];
    }
    __syncthreads();

    for (int c = tid; c < HID; c += 256) {
        float a[HB] = {};
        #pragma unroll 4
        for (int k = 0; k < 512; k++) {
            float w = fc2_w[(size_t)k * HID + c];
            #pragma unroll
            for (int r = 0; r < HB; r++) a[r] = fmaf(t1s[r][k], w, a[r]);
        }
        float bb = fc2_b[c];
        #pragma unroll
        for (int r = 0; r < HB; r++) fpns[r][c] = a[r] + bb;
    }
    __syncthreads();

    for (int c = tid; c < HID; c += 256) {
        float a[HB] = {}, e[HB] = {};
        #pragma unroll 4
        for (int k = 0; k < HID; k++) {
            float wg = Wg[(size_t)k * HID + c];
            float wf = Wf[(size_t)k * HID + c];
            #pragma unroll
            for (int r = 0; r < HB; r++) {
                a[r] = fmaf(gats[r][k], wg, a[r]);
                e[r] = fmaf(fpns[r][k], wf, e[r]);
            }
        }
        float bbg = bg[c], bbf = bf[c];
        #pragma unroll
        for (int r = 0; r < HB; r++) {
            us[r][c] = fmaxf(a[r] + bbg, 0.f);
            vs[r][c] = fmaxf(e[r] + bbf, 0.f);
        }
    }
    __syncthreads();

    for (int c = tid; c < HID; c += 256) {
        float a[HB] = {};
        #pragma unroll 4
        for (int k = 0; k < HID; k++) {
            float w = W1[(size_t)k * HID + c];
            #pragma unroll
            for (int r = 0; r < HB; r++) a[r] = fmaf(us[r][k], w, a[r]);
        }
        #pragma unroll 4
        for (int k = 0; k < HID; k++) {
            float w = W1[(size_t)(k + HID) * HID + c];
            #pragma unroll
            for (int r = 0; r < HB; r++) a[r] = fmaf(vs[r][k], w, a[r]);
        }
        float bb = b1[c];
        #pragma unroll
        for (int r = 0; r < HB; r++) ys[r][c] = fmaxf(a[r] + bb, 0.f);
    }
    __syncthreads();

    const int warp = tid >> 5, lane = tid & 31;
    if (warp < HB) {
        float s = 0.f;
        for (int k = lane; k < HID; k += 32) s = fmaf(ys[warp][k], w2[k], s);
        s = warp_sum(s);
        if (lane == 0) out[b0 + warp] = 1.f / (1.f + expf(-(s + b2[0])));
    }
}

// ---------------- launch ----------------
extern "C" void kernel_launch(void* const* d_in, const int* in_sizes, int n_in,
                              void* d_out, int out_size)
{
    const float* atom_feats = (const float*)d_in[0];
    const float* fp         = (const float*)d_in[1];
    const float* W_heads    = (const float*)d_in[2];
    const float* a_heads    = (const float*)d_in[3];
    const float* W_out      = (const float*)d_in[4];
    const float* a_out      = (const float*)d_in[5];
    const float* fc1_w      = (const float*)d_in[6];
    const float* fc1_b      = (const float*)d_in[7];
    const float* fc2_w      = (const float*)d_in[8];
    const float* fc2_b      = (const float*)d_in[9];
    const float* fc_gat_w   = (const float*)d_in[10];
    const float* fc_gat_b   = (const float*)d_in[11];
    const float* fc_fpn_w   = (const float*)d_in[12];
    const float* fc_fpn_b   = (const float*)d_in[13];
    const float* ffn_w1     = (const float*)d_in[14];
    const float* ffn_b1     = (const float*)d_in[15];
    const float* ffn_w2     = (const float*)d_in[16];
    const float* ffn_b2     = (const float*)d_in[17];
    const int*   adj        = (const int*)  d_in[18];
    float* out = (float*)d_out;

    float *pApad, *pWt, *pWh, *ph, *pWh2, *pP, *pO, *pFp, *pW1, *pPart;
    cudaGetSymbolAddress((void**)&pApad, g_Apad);
    cudaGetSymbolAddress((void**)&pWt,   g_Wt);
    cudaGetSymbolAddress((void**)&pWh,   g_Wh);
    cudaGetSymbolAddress((void**)&ph,    g_h);
    cudaGetSymbolAddress((void**)&pWh2,  g_Wh2);
    cudaGetSymbolAddress((void**)&pP,    g_P);
    cudaGetSymbolAddress((void**)&pO,    g_O);
    cudaGetSymbolAddress((void**)&pFp,   g_fppad);
    cudaGetSymbolAddress((void**)&pW1,   g_w1pad);
    cudaGetSymbolAddress((void**)&pPart, g_part);

    cudaFuncSetAttribute(gat1_kernel, cudaFuncAttributeMaxDynamicSharedMemorySize, G1_SM);

    // 1: pad A
    pad_atoms<<<(Bsz * Nn * KP + 255) / 256, 256>>>(atom_feats);
    // 2: transpose W_heads
    transpose_wheads<<<(KP * HD + 255) / 256, 256>>>(W_heads);
    // 3: pad fp
    pad_fp<<<(Bsz * KP1 + 255) / 256, 256>>>(fp);
    // 4: K1  Wh = Apad(32768x144) @ Wt(144x512)   <-- ncu capture target
    gemm_f2<<<dim3(HD / 64, (Bsz * Nn) / 128, 1), 256>>>(
        pApad, pWt, pWh, Bsz * Nn, HD, KP, KP, HD, HD, 0, 0, 0, 0);
    // 5: gat1
    gat1_kernel<<<Bsz * Hh, 256, G1_SM>>>(a_heads, adj);
    // 6: pad fc1_w
    pad_w1<<<(KP1 * FP2 + 255) / 256, 256>>>(fc1_w);
    // 7,8: fc1 split-K + reduce
    gemm_f2<<<dim3(FP2 / 64, Bsz / 128, FSPLIT), 256>>>(
        pFp, pW1, pPart, Bsz, FP2, FCHUNK, KP1, FP2, FP2,
        (long long)FCHUNK, (long long)FCHUNK * FP2, (long long)Bsz * FP2, 0);
    fc1_reduce<<<(Bsz * FP2 + 255) / 256, 256>>>(fc1_b);
    // 9: K3  Wh2 = h(32768x512) @ W_out(512x300)
    gemm_f2<<<dim3((HID + 63) / 64, (Bsz * Nn) / 128, 1), 256>>>(
        ph, W_out, pWh2, Bsz * Nn, HID, HD, HD, HID, HID, 0, 0, 0, 0);
    // 10: gat2 scores + probs
    sp2_kernel<<<Bsz, 256>>>(a_out, adj);
    // 11: gat2 AV batched GEMM + elu
    gemm_f2<<<dim3((HID + 63) / 64, 1, Bsz), 256>>>(
        pP, pWh2, pO, Nn, HID, Nn, Nn, HID, HID,
        (long long)Nn * Nn, (long long)Nn * HID, (long long)Nn * HID, 2);
    // 12: gat2 log_softmax + mean
    ls2_kernel<<<Bsz, 256>>>();
    // 13: fused head
    head_fused<<<Bsz / HB, 256>>>(
        fc2_w, fc2_b, fc_gat_w, fc_gat_b, fc_fpn_w, fc_fpn_b,
        ffn_w1, ffn_b1, ffn_w2, ffn_b2, out);
}

// round 6
// speedup vs baseline: 1.7725x; 1.0764x over previous
#include <cuda_runtime.h>
#include <cuda_bf16.h>
#include <math.h>

// Problem constants
#define Bsz 256
#define Nn  128
#define Ff  133
#define KP  144          // Ff padded to multiple of 16
#define Hh  8
#define NHID 64
#define HID 300
#define FP_DIM 1489
#define KP1 1536         // FP_DIM padded
#define FSPLIT 8
#define FCHUNK 192       // KP1 / FSPLIT
#define FP2 512
#define HD (Hh*NHID)     // 512
#define ALPHA 0.2f
#define NEGV (-9e15f)

// ---------------- scratch (device globals; no allocation allowed) ----------------
__device__ float g_Apad[(size_t)Bsz*Nn * KP];
__device__ float g_Wt  [KP * HD];
__device__ float g_Wh  [(size_t)Bsz*Nn * HD];
__device__ float g_P1  [(size_t)Bsz*Hh*Nn * Nn];   // layer1 probs (134MB)
__device__ float g_h   [(size_t)Bsz*Nn * HD];
__device__ float g_Wh2 [(size_t)Bsz*Nn * HID];
__device__ float g_P   [(size_t)Bsz*Nn * Nn];
__device__ float g_O   [(size_t)Bsz*Nn * HID];
__device__ float g_gat [Bsz * HID];
__device__ float g_fppad[(size_t)Bsz * KP1];
__device__ float g_w1pad[(size_t)KP1 * FP2];
__device__ float g_part[(size_t)FSPLIT * Bsz * FP2];
__device__ float g_t1  [Bsz * FP2];

// ---------------- f32x2 helpers ----------------
#define FMA2(acc, a, b) \
    asm("fma.rn.f32x2 %0, %1, %2, %0;" : "+l"(acc) : "l"(a), "l"(b))

__device__ __forceinline__ unsigned long long ld2(const float* p) {
    return *reinterpret_cast<const unsigned long long*>(p);
}
__device__ __forceinline__ unsigned long long dup2(float x) {
    unsigned long long r;
    asm("mov.b64 %0, {%1, %1};" : "=l"(r) : "r"(__float_as_uint(x)));
    return r;
}
__device__ __forceinline__ float lo32(unsigned long long v) {
    return __uint_as_float((unsigned)v);
}
__device__ __forceinline__ float hi32(unsigned long long v) {
    return __uint_as_float((unsigned)(v >> 32));
}

__device__ __forceinline__ float warp_sum(float v) {
    #pragma unroll
    for (int o = 16; o; o >>= 1) v += __shfl_down_sync(0xffffffffu, v, o);
    return v;
}
__device__ __forceinline__ float warp_max(float v) {
    #pragma unroll
    for (int o = 16; o; o >>= 1) v = fmaxf(v, __shfl_down_sync(0xffffffffu, v, o));
    return v;
}

// ---------------- pad kernels ----------------------------------------------------
__global__ void pad_atoms(const float* __restrict__ src) {
    int t = blockIdx.x * blockDim.x + threadIdx.x;
    if (t >= Bsz * Nn * KP) return;
    int k = t % KP;
    int r = t / KP;
    g_Apad[t] = (k < Ff) ? src[(size_t)r * Ff + k] : 0.f;
}
__global__ void transpose_wheads(const float* __restrict__ W_heads) {
    int t = blockIdx.x * blockDim.x + threadIdx.x;
    if (t >= KP * HD) return;
    int f = t / HD;
    int r = t - f * HD;
    int h = r >> 6, d = r & 63;
    g_Wt[t] = (f < Ff) ? W_heads[((size_t)h * Ff + f) * NHID + d] : 0.f;
}
__global__ void pad_fp(const float* __restrict__ fp) {
    int t = blockIdx.x * blockDim.x + threadIdx.x;
    if (t >= Bsz * KP1) return;
    int k = t % KP1, r = t / KP1;
    g_fppad[t] = (k < FP_DIM) ? fp[(size_t)r * FP_DIM + k] : 0.f;
}
__global__ void pad_w1(const float* __restrict__ w) {
    int t = blockIdx.x * blockDim.x + threadIdx.x;
    if (t >= KP1 * FP2) return;
    int r = t / FP2;
    g_w1pad[t] = (r < FP_DIM) ? w[t] : 0.f;
}

// ============ gemm_p2: f32x2 GEMM, N-pair accumulators ===========================
// 128 x (32*CP) tile, 256 threads; per thread 8 rows x CP col-pairs.
// C = act(A(MxK,lda) @ B(KxN,ldb)); M%128==0, K%16==0, lda/ldb%4==0, ldc even.
// ACT: 0 none, 2 elu. BMODE: 0 linear batch offsets; 1 gat1 (z -> b,h into Wh-layout).
template<int CP, int ACT, int BMODE>
__global__ __launch_bounds__(256) void gemm_p2(
    const float* __restrict__ A, const float* __restrict__ B, float* __restrict__ C,
    int M, int N, int K, int lda, int ldb, int ldc,
    long long bA, long long bB, long long bC)
{
    __shared__ __align__(16) float As[16][132];
    __shared__ __align__(16) float Bs[16][32 * CP + 4];

    const int z = blockIdx.z;
    A += (long long)z * bA;
    if (BMODE == 0) {
        B += (long long)z * bB;
        C += (long long)z * bC;
    } else {
        const long long off = (long long)(z >> 3) * ((long long)Nn * HD) + (long long)(z & 7) * NHID;
        B += off;
        C += off;
    }

    const int tid = threadIdx.x;
    const int tx = tid & 15, ty = tid >> 4;
    const int row0 = blockIdx.y * 128, col0 = blockIdx.x * (32 * CP);

    const int am = tid >> 2;               // 0..63 (+64 second chunk)
    const int aq = (tid & 3) << 2;         // 0,4,8,12
    const int bk = tid >> 4;               // 0..15
    const int bn4 = (tid & 15) << 2;       // 0..60

    unsigned long long acc[8][CP];
    #pragma unroll
    for (int i = 0; i < 8; i++)
        #pragma unroll
        for (int j = 0; j < CP; j++) acc[i][j] = 0ull;

    for (int k0 = 0; k0 < K; k0 += 16) {
        // A tile -> transposed As[k][m]
        #pragma unroll
        for (int it = 0; it < 2; it++) {
            const int m = am + it * 64;
            float4 v = *reinterpret_cast<const float4*>(A + (size_t)(row0 + m) * lda + k0 + aq);
            As[aq + 0][m] = v.x;
            As[aq + 1][m] = v.y;
            As[aq + 2][m] = v.z;
            As[aq + 3][m] = v.w;
        }
        // B tile -> Bs[k][n] (natural order)
        #pragma unroll
        for (int jj2 = 0; jj2 < CP / 2; jj2++) {
            const int n = bn4 + 64 * jj2;
            const int gc = col0 + n;
            float4 w;
            if (gc + 4 <= N) {
                w = *reinterpret_cast<const float4*>(B + (size_t)(k0 + bk) * ldb + gc);
            } else {
                w.x = (gc + 0 < N) ? B[(size_t)(k0 + bk) * ldb + gc + 0] : 0.f;
                w.y = (gc + 1 < N) ? B[(size_t)(k0 + bk) * ldb + gc + 1] : 0.f;
                w.z = (gc + 2 < N) ? B[(size_t)(k0 + bk) * ldb + gc + 2] : 0.f;
                w.w = (gc + 3 < N) ? B[(size_t)(k0 + bk) * ldb + gc + 3] : 0.f;
            }
            *reinterpret_cast<float4*>(&Bs[bk][n]) = w;
        }
        __syncthreads();
        #pragma unroll
        for (int k = 0; k < 16; k++) {
            unsigned long long aL[8], b2[CP];
            #pragma unroll
            for (int ii = 0; ii < 4; ii++) {
                const unsigned long long pr = ld2(&As[k][2 * ty + 32 * ii]);
                aL[2 * ii]     = dup2(lo32(pr));
                aL[2 * ii + 1] = dup2(hi32(pr));
            }
            #pragma unroll
            for (int jj = 0; jj < CP; jj++) b2[jj] = ld2(&Bs[k][2 * (tx + 16 * jj)]);
            #pragma unroll
            for (int i = 0; i < 8; i++)
                #pragma unroll
                for (int jj = 0; jj < CP; jj++)
                    FMA2(acc[i][jj], aL[i], b2[jj]);
        }
        __syncthreads();
    }

    // epilogue: row r = row0 + 2ty + 32*(i>>1) + (i&1); cols (c, c+1)
    #pragma unroll
    for (int i = 0; i < 8; i++) {
        const int r = row0 + 2 * ty + 32 * (i >> 1) + (i & 1);
        #pragma unroll
        for (int jj = 0; jj < CP; jj++) {
            const int c = col0 + 2 * (tx + 16 * jj);
            if (c < N) {
                float v0 = lo32(acc[i][jj]);
                float v1 = hi32(acc[i][jj]);
                if (ACT == 2) {
                    v0 = (v0 > 0.f) ? v0 : expm1f(v0);
                    v1 = (v1 > 0.f) ? v1 : expm1f(v1);
                }
                *reinterpret_cast<float2*>(C + (size_t)r * ldc + c) = make_float2(v0, v1);
            }
        }
    }
}

// ---------------- fc1 reduce ------------------------------------------------------
__global__ void fc1_reduce(const float* __restrict__ fc1_b) {
    int t = blockIdx.x * blockDim.x + threadIdx.x;
    if (t >= Bsz * FP2) return;
    float s = 0.f;
    #pragma unroll
    for (int z = 0; z < FSPLIT; z++) s += g_part[(size_t)z * Bsz * FP2 + t];
    g_t1[t] = fmaxf(s + fc1_b[t & (FP2 - 1)], 0.f);
}

// ---------------- sp1: gat1 scores + masked softmax -> g_P1 ----------------------
__global__ __launch_bounds__(256) void sp1_kernel(const float* __restrict__ a_heads,
                                                  const int* __restrict__ adj)
{
    __shared__ float ss[128], dd[128];
    const int z = blockIdx.x;
    const int b = z >> 3, h = z & 7;
    const int tid = threadIdx.x, warp = tid >> 5, lane = tid & 31;
    const float* whbase = g_Wh + ((size_t)b * Nn) * HD + h * NHID;
    const float* a1 = a_heads + h * (2 * NHID);
    const float* a2v = a1 + NHID;

    for (int j = warp; j < 128; j += 8) {
        const float w0 = whbase[(size_t)j * HD + lane];
        const float w1 = whbase[(size_t)j * HD + lane + 32];
        float s1 = fmaf(w0, a1[lane], w1 * a1[lane + 32]);
        float s2 = fmaf(w0, a2v[lane], w1 * a2v[lane + 32]);
        s1 = warp_sum(s1); s2 = warp_sum(s2);
        if (lane == 0) { ss[j] = s1; dd[j] = s2; }
    }
    __syncthreads();

    const int* adjb = adj + (size_t)b * Nn * Nn;
    for (int i = warp; i < 128; i += 8) {
        const float si = ss[i];
        const int* ar = adjb + i * Nn;
        float ev[4];
        #pragma unroll
        for (int q = 0; q < 4; q++) {
            int j = lane + q * 32;
            float e = si + dd[j];
            e = (e > 0.f) ? e : ALPHA * e;
            ev[q] = (ar[j] > 0) ? e : NEGV;
        }
        float mx = fmaxf(fmaxf(ev[0], ev[1]), fmaxf(ev[2], ev[3]));
        mx = warp_max(mx);
        mx = __shfl_sync(0xffffffffu, mx, 0);
        float ls = 0.f;
        #pragma unroll
        for (int q = 0; q < 4; q++) { ev[q] = __expf(ev[q] - mx); ls += ev[q]; }
        ls = warp_sum(ls);
        ls = __shfl_sync(0xffffffffu, ls, 0);
        const float inv = 1.f / ls;
        float* pr = g_P1 + ((size_t)z * Nn + i) * Nn;
        #pragma unroll
        for (int q = 0; q < 4; q++) pr[lane + 32 * q] = ev[q] * inv;
    }
}

// ---------------- sp2: gat2 scores + masked softmax -> g_P -----------------------
__global__ __launch_bounds__(256) void sp2_kernel(const float* __restrict__ a_out,
                                                  const int* __restrict__ adj)
{
    __shared__ float ss[128], dd[128];
    const int b = blockIdx.x;
    const int tid = threadIdx.x, warp = tid >> 5, lane = tid & 31;
    const float* W = g_Wh2 + (size_t)b * Nn * HID;

    for (int j = warp; j < 128; j += 8) {
        float s1 = 0.f, s2 = 0.f;
        #pragma unroll
        for (int t = 0; t < 10; t++) {
            int d = lane + 32 * t;
            if (d < HID) {
                float w = W[(size_t)j * HID + d];
                s1 = fmaf(w, a_out[d], s1);
                s2 = fmaf(w, a_out[HID + d], s2);
            }
        }
        s1 = warp_sum(s1); s2 = warp_sum(s2);
        if (lane == 0) { ss[j] = s1; dd[j] = s2; }
    }
    __syncthreads();

    for (int i = warp; i < 128; i += 8) {
        const float si = ss[i];
        const int* ar = adj + ((size_t)b * Nn + i) * Nn;
        float ev[4];
        #pragma unroll
        for (int q = 0; q < 4; q++) {
            int j = lane + q * 32;
            float e = si + dd[j];
            e = (e > 0.f) ? e : ALPHA * e;
            ev[q] = (ar[j] > 0) ? e : NEGV;
        }
        float mx = fmaxf(fmaxf(ev[0], ev[1]), fmaxf(ev[2], ev[3]));
        mx = warp_max(mx);
        mx = __shfl_sync(0xffffffffu, mx, 0);
        float ls = 0.f;
        #pragma unroll
        for (int q = 0; q < 4; q++) { ev[q] = __expf(ev[q] - mx); ls += ev[q]; }
        ls = warp_sum(ls);
        ls = __shfl_sync(0xffffffffu, ls, 0);
        const float inv = 1.f / ls;
        float* pr = g_P + ((size_t)b * Nn + i) * Nn;
        #pragma unroll
        for (int q = 0; q < 4; q++) pr[lane + 32 * q] = ev[q] * inv;
    }
}

// ---------------- ls2: log_softmax + mean ----------------------------------------
__global__ __launch_bounds__(256) void ls2_kernel()
{
    __shared__ float acc[8 * HID];
    const int b = blockIdx.x;
    const int tid = threadIdx.x, warp = tid >> 5, lane = tid & 31;
    for (int t = tid; t < 8 * HID; t += 256) acc[t] = 0.f;
    __syncthreads();

    const float* O = g_O + (size_t)b * Nn * HID;
    float* accw = acc + warp * HID;
    for (int i = warp; i < 128; i += 8) {
        float o[10];
        #pragma unroll
        for (int t = 0; t < 10; t++) {
            int d = lane + 32 * t;
            o[t] = (d < HID) ? O[(size_t)i * HID + d] : -1e30f;
        }
        float m = o[0];
        #pragma unroll
        for (int t = 1; t < 10; t++) m = fmaxf(m, o[t]);
        m = warp_max(m);
        m = __shfl_sync(0xffffffffu, m, 0);
        float se = 0.f;
        #pragma unroll
        for (int t = 0; t < 10; t++) se += __expf(o[t] - m);
        se = warp_sum(se);
        se = __shfl_sync(0xffffffffu, se, 0);
        const float lse = m + logf(se);
        #pragma unroll
        for (int t = 0; t < 10; t++) {
            int d = lane + 32 * t;
            if (d < HID) accw[d] += o[t] - lse;
        }
    }
    __syncthreads();
    for (int d = tid; d < HID; d += 256) {
        float s = 0.f;
        #pragma unroll
        for (int w = 0; w < 8; w++) s += acc[w * HID + d];
        g_gat[b * HID + d] = s * (1.f / 128.f);
    }
}

// ---------------- head: fc2 + fc_gat + fc_fpn + ffn1 + ffn2 + sigmoid ------------
#define HB 4
__global__ __launch_bounds__(256) void head_fused(
    const float* __restrict__ fc2_w, const float* __restrict__ fc2_b,
    const float* __restrict__ Wg,    const float* __restrict__ bg,
    const float* __restrict__ Wf,    const float* __restrict__ bf,
    const float* __restrict__ W1,    const float* __restrict__ b1,
    const float* __restrict__ w2,    const float* __restrict__ b2,
    float* __restrict__ out)
{
    __shared__ float t1s [HB][512];
    __shared__ float gats[HB][HID];
    __shared__ float fpns[HB][HID];
    __shared__ float us  [HB][HID];
    __shared__ float vs  [HB][HID];
    __shared__ float ys  [HB][HID];

    const int b0 = blockIdx.x * HB;
    const int tid = threadIdx.x;

    for (int t = tid; t < HB * 512; t += 256) {
        int r = t >> 9;
        t1s[r][t & 511] = g_t1[(size_t)(b0 + r) * FP2 + (t & 511)];
    }
    for (int t = tid; t < HB * HID; t += 256) {
        int r = t / HID, c = t - r * HID;
        gats[r][c] = g_gat[(size_t)(b0 + r) * HID + c];
    }
    __syncthreads();

    for (int c = tid; c < HID; c += 256) {
        float a[HB] = {};
        #pragma unroll 4
        for (int k = 0; k < 512; k++) {
            float w = fc2_w[(size_t)k * HID + c];
            #pragma unroll
            for (int r = 0; r < HB; r++) a[r] = fmaf(t1s[r][k], w, a[r]);
        }
        float bb = fc2_b[c];
        #pragma unroll
        for (int r = 0; r < HB; r++) fpns[r][c] = a[r] + bb;
    }
    __syncthreads();

    for (int c = tid; c < HID; c += 256) {
        float a[HB] = {}, e[HB] = {};
        #pragma unroll 4
        for (int k = 0; k < HID; k++) {
            float wg = Wg[(size_t)k * HID + c];
            float wf = Wf[(size_t)k * HID + c];
            #pragma unroll
            for (int r = 0; r < HB; r++) {
                a[r] = fmaf(gats[r][k], wg, a[r]);
                e[r] = fmaf(fpns[r][k], wf, e[r]);
            }
        }
        float bbg = bg[c], bbf = bf[c];
        #pragma unroll
        for (int r = 0; r < HB; r++) {
            us[r][c] = fmaxf(a[r] + bbg, 0.f);
            vs[r][c] = fmaxf(e[r] + bbf, 0.f);
        }
    }
    __syncthreads();

    for (int c = tid; c < HID; c += 256) {
        float a[HB] = {};
        #pragma unroll 4
        for (int k = 0; k < HID; k++) {
            float w = W1[(size_t)k * HID + c];
            #pragma unroll
            for (int r = 0; r < HB; r++) a[r] = fmaf(us[r][k], w, a[r]);
        }
        #pragma unroll 4
        for (int k = 0; k < HID; k++) {
            float w = W1[(size_t)(k + HID) * HID + c];
            #pragma unroll
            for (int r = 0; r < HB; r++) a[r] = fmaf(vs[r][k], w, a[r]);
        }
        float bb = b1[c];
        #pragma unroll
        for (int r = 0; r < HB; r++) ys[r][c] = fmaxf(a[r] + bb, 0.f);
    }
    __syncthreads();

    const int warp = tid >> 5, lane = tid & 31;
    if (warp < HB) {
        float s = 0.f;
        for (int k = lane; k < HID; k += 32) s = fmaf(ys[warp][k], w2[k], s);
        s = warp_sum(s);
        if (lane == 0) out[b0 + warp] = 1.f / (1.f + expf(-(s + b2[0])));
    }
}

// ---------------- launch ----------------
extern "C" void kernel_launch(void* const* d_in, const int* in_sizes, int n_in,
                              void* d_out, int out_size)
{
    const float* atom_feats = (const float*)d_in[0];
    const float* fp         = (const float*)d_in[1];
    const float* W_heads    = (const float*)d_in[2];
    const float* a_heads    = (const float*)d_in[3];
    const float* W_out      = (const float*)d_in[4];
    const float* a_out      = (const float*)d_in[5];
    const float* fc1_w      = (const float*)d_in[6];
    const float* fc1_b      = (const float*)d_in[7];
    const float* fc2_w      = (const float*)d_in[8];
    const float* fc2_b      = (const float*)d_in[9];
    const float* fc_gat_w   = (const float*)d_in[10];
    const float* fc_gat_b   = (const float*)d_in[11];
    const float* fc_fpn_w   = (const float*)d_in[12];
    const float* fc_fpn_b   = (const float*)d_in[13];
    const float* ffn_w1     = (const float*)d_in[14];
    const float* ffn_b1     = (const float*)d_in[15];
    const float* ffn_w2     = (const float*)d_in[16];
    const float* ffn_b2     = (const float*)d_in[17];
    const int*   adj        = (const int*)  d_in[18];
    float* out = (float*)d_out;

    float *pApad, *pWt, *pWh, *pP1, *ph, *pWh2, *pP, *pO, *pFp, *pW1, *pPart;
    cudaGetSymbolAddress((void**)&pApad, g_Apad);
    cudaGetSymbolAddress((void**)&pWt,   g_Wt);
    cudaGetSymbolAddress((void**)&pWh,   g_Wh);
    cudaGetSymbolAddress((void**)&pP1,   g_P1);
    cudaGetSymbolAddress((void**)&ph,    g_h);
    cudaGetSymbolAddress((void**)&pWh2,  g_Wh2);
    cudaGetSymbolAddress((void**)&pP,    g_P);
    cudaGetSymbolAddress((void**)&pO,    g_O);
    cudaGetSymbolAddress((void**)&pFp,   g_fppad);
    cudaGetSymbolAddress((void**)&pW1,   g_w1pad);
    cudaGetSymbolAddress((void**)&pPart, g_part);

    // 1: pad A
    pad_atoms<<<(Bsz * Nn * KP + 255) / 256, 256>>>(atom_feats);
    // 2: transpose W_heads
    transpose_wheads<<<(KP * HD + 255) / 256, 256>>>(W_heads);
    // 3: pad fp
    pad_fp<<<(Bsz * KP1 + 255) / 256, 256>>>(fp);
    // 4: K1  Wh = Apad(32768x144) @ Wt(144x512)   <-- ncu capture target
    gemm_p2<4, 0, 0><<<dim3(HD / 128, (Bsz * Nn) / 128, 1), 256>>>(
        pApad, pWt, pWh, Bsz * Nn, HD, KP, KP, HD, HD, 0, 0, 0);
    // 5: gat1 scores + softmax -> P1
    sp1_kernel<<<Bsz * Hh, 256>>>(a_heads, adj);
    // 6: gat1 AV batched (128x64x128 per (b,h)) + elu -> g_h
    gemm_p2<2, 2, 1><<<dim3(1, 1, Bsz * Hh), 256>>>(
        pP1, pWh, ph, Nn, NHID, Nn, Nn, HD, HD,
        (long long)Nn * Nn, 0, 0);
    // 7: pad fc1_w
    pad_w1<<<(KP1 * FP2 + 255) / 256, 256>>>(fc1_w);
    // 8,9: fc1 split-K + reduce
    gemm_p2<4, 0, 0><<<dim3(FP2 / 128, Bsz / 128, FSPLIT), 256>>>(
        pFp, pW1, pPart, Bsz, FP2, FCHUNK, KP1, FP2, FP2,
        (long long)FCHUNK, (long long)FCHUNK * FP2, (long long)Bsz * FP2);
    fc1_reduce<<<(Bsz * FP2 + 255) / 256, 256>>>(fc1_b);
    // 10: K3  Wh2 = h(32768x512) @ W_out(512x300)
    gemm_p2<4, 0, 0><<<dim3((HID + 127) / 128, (Bsz * Nn) / 128, 1), 256>>>(
        ph, W_out, pWh2, Bsz * Nn, HID, HD, HD, HID, HID, 0, 0, 0);
    // 11: gat2 scores + probs
    sp2_kernel<<<Bsz, 256>>>(a_out, adj);
    // 12: gat2 AV batched GEMM + elu
    gemm_p2<4, 2, 0><<<dim3((HID + 127) / 128, 1, Bsz), 256>>>(
        pP, pWh2, pO, Nn, HID, Nn, Nn, HID, HID,
        (long long)Nn * Nn, (long long)Nn * HID, (long long)Nn * HID);
    // 13: gat2 log_softmax + mean
    ls2_kernel<<<Bsz, 256>>>();
    // 14: fused head
    head_fused<<<Bsz / HB, 256>>>(
        fc2_w, fc2_b, fc_gat_w, fc_gat_b, fc_fpn_w, fc_fpn_b,
        ffn_w1, ffn_b1, ffn_w2, ffn_b2, out);
}

// round 7
// speedup vs baseline: 1.8388x; 1.0374x over previous
#include <cuda_runtime.h>
#include <cuda_bf16.h>
#include <math.h>

// Problem constants
#define Bsz 256
#define Nn  128
#define Ff  133
#define KP  144          // Ff padded to multiple of 16
#define Hh  8
#define NHID 64
#define HID 300
#define FP_DIM 1489
#define KP1 1536         // FP_DIM padded
#define FSPLIT 8
#define FCHUNK 192       // KP1 / FSPLIT
#define FP2 512
#define HD (Hh*NHID)     // 512
#define ALPHA 0.2f
#define NEGV (-9e15f)

// ---------------- scratch (device globals; no allocation allowed) ----------------
__device__ float g_Apad[(size_t)Bsz*Nn * KP];
__device__ float g_Wt  [KP * HD];
__device__ float g_Wh  [(size_t)Bsz*Nn * HD];
__device__ float g_P1  [(size_t)Bsz*Hh*Nn * Nn];   // layer1 probs (134MB)
__device__ float g_h   [(size_t)Bsz*Nn * HD];
__device__ float g_Wh2 [(size_t)Bsz*Nn * HID];
__device__ float g_P   [(size_t)Bsz*Nn * Nn];
__device__ float g_O   [(size_t)Bsz*Nn * HID];
__device__ float g_gat [Bsz * HID];
__device__ float g_fppad[(size_t)Bsz * KP1];
__device__ float g_w1pad[(size_t)KP1 * FP2];
__device__ float g_part[(size_t)FSPLIT * Bsz * FP2];
__device__ float g_t1  [Bsz * FP2];

// ---------------- f32x2 helpers ----------------
#define FMA2(acc, a, b) \
    asm("fma.rn.f32x2 %0, %1, %2, %0;" : "+l"(acc) : "l"(a), "l"(b))

__device__ __forceinline__ unsigned long long ld2(const float* p) {
    return *reinterpret_cast<const unsigned long long*>(p);
}
__device__ __forceinline__ unsigned long long dup2(float x) {
    unsigned long long r;
    asm("mov.b64 %0, {%1, %1};" : "=l"(r) : "r"(__float_as_uint(x)));
    return r;
}
__device__ __forceinline__ float lo32(unsigned long long v) {
    return __uint_as_float((unsigned)v);
}
__device__ __forceinline__ float hi32(unsigned long long v) {
    return __uint_as_float((unsigned)(v >> 32));
}

__device__ __forceinline__ float warp_sum(float v) {
    #pragma unroll
    for (int o = 16; o; o >>= 1) v += __shfl_down_sync(0xffffffffu, v, o);
    return v;
}
__device__ __forceinline__ float warp_max(float v) {
    #pragma unroll
    for (int o = 16; o; o >>= 1) v = fmaxf(v, __shfl_down_sync(0xffffffffu, v, o));
    return v;
}

// ---------------- pad kernels ----------------------------------------------------
__global__ void pad_atoms(const float* __restrict__ src) {
    int t = blockIdx.x * blockDim.x + threadIdx.x;
    if (t >= Bsz * Nn * KP) return;
    int k = t % KP;
    int r = t / KP;
    g_Apad[t] = (k < Ff) ? src[(size_t)r * Ff + k] : 0.f;
}
__global__ void transpose_wheads(const float* __restrict__ W_heads) {
    int t = blockIdx.x * blockDim.x + threadIdx.x;
    if (t >= KP * HD) return;
    int f = t / HD;
    int r = t - f * HD;
    int h = r >> 6, d = r & 63;
    g_Wt[t] = (f < Ff) ? W_heads[((size_t)h * Ff + f) * NHID + d] : 0.f;
}
__global__ void pad_fp(const float* __restrict__ fp) {
    int t = blockIdx.x * blockDim.x + threadIdx.x;
    if (t >= Bsz * KP1) return;
    int k = t % KP1, r = t / KP1;
    g_fppad[t] = (k < FP_DIM) ? fp[(size_t)r * FP_DIM + k] : 0.f;
}
__global__ void pad_w1(const float* __restrict__ w) {
    int t = blockIdx.x * blockDim.x + threadIdx.x;
    if (t >= KP1 * FP2) return;
    int r = t / FP2;
    g_w1pad[t] = (r < FP_DIM) ? w[t] : 0.f;
}

// ============ gemm_p2: f32x2 GEMM, N-pair accumulators, double-buffered ==========
// 128 x (32*CP) tile, 256 threads; per thread 8 rows x CP col-pairs.
// C = act(A(MxK,lda) @ B(KxN,ldb)); M%128==0, K%32==0... (K%16==0), lda/ldb%4==0, ldc even.
// ACT: 0 none, 2 elu. BMODE: 0 linear batch offsets; 1 gat1 (z -> b,h into Wh-layout).
template<int CP, int ACT, int BMODE>
__global__ __launch_bounds__(256) void gemm_p2(
    const float* __restrict__ A, const float* __restrict__ B, float* __restrict__ C,
    int M, int N, int K, int lda, int ldb, int ldc,
    long long bA, long long bB, long long bC)
{
    __shared__ __align__(16) float As[2][16][132];
    __shared__ __align__(16) float Bs[2][16][32 * CP + 4];

    const int z = blockIdx.z;
    A += (long long)z * bA;
    if (BMODE == 0) {
        B += (long long)z * bB;
        C += (long long)z * bC;
    } else {
        const long long off = (long long)(z >> 3) * ((long long)Nn * HD) + (long long)(z & 7) * NHID;
        B += off;
        C += off;
    }

    const int tid = threadIdx.x;
    const int tx = tid & 15, ty = tid >> 4;
    const int row0 = blockIdx.y * 128, col0 = blockIdx.x * (32 * CP);

    const int am = tid >> 2;               // 0..63 (+64 second chunk)
    const int aq = (tid & 3) << 2;         // 0,4,8,12
    const int bk = tid >> 4;               // 0..15
    const int bn4 = (tid & 15) << 2;       // 0..60

    float4 ra0, ra1, rb[CP / 2];

    // global-load of one 16-k tile into registers
    auto load_g = [&](int k0) {
        ra0 = *reinterpret_cast<const float4*>(A + (size_t)(row0 + am) * lda + k0 + aq);
        ra1 = *reinterpret_cast<const float4*>(A + (size_t)(row0 + am + 64) * lda + k0 + aq);
        #pragma unroll
        for (int jj2 = 0; jj2 < CP / 2; jj2++) {
            const int gc = col0 + bn4 + 64 * jj2;
            if (gc + 4 <= N) {
                rb[jj2] = *reinterpret_cast<const float4*>(B + (size_t)(k0 + bk) * ldb + gc);
            } else {
                rb[jj2].x = (gc + 0 < N) ? B[(size_t)(k0 + bk) * ldb + gc + 0] : 0.f;
                rb[jj2].y = (gc + 1 < N) ? B[(size_t)(k0 + bk) * ldb + gc + 1] : 0.f;
                rb[jj2].z = (gc + 2 < N) ? B[(size_t)(k0 + bk) * ldb + gc + 2] : 0.f;
                rb[jj2].w = (gc + 3 < N) ? B[(size_t)(k0 + bk) * ldb + gc + 3] : 0.f;
            }
        }
    };
    // registers -> smem buffer
    auto store_s = [&](int buf) {
        As[buf][aq + 0][am] = ra0.x;
        As[buf][aq + 1][am] = ra0.y;
        As[buf][aq + 2][am] = ra0.z;
        As[buf][aq + 3][am] = ra0.w;
        As[buf][aq + 0][am + 64] = ra1.x;
        As[buf][aq + 1][am + 64] = ra1.y;
        As[buf][aq + 2][am + 64] = ra1.z;
        As[buf][aq + 3][am + 64] = ra1.w;
        #pragma unroll
        for (int jj2 = 0; jj2 < CP / 2; jj2++)
            *reinterpret_cast<float4*>(&Bs[buf][bk][bn4 + 64 * jj2]) = rb[jj2];
    };

    unsigned long long acc[8][CP];
    #pragma unroll
    for (int i = 0; i < 8; i++)
        #pragma unroll
        for (int j = 0; j < CP; j++) acc[i][j] = 0ull;

    const int nsteps = K >> 4;
    load_g(0);
    store_s(0);
    __syncthreads();

    for (int s = 0; s < nsteps; s++) {
        const int cur = s & 1;
        if (s + 1 < nsteps) load_g((s + 1) << 4);     // prefetch (latency hidden)
        #pragma unroll
        for (int k = 0; k < 16; k++) {
            unsigned long long aL[8], b2[CP];
            #pragma unroll
            for (int ii = 0; ii < 4; ii++) {
                const unsigned long long pr = ld2(&As[cur][k][2 * ty + 32 * ii]);
                aL[2 * ii]     = dup2(lo32(pr));
                aL[2 * ii + 1] = dup2(hi32(pr));
            }
            #pragma unroll
            for (int jj = 0; jj < CP; jj++) b2[jj] = ld2(&Bs[cur][k][2 * (tx + 16 * jj)]);
            #pragma unroll
            for (int i = 0; i < 8; i++)
                #pragma unroll
                for (int jj = 0; jj < CP; jj++)
                    FMA2(acc[i][jj], aL[i], b2[jj]);
        }
        if (s + 1 < nsteps) store_s(cur ^ 1);
        __syncthreads();
    }

    // epilogue: row r = row0 + 2ty + 32*(i>>1) + (i&1); cols (c, c+1)
    #pragma unroll
    for (int i = 0; i < 8; i++) {
        const int r = row0 + 2 * ty + 32 * (i >> 1) + (i & 1);
        #pragma unroll
        for (int jj = 0; jj < CP; jj++) {
            const int c = col0 + 2 * (tx + 16 * jj);
            if (c < N) {
                float v0 = lo32(acc[i][jj]);
                float v1 = hi32(acc[i][jj]);
                if (ACT == 2) {
                    v0 = (v0 > 0.f) ? v0 : expm1f(v0);
                    v1 = (v1 > 0.f) ? v1 : expm1f(v1);
                }
                *reinterpret_cast<float2*>(C + (size_t)r * ldc + c) = make_float2(v0, v1);
            }
        }
    }
}

// ---------------- fc1 reduce ------------------------------------------------------
__global__ void fc1_reduce(const float* __restrict__ fc1_b) {
    int t = blockIdx.x * blockDim.x + threadIdx.x;
    if (t >= Bsz * FP2) return;
    float s = 0.f;
    #pragma unroll
    for (int z = 0; z < FSPLIT; z++) s += g_part[(size_t)z * Bsz * FP2 + t];
    g_t1[t] = fmaxf(s + fc1_b[t & (FP2 - 1)], 0.f);
}

// ---------------- sp1: gat1 scores + masked softmax -> g_P1 ----------------------
__global__ __launch_bounds__(256) void sp1_kernel(const float* __restrict__ a_heads,
                                                  const int* __restrict__ adj)
{
    __shared__ float ss[128], dd[128];
    const int z = blockIdx.x;
    const int b = z >> 3, h = z & 7;
    const int tid = threadIdx.x, warp = tid >> 5, lane = tid & 31;
    const float* whbase = g_Wh + ((size_t)b * Nn) * HD + h * NHID;
    const float* a1 = a_heads + h * (2 * NHID);
    const float* a2v = a1 + NHID;

    for (int j = warp; j < 128; j += 8) {
        const float w0 = whbase[(size_t)j * HD + lane];
        const float w1 = whbase[(size_t)j * HD + lane + 32];
        float s1 = fmaf(w0, a1[lane], w1 * a1[lane + 32]);
        float s2 = fmaf(w0, a2v[lane], w1 * a2v[lane + 32]);
        s1 = warp_sum(s1); s2 = warp_sum(s2);
        if (lane == 0) { ss[j] = s1; dd[j] = s2; }
    }
    __syncthreads();

    const int* adjb = adj + (size_t)b * Nn * Nn;
    for (int i = warp; i < 128; i += 8) {
        const float si = ss[i];
        const int* ar = adjb + i * Nn;
        float ev[4];
        #pragma unroll
        for (int q = 0; q < 4; q++) {
            int j = lane + q * 32;
            float e = si + dd[j];
            e = (e > 0.f) ? e : ALPHA * e;
            ev[q] = (ar[j] > 0) ? e : NEGV;
        }
        float mx = fmaxf(fmaxf(ev[0], ev[1]), fmaxf(ev[2], ev[3]));
        mx = warp_max(mx);
        mx = __shfl_sync(0xffffffffu, mx, 0);
        float ls = 0.f;
        #pragma unroll
        for (int q = 0; q < 4; q++) { ev[q] = __expf(ev[q] - mx); ls += ev[q]; }
        ls = warp_sum(ls);
        ls = __shfl_sync(0xffffffffu, ls, 0);
        const float inv = 1.f / ls;
        float* pr = g_P1 + ((size_t)z * Nn + i) * Nn;
        #pragma unroll
        for (int q = 0; q < 4; q++) pr[lane + 32 * q] = ev[q] * inv;
    }
}

// ---------------- sp2: gat2 scores + masked softmax -> g_P -----------------------
__global__ __launch_bounds__(256) void sp2_kernel(const float* __restrict__ a_out,
                                                  const int* __restrict__ adj)
{
    __shared__ float ss[128], dd[128];
    const int b = blockIdx.x;
    const int tid = threadIdx.x, warp = tid >> 5, lane = tid & 31;
    const float* W = g_Wh2 + (size_t)b * Nn * HID;

    for (int j = warp; j < 128; j += 8) {
        float s1 = 0.f, s2 = 0.f;
        #pragma unroll
        for (int t = 0; t < 10; t++) {
            int d = lane + 32 * t;
            if (d < HID) {
                float w = W[(size_t)j * HID + d];
                s1 = fmaf(w, a_out[d], s1);
                s2 = fmaf(w, a_out[HID + d], s2);
            }
        }
        s1 = warp_sum(s1); s2 = warp_sum(s2);
        if (lane == 0) { ss[j] = s1; dd[j] = s2; }
    }
    __syncthreads();

    for (int i = warp; i < 128; i += 8) {
        const float si = ss[i];
        const int* ar = adj + ((size_t)b * Nn + i) * Nn;
        float ev[4];
        #pragma unroll
        for (int q = 0; q < 4; q++) {
            int j = lane + q * 32;
            float e = si + dd[j];
            e = (e > 0.f) ? e : ALPHA * e;
            ev[q] = (ar[j] > 0) ? e : NEGV;
        }
        float mx = fmaxf(fmaxf(ev[0], ev[1]), fmaxf(ev[2], ev[3]));
        mx = warp_max(mx);
        mx = __shfl_sync(0xffffffffu, mx, 0);
        float ls = 0.f;
        #pragma unroll
        for (int q = 0; q < 4; q++) { ev[q] = __expf(ev[q] - mx); ls += ev[q]; }
        ls = warp_sum(ls);
        ls = __shfl_sync(0xffffffffu, ls, 0);
        const float inv = 1.f / ls;
        float* pr = g_P + ((size_t)b * Nn + i) * Nn;
        #pragma unroll
        for (int q = 0; q < 4; q++) pr[lane + 32 * q] = ev[q] * inv;
    }
}

// ---------------- ls2: log_softmax + mean ----------------------------------------
__global__ __launch_bounds__(256) void ls2_kernel()
{
    __shared__ float acc[8 * HID];
    const int b = blockIdx.x;
    const int tid = threadIdx.x, warp = tid >> 5, lane = tid & 31;
    for (int t = tid; t < 8 * HID; t += 256) acc[t] = 0.f;
    __syncthreads();

    const float* O = g_O + (size_t)b * Nn * HID;
    float* accw = acc + warp * HID;
    for (int i = warp; i < 128; i += 8) {
        float o[10];
        #pragma unroll
        for (int t = 0; t < 10; t++) {
            int d = lane + 32 * t;
            o[t] = (d < HID) ? O[(size_t)i * HID + d] : -1e30f;
        }
        float m = o[0];
        #pragma unroll
        for (int t = 1; t < 10; t++) m = fmaxf(m, o[t]);
        m = warp_max(m);
        m = __shfl_sync(0xffffffffu, m, 0);
        float se = 0.f;
        #pragma unroll
        for (int t = 0; t < 10; t++) se += __expf(o[t] - m);
        se = warp_sum(se);
        se = __shfl_sync(0xffffffffu, se, 0);
        const float lse = m + logf(se);
        #pragma unroll
        for (int t = 0; t < 10; t++) {
            int d = lane + 32 * t;
            if (d < HID) accw[d] += o[t] - lse;
        }
    }
    __syncthreads();
    for (int d = tid; d < HID; d += 256) {
        float s = 0.f;
        #pragma unroll
        for (int w = 0; w < 8; w++) s += acc[w * HID + d];
        g_gat[b * HID + d] = s * (1.f / 128.f);
    }
}

// ---------------- head: fc2 + fc_gat + fc_fpn + ffn1 + ffn2 + sigmoid ------------
#define HB 4
__global__ __launch_bounds__(256) void head_fused(
    const float* __restrict__ fc2_w, const float* __restrict__ fc2_b,
    const float* __restrict__ Wg,    const float* __restrict__ bg,
    const float* __restrict__ Wf,    const float* __restrict__ bf,
    const float* __restrict__ W1,    const float* __restrict__ b1,
    const float* __restrict__ w2,    const float* __restrict__ b2,
    float* __restrict__ out)
{
    __shared__ float t1s [HB][512];
    __shared__ float gats[HB][HID];
    __shared__ float fpns[HB][HID];
    __shared__ float us  [HB][HID];
    __shared__ float vs  [HB][HID];
    __shared__ float ys  [HB][HID];

    const int b0 = blockIdx.x * HB;
    const int tid = threadIdx.x;

    for (int t = tid; t < HB * 512; t += 256) {
        int r = t >> 9;
        t1s[r][t & 511] = g_t1[(size_t)(b0 + r) * FP2 + (t & 511)];
    }
    for (int t = tid; t < HB * HID; t += 256) {
        int r = t / HID, c = t - r * HID;
        gats[r][c] = g_gat[(size_t)(b0 + r) * HID + c];
    }
    __syncthreads();

    for (int c = tid; c < HID; c += 256) {
        float a[HB] = {};
        #pragma unroll 4
        for (int k = 0; k < 512; k++) {
            float w = fc2_w[(size_t)k * HID + c];
            #pragma unroll
            for (int r = 0; r < HB; r++) a[r] = fmaf(t1s[r][k], w, a[r]);
        }
        float bb = fc2_b[c];
        #pragma unroll
        for (int r = 0; r < HB; r++) fpns[r][c] = a[r] + bb;
    }
    __syncthreads();

    for (int c = tid; c < HID; c += 256) {
        float a[HB] = {}, e[HB] = {};
        #pragma unroll 4
        for (int k = 0; k < HID; k++) {
            float wg = Wg[(size_t)k * HID + c];
            float wf = Wf[(size_t)k * HID + c];
            #pragma unroll
            for (int r = 0; r < HB; r++) {
                a[r] = fmaf(gats[r][k], wg, a[r]);
                e[r] = fmaf(fpns[r][k], wf, e[r]);
            }
        }
        float bbg = bg[c], bbf = bf[c];
        #pragma unroll
        for (int r = 0; r < HB; r++) {
            us[r][c] = fmaxf(a[r] + bbg, 0.f);
            vs[r][c] = fmaxf(e[r] + bbf, 0.f);
        }
    }
    __syncthreads();

    for (int c = tid; c < HID; c += 256) {
        float a[HB] = {};
        #pragma unroll 4
        for (int k = 0; k < HID; k++) {
            float w = W1[(size_t)k * HID + c];
            #pragma unroll
            for (int r = 0; r < HB; r++) a[r] = fmaf(us[r][k], w, a[r]);
        }
        #pragma unroll 4
        for (int k = 0; k < HID; k++) {
            float w = W1[(size_t)(k + HID) * HID + c];
            #pragma unroll
            for (int r = 0; r < HB; r++) a[r] = fmaf(vs[r][k], w, a[r]);
        }
        float bb = b1[c];
        #pragma unroll
        for (int r = 0; r < HB; r++) ys[r][c] = fmaxf(a[r] + bb, 0.f);
    }
    __syncthreads();

    const int warp = tid >> 5, lane = tid & 31;
    if (warp < HB) {
        float s = 0.f;
        for (int k = lane; k < HID; k += 32) s = fmaf(ys[warp][k], w2[k], s);
        s = warp_sum(s);
        if (lane == 0) out[b0 + warp] = 1.f / (1.f + expf(-(s + b2[0])));
    }
}

// ---------------- launch ----------------
extern "C" void kernel_launch(void* const* d_in, const int* in_sizes, int n_in,
                              void* d_out, int out_size)
{
    const float* atom_feats = (const float*)d_in[0];
    const float* fp         = (const float*)d_in[1];
    const float* W_heads    = (const float*)d_in[2];
    const float* a_heads    = (const float*)d_in[3];
    const float* W_out      = (const float*)d_in[4];
    const float* a_out      = (const float*)d_in[5];
    const float* fc1_w      = (const float*)d_in[6];
    const float* fc1_b      = (const float*)d_in[7];
    const float* fc2_w      = (const float*)d_in[8];
    const float* fc2_b      = (const float*)d_in[9];
    const float* fc_gat_w   = (const float*)d_in[10];
    const float* fc_gat_b   = (const float*)d_in[11];
    const float* fc_fpn_w   = (const float*)d_in[12];
    const float* fc_fpn_b   = (const float*)d_in[13];
    const float* ffn_w1     = (const float*)d_in[14];
    const float* ffn_b1     = (const float*)d_in[15];
    const float* ffn_w2     = (const float*)d_in[16];
    const float* ffn_b2     = (const float*)d_in[17];
    const int*   adj        = (const int*)  d_in[18];
    float* out = (float*)d_out;

    float *pApad, *pWt, *pWh, *pP1, *ph, *pWh2, *pP, *pO, *pFp, *pW1, *pPart;
    cudaGetSymbolAddress((void**)&pApad, g_Apad);
    cudaGetSymbolAddress((void**)&pWt,   g_Wt);
    cudaGetSymbolAddress((void**)&pWh,   g_Wh);
    cudaGetSymbolAddress((void**)&pP1,   g_P1);
    cudaGetSymbolAddress((void**)&ph,    g_h);
    cudaGetSymbolAddress((void**)&pWh2,  g_Wh2);
    cudaGetSymbolAddress((void**)&pP,    g_P);
    cudaGetSymbolAddress((void**)&pO,    g_O);
    cudaGetSymbolAddress((void**)&pFp,   g_fppad);
    cudaGetSymbolAddress((void**)&pW1,   g_w1pad);
    cudaGetSymbolAddress((void**)&pPart, g_part);

    // 1: pad A
    pad_atoms<<<(Bsz * Nn * KP + 255) / 256, 256>>>(atom_feats);
    // 2: transpose W_heads
    transpose_wheads<<<(KP * HD + 255) / 256, 256>>>(W_heads);
    // 3: pad fp
    pad_fp<<<(Bsz * KP1 + 255) / 256, 256>>>(fp);
    // 4: K1  Wh = Apad(32768x144) @ Wt(144x512)   <-- ncu capture target
    gemm_p2<4, 0, 0><<<dim3(HD / 128, (Bsz * Nn) / 128, 1), 256>>>(
        pApad, pWt, pWh, Bsz * Nn, HD, KP, KP, HD, HD, 0, 0, 0);
    // 5: gat1 scores + softmax -> P1
    sp1_kernel<<<Bsz * Hh, 256>>>(a_heads, adj);
    // 6: gat1 AV batched (128x64x128 per (b,h)) + elu -> g_h
    gemm_p2<2, 2, 1><<<dim3(1, 1, Bsz * Hh), 256>>>(
        pP1, pWh, ph, Nn, NHID, Nn, Nn, HD, HD,
        (long long)Nn * Nn, 0, 0);
    // 7: pad fc1_w
    pad_w1<<<(KP1 * FP2 + 255) / 256, 256>>>(fc1_w);
    // 8,9: fc1 split-K + reduce
    gemm_p2<4, 0, 0><<<dim3(FP2 / 128, Bsz / 128, FSPLIT), 256>>>(
        pFp, pW1, pPart, Bsz, FP2, FCHUNK, KP1, FP2, FP2,
        (long long)FCHUNK, (long long)FCHUNK * FP2, (long long)Bsz * FP2);
    fc1_reduce<<<(Bsz * FP2 + 255) / 256, 256>>>(fc1_b);
    // 10: K3  Wh2 = h(32768x512) @ W_out(512x300)
    gemm_p2<4, 0, 0><<<dim3((HID + 127) / 128, (Bsz * Nn) / 128, 1), 256>>>(
        ph, W_out, pWh2, Bsz * Nn, HID, HD, HD, HID, HID, 0, 0, 0);
    // 11: gat2 scores + probs
    sp2_kernel<<<Bsz, 256>>>(a_out, adj);
    // 12: gat2 AV batched GEMM + elu
    gemm_p2<4, 2, 0><<<dim3((HID + 127) / 128, 1, Bsz), 256>>>(
        pP, pWh2, pO, Nn, HID, Nn, Nn, HID, HID,
        (long long)Nn * Nn, (long long)Nn * HID, (long long)Nn * HID);
    // 13: gat2 log_softmax + mean
    ls2_kernel<<<Bsz, 256>>>();
    // 14: fused head
    head_fused<<<Bsz / HB, 256>>>(
        fc2_w, fc2_b, fc_gat_w, fc_gat_b, fc_fpn_w, fc_fpn_b,
        ffn_w1, ffn_b1, ffn_w2, ffn_b2, out);
}

// round 8
// speedup vs baseline: 1.8628x; 1.0130x over previous
#include <cuda_runtime.h>
#include <cuda_bf16.h>
#include <math.h>

// Problem constants
#define Bsz 256
#define Nn  128
#define Ff  133
#define KP  144          // Ff padded to multiple of 16
#define Hh  8
#define NHID 64
#define HID 300
#define FP_DIM 1489
#define KP1 1536         // FP_DIM padded
#define FSPLIT 8
#define FCHUNK 192       // KP1 / FSPLIT
#define FP2 512
#define HD (Hh*NHID)     // 512
#define ALPHA 0.2f
#define NEGV (-9e15f)

// ---------------- scratch (device globals; no allocation allowed) ----------------
__device__ float g_Apad[(size_t)Bsz*Nn * KP];
__device__ float g_Wt  [KP * HD];
__device__ float g_Wh  [(size_t)Bsz*Nn * HD];
__device__ float g_h   [(size_t)Bsz*Nn * HD];
__device__ float g_Wh2 [(size_t)Bsz*Nn * HID];
__device__ float g_ss2 [Bsz * Nn];
__device__ float g_dd2 [Bsz * Nn];
__device__ float g_O   [(size_t)Bsz*Nn * HID];
__device__ float g_gat [Bsz * HID];
__device__ float g_fppad[(size_t)Bsz * KP1];
__device__ float g_w1pad[(size_t)KP1 * FP2];
__device__ float g_part[(size_t)FSPLIT * Bsz * FP2];
__device__ float g_t1  [Bsz * FP2];

// ---------------- f32x2 helpers ----------------
#define FMA2(acc, a, b) \
    asm("fma.rn.f32x2 %0, %1, %2, %0;" : "+l"(acc) : "l"(a), "l"(b))

__device__ __forceinline__ unsigned long long ld2(const float* p) {
    return *reinterpret_cast<const unsigned long long*>(p);
}
__device__ __forceinline__ unsigned long long dup2(float x) {
    unsigned long long r;
    asm("mov.b64 %0, {%1, %1};" : "=l"(r) : "r"(__float_as_uint(x)));
    return r;
}
__device__ __forceinline__ float lo32(unsigned long long v) {
    return __uint_as_float((unsigned)v);
}
__device__ __forceinline__ float hi32(unsigned long long v) {
    return __uint_as_float((unsigned)(v >> 32));
}

__device__ __forceinline__ float warp_sum(float v) {
    #pragma unroll
    for (int o = 16; o; o >>= 1) v += __shfl_down_sync(0xffffffffu, v, o);
    return v;
}
__device__ __forceinline__ float warp_max(float v) {
    #pragma unroll
    for (int o = 16; o; o >>= 1) v = fmaxf(v, __shfl_down_sync(0xffffffffu, v, o));
    return v;
}

// ---------------- pad kernels ----------------------------------------------------
__global__ void pad_atoms(const float* __restrict__ src) {
    int t = blockIdx.x * blockDim.x + threadIdx.x;
    if (t >= Bsz * Nn * KP) return;
    int k = t % KP;
    int r = t / KP;
    g_Apad[t] = (k < Ff) ? src[(size_t)r * Ff + k] : 0.f;
}
__global__ void transpose_wheads(const float* __restrict__ W_heads) {
    int t = blockIdx.x * blockDim.x + threadIdx.x;
    if (t >= KP * HD) return;
    int f = t / HD;
    int r = t - f * HD;
    int h = r >> 6, d = r & 63;
    g_Wt[t] = (f < Ff) ? W_heads[((size_t)h * Ff + f) * NHID + d] : 0.f;
}
__global__ void pad_fp(const float* __restrict__ fp) {
    int t = blockIdx.x * blockDim.x + threadIdx.x;
    if (t >= Bsz * KP1) return;
    int k = t % KP1, r = t / KP1;
    g_fppad[t] = (k < FP_DIM) ? fp[(size_t)r * FP_DIM + k] : 0.f;
}
__global__ void pad_w1(const float* __restrict__ w) {
    int t = blockIdx.x * blockDim.x + threadIdx.x;
    if (t >= KP1 * FP2) return;
    int r = t / FP2;
    g_w1pad[t] = (r < FP_DIM) ? w[t] : 0.f;
}

// ============ gemm_p2: f32x2 GEMM, N-pair accumulators, double-buffered ==========
template<int CP, int ACT>
__global__ __launch_bounds__(256) void gemm_p2(
    const float* __restrict__ A, const float* __restrict__ B, float* __restrict__ C,
    int M, int N, int K, int lda, int ldb, int ldc,
    long long bA, long long bB, long long bC)
{
    __shared__ __align__(16) float As[2][16][132];
    __shared__ __align__(16) float Bs[2][16][32 * CP + 4];

    const int z = blockIdx.z;
    A += (long long)z * bA;
    B += (long long)z * bB;
    C += (long long)z * bC;

    const int tid = threadIdx.x;
    const int tx = tid & 15, ty = tid >> 4;
    const int row0 = blockIdx.y * 128, col0 = blockIdx.x * (32 * CP);

    const int am = tid >> 2;
    const int aq = (tid & 3) << 2;
    const int bk = tid >> 4;
    const int bn4 = (tid & 15) << 2;

    float4 ra0, ra1, rb[CP / 2];

    auto load_g = [&](int k0) {
        ra0 = *reinterpret_cast<const float4*>(A + (size_t)(row0 + am) * lda + k0 + aq);
        ra1 = *reinterpret_cast<const float4*>(A + (size_t)(row0 + am + 64) * lda + k0 + aq);
        #pragma unroll
        for (int jj2 = 0; jj2 < CP / 2; jj2++) {
            const int gc = col0 + bn4 + 64 * jj2;
            if (gc + 4 <= N) {
                rb[jj2] = *reinterpret_cast<const float4*>(B + (size_t)(k0 + bk) * ldb + gc);
            } else {
                rb[jj2].x = (gc + 0 < N) ? B[(size_t)(k0 + bk) * ldb + gc + 0] : 0.f;
                rb[jj2].y = (gc + 1 < N) ? B[(size_t)(k0 + bk) * ldb + gc + 1] : 0.f;
                rb[jj2].z = (gc + 2 < N) ? B[(size_t)(k0 + bk) * ldb + gc + 2] : 0.f;
                rb[jj2].w = (gc + 3 < N) ? B[(size_t)(k0 + bk) * ldb + gc + 3] : 0.f;
            }
        }
    };
    auto store_s = [&](int buf) {
        As[buf][aq + 0][am] = ra0.x;
        As[buf][aq + 1][am] = ra0.y;
        As[buf][aq + 2][am] = ra0.z;
        As[buf][aq + 3][am] = ra0.w;
        As[buf][aq + 0][am + 64] = ra1.x;
        As[buf][aq + 1][am + 64] = ra1.y;
        As[buf][aq + 2][am + 64] = ra1.z;
        As[buf][aq + 3][am + 64] = ra1.w;
        #pragma unroll
        for (int jj2 = 0; jj2 < CP / 2; jj2++)
            *reinterpret_cast<float4*>(&Bs[buf][bk][bn4 + 64 * jj2]) = rb[jj2];
    };

    unsigned long long acc[8][CP];
    #pragma unroll
    for (int i = 0; i < 8; i++)
        #pragma unroll
        for (int j = 0; j < CP; j++) acc[i][j] = 0ull;

    const int nsteps = K >> 4;
    load_g(0);
    store_s(0);
    __syncthreads();

    for (int s = 0; s < nsteps; s++) {
        const int cur = s & 1;
        if (s + 1 < nsteps) load_g((s + 1) << 4);
        #pragma unroll
        for (int k = 0; k < 16; k++) {
            unsigned long long aL[8], b2[CP];
            #pragma unroll
            for (int ii = 0; ii < 4; ii++) {
                const unsigned long long pr = ld2(&As[cur][k][2 * ty + 32 * ii]);
                aL[2 * ii]     = dup2(lo32(pr));
                aL[2 * ii + 1] = dup2(hi32(pr));
            }
            #pragma unroll
            for (int jj = 0; jj < CP; jj++) b2[jj] = ld2(&Bs[cur][k][2 * (tx + 16 * jj)]);
            #pragma unroll
            for (int i = 0; i < 8; i++)
                #pragma unroll
                for (int jj = 0; jj < CP; jj++)
                    FMA2(acc[i][jj], aL[i], b2[jj]);
        }
        if (s + 1 < nsteps) store_s(cur ^ 1);
        __syncthreads();
    }

    #pragma unroll
    for (int i = 0; i < 8; i++) {
        const int r = row0 + 2 * ty + 32 * (i >> 1) + (i & 1);
        #pragma unroll
        for (int jj = 0; jj < CP; jj++) {
            const int c = col0 + 2 * (tx + 16 * jj);
            if (c < N) {
                float v0 = lo32(acc[i][jj]);
                float v1 = hi32(acc[i][jj]);
                if (ACT == 2) {
                    v0 = (v0 > 0.f) ? v0 : expm1f(v0);
                    v1 = (v1 > 0.f) ? v1 : expm1f(v1);
                }
                *reinterpret_cast<float2*>(C + (size_t)r * ldc + c) = make_float2(v0, v1);
            }
        }
    }
}

// ---------------- fc1 reduce ------------------------------------------------------
__global__ void fc1_reduce(const float* __restrict__ fc1_b) {
    int t = blockIdx.x * blockDim.x + threadIdx.x;
    if (t >= Bsz * FP2) return;
    float s = 0.f;
    #pragma unroll
    for (int z = 0; z < FSPLIT; z++) s += g_part[(size_t)z * Bsz * FP2 + t];
    g_t1[t] = fmaxf(s + fc1_b[t & (FP2 - 1)], 0.f);
}

// ============ gat1_fused: scores + on-the-fly softmax probs + AV GEMM + elu ======
// one block per (b,h). A[i][k] = adj ? exp(leaky(ss[i]+dd[k])) : 0 generated per
// 128x16 tile; row sums accumulated in registers -> smem atomics; epilogue scales.
__global__ __launch_bounds__(256) void gat1_fused(const float* __restrict__ a_heads,
                                                  const int* __restrict__ adj)
{
    __shared__ __align__(16) float Ws[128 * 68];
    __shared__ __align__(16) float As[2][16][132];
    __shared__ float ss[128], dd[128], rsum[128];

    const int z = blockIdx.x;
    const int b = z >> 3, h = z & 7;
    const int tid = threadIdx.x, warp = tid >> 5, lane = tid & 31;
    const float* whbase = g_Wh + ((size_t)b * Nn) * HD + h * NHID;

    for (int s = tid; s < 2048; s += 256) {
        int j = s >> 4, q = (s & 15) << 2;
        float4 v = *reinterpret_cast<const float4*>(whbase + (size_t)j * HD + q);
        *reinterpret_cast<float4*>(&Ws[j * 68 + q]) = v;
    }
    if (tid < 128) rsum[tid] = 0.f;
    __syncthreads();

    // scores
    const float* a1 = a_heads + h * (2 * NHID);
    const float* a2v = a1 + NHID;
    for (int j = warp; j < 128; j += 8) {
        const float w0 = Ws[j * 68 + lane];
        const float w1 = Ws[j * 68 + lane + 32];
        float s1 = fmaf(w0, a1[lane], w1 * a1[lane + 32]);
        float s2 = fmaf(w0, a2v[lane], w1 * a2v[lane + 32]);
        s1 = warp_sum(s1); s2 = warp_sum(s2);
        if (lane == 0) { ss[j] = s1; dd[j] = s2; }
    }
    __syncthreads();

    const int* adjb = adj + (size_t)b * Nn * Nn;
    const int am = tid >> 2;
    const int aq = (tid & 3) << 2;
    const float sm0 = ss[am], sm1 = ss[am + 64];
    float rs0 = 0.f, rs1 = 0.f;
    int mm0[4], mm1[4];

    auto loadM = [&](int k0) {
        *reinterpret_cast<int4*>(mm0) = *reinterpret_cast<const int4*>(adjb + am * Nn + k0 + aq);
        *reinterpret_cast<int4*>(mm1) = *reinterpret_cast<const int4*>(adjb + (am + 64) * Nn + k0 + aq);
    };
    auto genStore = [&](int k0, int buf) {
        #pragma unroll
        for (int q = 0; q < 4; q++) {
            const float dv = dd[k0 + aq + q];
            float e0 = sm0 + dv; e0 = (e0 > 0.f) ? e0 : ALPHA * e0;
            float e1 = sm1 + dv; e1 = (e1 > 0.f) ? e1 : ALPHA * e1;
            float p0 = (mm0[q] > 0) ? __expf(e0) : 0.f;
            float p1 = (mm1[q] > 0) ? __expf(e1) : 0.f;
            rs0 += p0; rs1 += p1;
            As[buf][aq + q][am] = p0;
            As[buf][aq + q][am + 64] = p1;
        }
    };

    const int tx = tid & 15, ty = tid >> 4;
    unsigned long long acc[8][2];
    #pragma unroll
    for (int i = 0; i < 8; i++) { acc[i][0] = 0ull; acc[i][1] = 0ull; }

    loadM(0);
    genStore(0, 0);
    __syncthreads();

    for (int s = 0; s < 8; s++) {
        const int cur = s & 1;
        if (s < 7) loadM((s + 1) << 4);
        #pragma unroll
        for (int k = 0; k < 16; k++) {
            unsigned long long aL[8], b2[2];
            #pragma unroll
            for (int ii = 0; ii < 4; ii++) {
                const unsigned long long pr = ld2(&As[cur][k][2 * ty + 32 * ii]);
                aL[2 * ii]     = dup2(lo32(pr));
                aL[2 * ii + 1] = dup2(hi32(pr));
            }
            b2[0] = ld2(&Ws[(s * 16 + k) * 68 + 2 * tx]);
            b2[1] = ld2(&Ws[(s * 16 + k) * 68 + 2 * tx + 32]);
            #pragma unroll
            for (int i = 0; i < 8; i++) {
                FMA2(acc[i][0], aL[i], b2[0]);
                FMA2(acc[i][1], aL[i], b2[1]);
            }
        }
        if (s < 7) genStore((s + 1) << 4, cur ^ 1);
        __syncthreads();
    }

    atomicAdd(&rsum[am], rs0);
    atomicAdd(&rsum[am + 64], rs1);
    __syncthreads();

    float* outb = g_h + ((size_t)b * Nn) * HD + h * NHID;
    #pragma unroll
    for (int i = 0; i < 8; i++) {
        const int r = 2 * ty + 32 * (i >> 1) + (i & 1);
        const float inv = 1.f / rsum[r];
        #pragma unroll
        for (int jj = 0; jj < 2; jj++) {
            const int c = 2 * (tx + 16 * jj);
            float v0 = lo32(acc[i][jj]) * inv;
            float v1 = hi32(acc[i][jj]) * inv;
            v0 = (v0 > 0.f) ? v0 : expm1f(v0);
            v1 = (v1 > 0.f) ? v1 : expm1f(v1);
            *reinterpret_cast<float2*>(outb + (size_t)r * HD + c) = make_float2(v0, v1);
        }
    }
}

// ---------------- score2: gat2 scores -> g_ss2/g_dd2 -----------------------------
__global__ __launch_bounds__(256) void score2_kernel(const float* __restrict__ a_out)
{
    const int b = blockIdx.x;
    const int tid = threadIdx.x, warp = tid >> 5, lane = tid & 31;
    const float* W = g_Wh2 + (size_t)b * Nn * HID;
    for (int j = warp; j < 128; j += 8) {
        float s1 = 0.f, s2 = 0.f;
        #pragma unroll
        for (int t = 0; t < 10; t++) {
            int d = lane + 32 * t;
            if (d < HID) {
                float w = W[(size_t)j * HID + d];
                s1 = fmaf(w, a_out[d], s1);
                s2 = fmaf(w, a_out[HID + d], s2);
            }
        }
        s1 = warp_sum(s1); s2 = warp_sum(s2);
        if (lane == 0) { g_ss2[b * Nn + j] = s1; g_dd2[b * Nn + j] = s2; }
    }
}

// ============ av2f: gat2 on-the-fly probs + AV GEMM + elu ========================
// grid (3, 1, Bsz): col0 = bx*128, per-b block over all 128 rows.
__global__ __launch_bounds__(256) void av2f(const int* __restrict__ adj)
{
    __shared__ __align__(16) float As[2][16][132];
    __shared__ __align__(16) float Bs[2][16][132];
    __shared__ float ss[128], dd[128], rsum[128];

    const int b = blockIdx.z;
    const int col0 = blockIdx.x * 128;
    const int tid = threadIdx.x;
    const int tx = tid & 15, ty = tid >> 4;
    const int am = tid >> 2, aq = (tid & 3) << 2;
    const int bk = tid >> 4, bn4 = (tid & 15) << 2;

    if (tid < 128) {
        ss[tid] = g_ss2[b * Nn + tid];
        dd[tid] = g_dd2[b * Nn + tid];
        rsum[tid] = 0.f;
    }
    __syncthreads();

    const float* Bp = g_Wh2 + (size_t)b * Nn * HID;
    const int* adjb = adj + (size_t)b * Nn * Nn;
    const float sm0 = ss[am], sm1 = ss[am + 64];
    float rs0 = 0.f, rs1 = 0.f;
    int mm0[4], mm1[4];
    float4 rb[2];

    auto loadM = [&](int k0) {
        *reinterpret_cast<int4*>(mm0) = *reinterpret_cast<const int4*>(adjb + am * Nn + k0 + aq);
        *reinterpret_cast<int4*>(mm1) = *reinterpret_cast<const int4*>(adjb + (am + 64) * Nn + k0 + aq);
    };
    auto loadB = [&](int k0) {
        #pragma unroll
        for (int jj2 = 0; jj2 < 2; jj2++) {
            const int gc = col0 + bn4 + 64 * jj2;
            if (gc + 4 <= HID) {
                rb[jj2] = *reinterpret_cast<const float4*>(Bp + (size_t)(k0 + bk) * HID + gc);
            } else {
                rb[jj2].x = (gc + 0 < HID) ? Bp[(size_t)(k0 + bk) * HID + gc + 0] : 0.f;
                rb[jj2].y = (gc + 1 < HID) ? Bp[(size_t)(k0 + bk) * HID + gc + 1] : 0.f;
                rb[jj2].z = (gc + 2 < HID) ? Bp[(size_t)(k0 + bk) * HID + gc + 2] : 0.f;
                rb[jj2].w = (gc + 3 < HID) ? Bp[(size_t)(k0 + bk) * HID + gc + 3] : 0.f;
            }
        }
    };
    auto genStore = [&](int k0, int buf) {
        #pragma unroll
        for (int q = 0; q < 4; q++) {
            const float dv = dd[k0 + aq + q];
            float e0 = sm0 + dv; e0 = (e0 > 0.f) ? e0 : ALPHA * e0;
            float e1 = sm1 + dv; e1 = (e1 > 0.f) ? e1 : ALPHA * e1;
            float p0 = (mm0[q] > 0) ? __expf(e0) : 0.f;
            float p1 = (mm1[q] > 0) ? __expf(e1) : 0.f;
            rs0 += p0; rs1 += p1;
            As[buf][aq + q][am] = p0;
            As[buf][aq + q][am + 64] = p1;
        }
    };
    auto storeB = [&](int buf) {
        #pragma unroll
        for (int jj2 = 0; jj2 < 2; jj2++)
            *reinterpret_cast<float4*>(&Bs[buf][bk][bn4 + 64 * jj2]) = rb[jj2];
    };

    unsigned long long acc[8][4];
    #pragma unroll
    for (int i = 0; i < 8; i++)
        #pragma unroll
        for (int j = 0; j < 4; j++) acc[i][j] = 0ull;

    loadM(0);
    loadB(0);
    genStore(0, 0);
    storeB(0);
    __syncthreads();

    for (int s = 0; s < 8; s++) {
        const int cur = s & 1;
        if (s < 7) { loadM((s + 1) << 4); loadB((s + 1) << 4); }
        #pragma unroll
        for (int k = 0; k < 16; k++) {
            unsigned long long aL[8], b2[4];
            #pragma unroll
            for (int ii = 0; ii < 4; ii++) {
                const unsigned long long pr = ld2(&As[cur][k][2 * ty + 32 * ii]);
                aL[2 * ii]     = dup2(lo32(pr));
                aL[2 * ii + 1] = dup2(hi32(pr));
            }
            #pragma unroll
            for (int jj = 0; jj < 4; jj++) b2[jj] = ld2(&Bs[cur][k][2 * (tx + 16 * jj)]);
            #pragma unroll
            for (int i = 0; i < 8; i++)
                #pragma unroll
                for (int jj = 0; jj < 4; jj++)
                    FMA2(acc[i][jj], aL[i], b2[jj]);
        }
        if (s < 7) { genStore((s + 1) << 4, cur ^ 1); storeB(cur ^ 1); }
        __syncthreads();
    }

    atomicAdd(&rsum[am], rs0);
    atomicAdd(&rsum[am + 64], rs1);
    __syncthreads();

    float* Cb = g_O + (size_t)b * Nn * HID;
    #pragma unroll
    for (int i = 0; i < 8; i++) {
        const int r = 2 * ty + 32 * (i >> 1) + (i & 1);
        const float inv = 1.f / rsum[r];
        #pragma unroll
        for (int jj = 0; jj < 4; jj++) {
            const int c = col0 + 2 * (tx + 16 * jj);
            if (c < HID) {
                float v0 = lo32(acc[i][jj]) * inv;
                float v1 = hi32(acc[i][jj]) * inv;
                v0 = (v0 > 0.f) ? v0 : expm1f(v0);
                v1 = (v1 > 0.f) ? v1 : expm1f(v1);
                *reinterpret_cast<float2*>(Cb + (size_t)r * HID + c) = make_float2(v0, v1);
            }
        }
    }
}

// ---------------- ls2: log_softmax + mean ----------------------------------------
__global__ __launch_bounds__(256) void ls2_kernel()
{
    __shared__ float acc[8 * HID];
    const int b = blockIdx.x;
    const int tid = threadIdx.x, warp = tid >> 5, lane = tid & 31;
    for (int t = tid; t < 8 * HID; t += 256) acc[t] = 0.f;
    __syncthreads();

    const float* O = g_O + (size_t)b * Nn * HID;
    float* accw = acc + warp * HID;
    for (int i = warp; i < 128; i += 8) {
        float o[10];
        #pragma unroll
        for (int t = 0; t < 10; t++) {
            int d = lane + 32 * t;
            o[t] = (d < HID) ? O[(size_t)i * HID + d] : -1e30f;
        }
        float m = o[0];
        #pragma unroll
        for (int t = 1; t < 10; t++) m = fmaxf(m, o[t]);
        m = warp_max(m);
        m = __shfl_sync(0xffffffffu, m, 0);
        float se = 0.f;
        #pragma unroll
        for (int t = 0; t < 10; t++) se += __expf(o[t] - m);
        se = warp_sum(se);
        se = __shfl_sync(0xffffffffu, se, 0);
        const float lse = m + logf(se);
        #pragma unroll
        for (int t = 0; t < 10; t++) {
            int d = lane + 32 * t;
            if (d < HID) accw[d] += o[t] - lse;
        }
    }
    __syncthreads();
    for (int d = tid; d < HID; d += 256) {
        float s = 0.f;
        #pragma unroll
        for (int w = 0; w < 8; w++) s += acc[w * HID + d];
        g_gat[b * HID + d] = s * (1.f / 128.f);
    }
}

// ---------------- head: fc2 + fc_gat + fc_fpn + ffn1 + ffn2 + sigmoid ------------
#define HB 4
__global__ __launch_bounds__(256) void head_fused(
    const float* __restrict__ fc2_w, const float* __restrict__ fc2_b,
    const float* __restrict__ Wg,    const float* __restrict__ bg,
    const float* __restrict__ Wf,    const float* __restrict__ bf,
    const float* __restrict__ W1,    const float* __restrict__ b1,
    const float* __restrict__ w2,    const float* __restrict__ b2,
    float* __restrict__ out)
{
    __shared__ float t1s [HB][512];
    __shared__ float gats[HB][HID];
    __shared__ float fpns[HB][HID];
    __shared__ float us  [HB][HID];
    __shared__ float vs  [HB][HID];
    __shared__ float ys  [HB][HID];

    const int b0 = blockIdx.x * HB;
    const int tid = threadIdx.x;

    for (int t = tid; t < HB * 512; t += 256) {
        int r = t >> 9;
        t1s[r][t & 511] = g_t1[(size_t)(b0 + r) * FP2 + (t & 511)];
    }
    for (int t = tid; t < HB * HID; t += 256) {
        int r = t / HID, c = t - r * HID;
        gats[r][c] = g_gat[(size_t)(b0 + r) * HID + c];
    }
    __syncthreads();

    for (int c = tid; c < HID; c += 256) {
        float a[HB] = {};
        #pragma unroll 4
        for (int k = 0; k < 512; k++) {
            float w = fc2_w[(size_t)k * HID + c];
            #pragma unroll
            for (int r = 0; r < HB; r++) a[r] = fmaf(t1s[r][k], w, a[r]);
        }
        float bb = fc2_b[c];
        #pragma unroll
        for (int r = 0; r < HB; r++) fpns[r][c] = a[r] + bb;
    }
    __syncthreads();

    for (int c = tid; c < HID; c += 256) {
        float a[HB] = {}, e[HB] = {};
        #pragma unroll 4
        for (int k = 0; k < HID; k++) {
            float wg = Wg[(size_t)k * HID + c];
            float wf = Wf[(size_t)k * HID + c];
            #pragma unroll
            for (int r = 0; r < HB; r++) {
                a[r] = fmaf(gats[r][k], wg, a[r]);
                e[r] = fmaf(fpns[r][k], wf, e[r]);
            }
        }
        float bbg = bg[c], bbf = bf[c];
        #pragma unroll
        for (int r = 0; r < HB; r++) {
            us[r][c] = fmaxf(a[r] + bbg, 0.f);
            vs[r][c] = fmaxf(e[r] + bbf, 0.f);
        }
    }
    __syncthreads();

    for (int c = tid; c < HID; c += 256) {
        float a[HB] = {};
        #pragma unroll 4
        for (int k = 0; k < HID; k++) {
            float w = W1[(size_t)k * HID + c];
            #pragma unroll
            for (int r = 0; r < HB; r++) a[r] = fmaf(us[r][k], w, a[r]);
        }
        #pragma unroll 4
        for (int k = 0; k < HID; k++) {
            float w = W1[(size_t)(k + HID) * HID + c];
            #pragma unroll
            for (int r = 0; r < HB; r++) a[r] = fmaf(vs[r][k], w, a[r]);
        }
        float bb = b1[c];
        #pragma unroll
        for (int r = 0; r < HB; r++) ys[r][c] = fmaxf(a[r] + bb, 0.f);
    }
    __syncthreads();

    const int warp = tid >> 5, lane = tid & 31;
    if (warp < HB) {
        float s = 0.f;
        for (int k = lane; k < HID; k += 32) s = fmaf(ys[warp][k], w2[k], s);
        s = warp_sum(s);
        if (lane == 0) out[b0 + warp] = 1.f / (1.f + expf(-(s + b2[0])));
    }
}

// ---------------- launch ----------------
extern "C" void kernel_launch(void* const* d_in, const int* in_sizes, int n_in,
                              void* d_out, int out_size)
{
    const float* atom_feats = (const float*)d_in[0];
    const float* fp         = (const float*)d_in[1];
    const float* W_heads    = (const float*)d_in[2];
    const float* a_heads    = (const float*)d_in[3];
    const float* W_out      = (const float*)d_in[4];
    const float* a_out      = (const float*)d_in[5];
    const float* fc1_w      = (const float*)d_in[6];
    const float* fc1_b      = (const float*)d_in[7];
    const float* fc2_w      = (const float*)d_in[8];
    const float* fc2_b      = (const float*)d_in[9];
    const float* fc_gat_w   = (const float*)d_in[10];
    const float* fc_gat_b   = (const float*)d_in[11];
    const float* fc_fpn_w   = (const float*)d_in[12];
    const float* fc_fpn_b   = (const float*)d_in[13];
    const float* ffn_w1     = (const float*)d_in[14];
    const float* ffn_b1     = (const float*)d_in[15];
    const float* ffn_w2     = (const float*)d_in[16];
    const float* ffn_b2     = (const float*)d_in[17];
    const int*   adj        = (const int*)  d_in[18];
    float* out = (float*)d_out;

    float *pApad, *pWt, *pWh, *ph, *pWh2, *pFp, *pW1, *pPart;
    cudaGetSymbolAddress((void**)&pApad, g_Apad);
    cudaGetSymbolAddress((void**)&pWt,   g_Wt);
    cudaGetSymbolAddress((void**)&pWh,   g_Wh);
    cudaGetSymbolAddress((void**)&ph,    g_h);
    cudaGetSymbolAddress((void**)&pWh2,  g_Wh2);
    cudaGetSymbolAddress((void**)&pFp,   g_fppad);
    cudaGetSymbolAddress((void**)&pW1,   g_w1pad);
    cudaGetSymbolAddress((void**)&pPart, g_part);

    // 1: pad A
    pad_atoms<<<(Bsz * Nn * KP + 255) / 256, 256>>>(atom_feats);
    // 2: transpose W_heads
    transpose_wheads<<<(KP * HD + 255) / 256, 256>>>(W_heads);
    // 3: K1  Wh = Apad(32768x144) @ Wt(144x512)
    gemm_p2<4, 0><<<dim3(HD / 128, (Bsz * Nn) / 128, 1), 256>>>(
        pApad, pWt, pWh, Bsz * Nn, HD, KP, KP, HD, HD, 0, 0, 0);
    // 4: gat1 fused (scores + softmax + AV + elu)   <-- ncu capture target
    gat1_fused<<<Bsz * Hh, 256>>>(a_heads, adj);
    // 5,6: fp pads
    pad_fp<<<(Bsz * KP1 + 255) / 256, 256>>>(fp);
    pad_w1<<<(KP1 * FP2 + 255) / 256, 256>>>(fc1_w);
    // 7,8: fc1 split-K + reduce
    gemm_p2<4, 0><<<dim3(FP2 / 128, Bsz / 128, FSPLIT), 256>>>(
        pFp, pW1, pPart, Bsz, FP2, FCHUNK, KP1, FP2, FP2,
        (long long)FCHUNK, (long long)FCHUNK * FP2, (long long)Bsz * FP2);
    fc1_reduce<<<(Bsz * FP2 + 255) / 256, 256>>>(fc1_b);
    // 9: K3  Wh2 = h(32768x512) @ W_out(512x300)
    gemm_p2<4, 0><<<dim3((HID + 127) / 128, (Bsz * Nn) / 128, 1), 256>>>(
        ph, W_out, pWh2, Bsz * Nn, HID, HD, HD, HID, HID, 0, 0, 0);
    // 10: gat2 scores
    score2_kernel<<<Bsz, 256>>>(a_out);
    // 11: gat2 fused probs + AV + elu
    av2f<<<dim3(3, 1, Bsz), 256>>>(adj);
    // 12: gat2 log_softmax + mean
    ls2_kernel<<<Bsz, 256>>>();
    // 13: fused head
    head_fused<<<Bsz / HB, 256>>>(
        fc2_w, fc2_b, fc_gat_w, fc_gat_b, fc_fpn_w, fc_fpn_b,
        ffn_w1, ffn_b1, ffn_w2, ffn_b2, out);
}

// round 10
// speedup vs baseline: 1.9959x; 1.0715x over previous
#include <cuda_runtime.h>
#include <cuda_bf16.h>
#include <math.h>

// Problem constants
#define Bsz 256
#define Nn  128
#define Ff  133
#define Hh  8
#define NHID 64
#define HID 300
#define FP_DIM 1489
#define KP1 1536         // FP_DIM padded
#define FSPLIT 8
#define FCHUNK 192       // KP1 / FSPLIT
#define FP2 512
#define HD (Hh*NHID)     // 512
#define ALPHA 0.2f
#define NEGV (-9e15f)

#define K1P   144        // Ff padded to multiple of 16
#define K1T   (3*K1P)    // 432  packed-K for K1
#define K3T   (3*HD)     // 1536 packed-K for K3
#define N3P   384        // HID padded to 3 tiles of 128

// ---------------- scratch (device globals; no allocation allowed) ----------------
__device__ __nv_bfloat16 g_Apk [(size_t)Bsz*Nn * K1T];   // atom feats packed [Ah|Ah|Al]
__device__ __nv_bfloat16 g_Bpk1[(size_t)HD * K1T];       // W_heads^T packed [Bh|Bl|Bh]
__device__ float         g_Wh  [(size_t)Bsz*Nn * HD];
__device__ __nv_bfloat16 g_hpk [(size_t)Bsz*Nn * K3T];   // gat1 out packed [Ah|Ah|Al]
__device__ __nv_bfloat16 g_Bpk3[(size_t)N3P * K3T];      // W_out^T packed [Bh|Bl|Bh]
__device__ float g_Wh2 [(size_t)Bsz*Nn * HID];
__device__ float g_ss2 [Bsz * Nn];
__device__ float g_dd2 [Bsz * Nn];
__device__ float g_O   [(size_t)Bsz*Nn * HID];
__device__ float g_gat [Bsz * HID];
__device__ float g_fppad[(size_t)Bsz * KP1];
__device__ float g_w1pad[(size_t)KP1 * FP2];
__device__ float g_part[(size_t)FSPLIT * Bsz * FP2];
__device__ float g_t1  [Bsz * FP2];

// ---------------- f32x2 helpers ----------------
#define FMA2(acc, a, b) \
    asm("fma.rn.f32x2 %0, %1, %2, %0;" : "+l"(acc) : "l"(a), "l"(b))

__device__ __forceinline__ unsigned long long ld2(const float* p) {
    return *reinterpret_cast<const unsigned long long*>(p);
}
__device__ __forceinline__ unsigned long long dup2(float x) {
    unsigned long long r;
    asm("mov.b64 %0, {%1, %1};" : "=l"(r) : "r"(__float_as_uint(x)));
    return r;
}
__device__ __forceinline__ float lo32(unsigned long long v) {
    return __uint_as_float((unsigned)v);
}
__device__ __forceinline__ float hi32(unsigned long long v) {
    return __uint_as_float((unsigned)(v >> 32));
}
__device__ __forceinline__ float warp_sum(float v) {
    #pragma unroll
    for (int o = 16; o; o >>= 1) v += __shfl_down_sync(0xffffffffu, v, o);
    return v;
}
__device__ __forceinline__ float warp_max(float v) {
    #pragma unroll
    for (int o = 16; o; o >>= 1) v = fmaxf(v, __shfl_down_sync(0xffffffffu, v, o));
    return v;
}

// ================= mma_gemm: bf16 HMMA GEMM, 128x128 tile ========================
// C(f32 [M][ldc]) = A(bf16 [M][Ktot]) @ B(bf16 [Ncover][Ktot])^T
// Ktot % 16 == 0. 256 threads, warp grid 4(m) x 2(n), warp tile 32x64.
#define MSTR 24   // smem row stride in bf16 (48B: 16B-aligned, conflict-free frags)
__global__ __launch_bounds__(256) void mma_gemm(
    const __nv_bfloat16* __restrict__ A, const __nv_bfloat16* __restrict__ B,
    float* __restrict__ C, int Ktot, int Nreal, int ldc)
{
    __shared__ __align__(16) __nv_bfloat16 As[2][128][MSTR];
    __shared__ __align__(16) __nv_bfloat16 Bs[2][128][MSTR];

    const int tid = threadIdx.x;
    const int wid = tid >> 5, lane = tid & 31;
    const int wy = wid & 3, wx = wid >> 2;        // warp tile: rows wy*32, cols wx*64
    const int gid = lane >> 2, tig = lane & 3;
    const int row0 = blockIdx.y * 128, col0 = blockIdx.x * 128;

    const int lr = tid >> 1;            // 0..127 load row
    const int lh = (tid & 1) << 3;      // 0 or 8 (bf16 offset)

    uint4 va, vb;
    auto load_g = [&](int k0) {
        va = *reinterpret_cast<const uint4*>(A + (size_t)(row0 + lr) * Ktot + k0 + lh);
        vb = *reinterpret_cast<const uint4*>(B + (size_t)(col0 + lr) * Ktot + k0 + lh);
    };
    auto store_s = [&](int buf) {
        *reinterpret_cast<uint4*>(&As[buf][lr][lh]) = va;
        *reinterpret_cast<uint4*>(&Bs[buf][lr][lh]) = vb;
    };

    float acc[2][8][4];
    #pragma unroll
    for (int mt = 0; mt < 2; mt++)
        #pragma unroll
        for (int nt = 0; nt < 8; nt++)
            #pragma unroll
            for (int q = 0; q < 4; q++) acc[mt][nt][q] = 0.f;

    const int nsteps = Ktot >> 4;
    load_g(0);
    store_s(0);
    __syncthreads();

    for (int s = 0; s < nsteps; s++) {
        const int cur = s & 1;
        if (s + 1 < nsteps) load_g((s + 1) << 4);

        unsigned af[2][4], bf[8][2];
        #pragma unroll
        for (int mt = 0; mt < 2; mt++) {
            const int mr = wy * 32 + mt * 16 + gid;
            af[mt][0] = *reinterpret_cast<const unsigned*>(&As[cur][mr][2 * tig]);
            af[mt][1] = *reinterpret_cast<const unsigned*>(&As[cur][mr + 8][2 * tig]);
            af[mt][2] = *reinterpret_cast<const unsigned*>(&As[cur][mr][2 * tig + 8]);
            af[mt][3] = *reinterpret_cast<const unsigned*>(&As[cur][mr + 8][2 * tig + 8]);
        }
        #pragma unroll
        for (int nt = 0; nt < 8; nt++) {
            const int nr = wx * 64 + nt * 8 + gid;
            bf[nt][0] = *reinterpret_cast<const unsigned*>(&Bs[cur][nr][2 * tig]);
            bf[nt][1] = *reinterpret_cast<const unsigned*>(&Bs[cur][nr][2 * tig + 8]);
        }
        #pragma unroll
        for (int mt = 0; mt < 2; mt++)
            #pragma unroll
            for (int nt = 0; nt < 8; nt++)
                asm volatile(
                    "mma.sync.aligned.m16n8k16.row.col.f32.bf16.bf16.f32 "
                    "{%0,%1,%2,%3}, {%4,%5,%6,%7}, {%8,%9}, {%0,%1,%2,%3};"
                    : "+f"(acc[mt][nt][0]), "+f"(acc[mt][nt][1]),
                      "+f"(acc[mt][nt][2]), "+f"(acc[mt][nt][3])
                    : "r"(af[mt][0]), "r"(af[mt][1]), "r"(af[mt][2]), "r"(af[mt][3]),
                      "r"(bf[nt][0]), "r"(bf[nt][1]));

        if (s + 1 < nsteps) store_s(cur ^ 1);
        __syncthreads();
    }

    // epilogue: d0,d1 -> row gid cols 2tig,2tig+1 ; d2,d3 -> row gid+8
    #pragma unroll
    for (int mt = 0; mt < 2; mt++) {
        const int r0 = row0 + wy * 32 + mt * 16 + gid;
        #pragma unroll
        for (int nt = 0; nt < 8; nt++) {
            const int c = col0 + wx * 64 + nt * 8 + 2 * tig;
            if (c < Nreal) {
                *reinterpret_cast<float2*>(C + (size_t)r0 * ldc + c) =
                    make_float2(acc[mt][nt][0], acc[mt][nt][1]);
                *reinterpret_cast<float2*>(C + (size_t)(r0 + 8) * ldc + c) =
                    make_float2(acc[mt][nt][2], acc[mt][nt][3]);
            }
        }
    }
}

// ---------------- packing kernels ------------------------------------------------
__global__ void pack_atoms(const float* __restrict__ src) {
    int t = blockIdx.x * blockDim.x + threadIdx.x;
    if (t >= Bsz * Nn * K1P) return;
    int k = t % K1P, r = t / K1P;
    float x = (k < Ff) ? src[(size_t)r * Ff + k] : 0.f;
    __nv_bfloat16 hi = __float2bfloat16(x);
    __nv_bfloat16 lo = __float2bfloat16(x - __bfloat162float(hi));
    __nv_bfloat16* row = g_Apk + (size_t)r * K1T;
    row[k] = hi; row[K1P + k] = hi; row[2 * K1P + k] = lo;
}
__global__ void pack_B1(const float* __restrict__ W_heads) {
    int t = blockIdx.x * blockDim.x + threadIdx.x;
    if (t >= HD * K1P) return;
    int k = t % K1P, n = t / K1P;
    int h = n >> 6, d = n & 63;
    float x = (k < Ff) ? W_heads[((size_t)h * Ff + k) * NHID + d] : 0.f;
    __nv_bfloat16 hi = __float2bfloat16(x);
    __nv_bfloat16 lo = __float2bfloat16(x - __bfloat162float(hi));
    __nv_bfloat16* row = g_Bpk1 + (size_t)n * K1T;
    row[k] = hi; row[K1P + k] = lo; row[2 * K1P + k] = hi;
}
__global__ void pack_B3(const float* __restrict__ W_out) {
    int t = blockIdx.x * blockDim.x + threadIdx.x;
    if (t >= N3P * HD) return;
    int k = t % HD, n = t / HD;
    float x = (n < HID) ? W_out[(size_t)k * HID + n] : 0.f;
    __nv_bfloat16 hi = __float2bfloat16(x);
    __nv_bfloat16 lo = __float2bfloat16(x - __bfloat162float(hi));
    __nv_bfloat16* row = g_Bpk3 + (size_t)n * K3T;
    row[k] = hi; row[HD + k] = lo; row[2 * HD + k] = hi;
}
__global__ void pad_fp(const float* __restrict__ fp) {
    int t = blockIdx.x * blockDim.x + threadIdx.x;
    if (t >= Bsz * KP1) return;
    int k = t % KP1, r = t / KP1;
    g_fppad[t] = (k < FP_DIM) ? fp[(size_t)r * FP_DIM + k] : 0.f;
}
__global__ void pad_w1(const float* __restrict__ w) {
    int t = blockIdx.x * blockDim.x + threadIdx.x;
    if (t >= KP1 * FP2) return;
    int r = t / FP2;
    g_w1pad[t] = (r < FP_DIM) ? w[t] : 0.f;
}

// ============ gemm_p2 (fc1): f32x2 GEMM, double-buffered =========================
template<int CP, int ACT>
__global__ __launch_bounds__(256) void gemm_p2(
    const float* __restrict__ A, const float* __restrict__ B, float* __restrict__ C,
    int M, int N, int K, int lda, int ldb, int ldc,
    long long bA, long long bB, long long bC)
{
    __shared__ __align__(16) float As[2][16][132];
    __shared__ __align__(16) float Bs[2][16][32 * CP + 4];

    const int z = blockIdx.z;
    A += (long long)z * bA;
    B += (long long)z * bB;
    C += (long long)z * bC;

    const int tid = threadIdx.x;
    const int tx = tid & 15, ty = tid >> 4;
    const int row0 = blockIdx.y * 128, col0 = blockIdx.x * (32 * CP);

    const int am = tid >> 2;
    const int aq = (tid & 3) << 2;
    const int bk = tid >> 4;
    const int bn4 = (tid & 15) << 2;

    float4 ra0, ra1, rb[CP / 2];
    auto load_g = [&](int k0) {
        ra0 = *reinterpret_cast<const float4*>(A + (size_t)(row0 + am) * lda + k0 + aq);
        ra1 = *reinterpret_cast<const float4*>(A + (size_t)(row0 + am + 64) * lda + k0 + aq);
        #pragma unroll
        for (int jj2 = 0; jj2 < CP / 2; jj2++) {
            const int gc = col0 + bn4 + 64 * jj2;
            if (gc + 4 <= N) {
                rb[jj2] = *reinterpret_cast<const float4*>(B + (size_t)(k0 + bk) * ldb + gc);
            } else {
                rb[jj2].x = (gc + 0 < N) ? B[(size_t)(k0 + bk) * ldb + gc + 0] : 0.f;
                rb[jj2].y = (gc + 1 < N) ? B[(size_t)(k0 + bk) * ldb + gc + 1] : 0.f;
                rb[jj2].z = (gc + 2 < N) ? B[(size_t)(k0 + bk) * ldb + gc + 2] : 0.f;
                rb[jj2].w = (gc + 3 < N) ? B[(size_t)(k0 + bk) * ldb + gc + 3] : 0.f;
            }
        }
    };
    auto store_s = [&](int buf) {
        As[buf][aq + 0][am] = ra0.x;
        As[buf][aq + 1][am] = ra0.y;
        As[buf][aq + 2][am] = ra0.z;
        As[buf][aq + 3][am] = ra0.w;
        As[buf][aq + 0][am + 64] = ra1.x;
        As[buf][aq + 1][am + 64] = ra1.y;
        As[buf][aq + 2][am + 64] = ra1.z;
        As[buf][aq + 3][am + 64] = ra1.w;
        #pragma unroll
        for (int jj2 = 0; jj2 < CP / 2; jj2++)
            *reinterpret_cast<float4*>(&Bs[buf][bk][bn4 + 64 * jj2]) = rb[jj2];
    };

    unsigned long long acc[8][CP];
    #pragma unroll
    for (int i = 0; i < 8; i++)
        #pragma unroll
        for (int j = 0; j < CP; j++) acc[i][j] = 0ull;

    const int nsteps = K >> 4;
    load_g(0);
    store_s(0);
    __syncthreads();

    for (int s = 0; s < nsteps; s++) {
        const int cur = s & 1;
        if (s + 1 < nsteps) load_g((s + 1) << 4);
        #pragma unroll
        for (int k = 0; k < 16; k++) {
            unsigned long long aL[8], b2[CP];
            #pragma unroll
            for (int ii = 0; ii < 4; ii++) {
                const unsigned long long pr = ld2(&As[cur][k][2 * ty + 32 * ii]);
                aL[2 * ii]     = dup2(lo32(pr));
                aL[2 * ii + 1] = dup2(hi32(pr));
            }
            #pragma unroll
            for (int jj = 0; jj < CP; jj++) b2[jj] = ld2(&Bs[cur][k][2 * (tx + 16 * jj)]);
            #pragma unroll
            for (int i = 0; i < 8; i++)
                #pragma unroll
                for (int jj = 0; jj < CP; jj++)
                    FMA2(acc[i][jj], aL[i], b2[jj]);
        }
        if (s + 1 < nsteps) store_s(cur ^ 1);
        __syncthreads();
    }

    #pragma unroll
    for (int i = 0; i < 8; i++) {
        const int r = row0 + 2 * ty + 32 * (i >> 1) + (i & 1);
        #pragma unroll
        for (int jj = 0; jj < CP; jj++) {
            const int c = col0 + 2 * (tx + 16 * jj);
            if (c < N) {
                float v0 = lo32(acc[i][jj]);
                float v1 = hi32(acc[i][jj]);
                if (ACT == 2) {
                    v0 = (v0 > 0.f) ? v0 : expm1f(v0);
                    v1 = (v1 > 0.f) ? v1 : expm1f(v1);
                }
                *reinterpret_cast<float2*>(C + (size_t)r * ldc + c) = make_float2(v0, v1);
            }
        }
    }
}

// ---------------- fc1 reduce ------------------------------------------------------
__global__ void fc1_reduce(const float* __restrict__ fc1_b) {
    int t = blockIdx.x * blockDim.x + threadIdx.x;
    if (t >= Bsz * FP2) return;
    float s = 0.f;
    #pragma unroll
    for (int z = 0; z < FSPLIT; z++) s += g_part[(size_t)z * Bsz * FP2 + t];
    g_t1[t] = fmaxf(s + fc1_b[t & (FP2 - 1)], 0.f);
}

// ============ gat1_fused: scores + on-the-fly probs + AV GEMM + elu ==============
// epilogue writes h directly in packed split-bf16 layout into g_hpk.
__global__ __launch_bounds__(256) void gat1_fused(const float* __restrict__ a_heads,
                                                  const int* __restrict__ adj)
{
    __shared__ __align__(16) float Ws[128 * 68];
    __shared__ __align__(16) float As[2][16][132];
    __shared__ float ss[128], dd[128], rsum[128];

    const int z = blockIdx.x;
    const int b = z >> 3, h = z & 7;
    const int tid = threadIdx.x, warp = tid >> 5, lane = tid & 31;
    const float* whbase = g_Wh + ((size_t)b * Nn) * HD + h * NHID;

    for (int s = tid; s < 2048; s += 256) {
        int j = s >> 4, q = (s & 15) << 2;
        float4 v = *reinterpret_cast<const float4*>(whbase + (size_t)j * HD + q);
        *reinterpret_cast<float4*>(&Ws[j * 68 + q]) = v;
    }
    if (tid < 128) rsum[tid] = 0.f;
    __syncthreads();

    const float* a1 = a_heads + h * (2 * NHID);
    const float* a2v = a1 + NHID;
    for (int j = warp; j < 128; j += 8) {
        const float w0 = Ws[j * 68 + lane];
        const float w1 = Ws[j * 68 + lane + 32];
        float s1 = fmaf(w0, a1[lane], w1 * a1[lane + 32]);
        float s2 = fmaf(w0, a2v[lane], w1 * a2v[lane + 32]);
        s1 = warp_sum(s1); s2 = warp_sum(s2);
        if (lane == 0) { ss[j] = s1; dd[j] = s2; }
    }
    __syncthreads();

    const int* adjb = adj + (size_t)b * Nn * Nn;
    const int am = tid >> 2;
    const int aq = (tid & 3) << 2;
    const float sm0 = ss[am], sm1 = ss[am + 64];
    float rs0 = 0.f, rs1 = 0.f;
    int mm0[4], mm1[4];

    auto loadM = [&](int k0) {
        *reinterpret_cast<int4*>(mm0) = *reinterpret_cast<const int4*>(adjb + am * Nn + k0 + aq);
        *reinterpret_cast<int4*>(mm1) = *reinterpret_cast<const int4*>(adjb + (am + 64) * Nn + k0 + aq);
    };
    auto genStore = [&](int k0, int buf) {
        #pragma unroll
        for (int q = 0; q < 4; q++) {
            const float dv = dd[k0 + aq + q];
            float e0 = sm0 + dv; e0 = (e0 > 0.f) ? e0 : ALPHA * e0;
            float e1 = sm1 + dv; e1 = (e1 > 0.f) ? e1 : ALPHA * e1;
            float p0 = (mm0[q] > 0) ? __expf(e0) : 0.f;
            float p1 = (mm1[q] > 0) ? __expf(e1) : 0.f;
            rs0 += p0; rs1 += p1;
            As[buf][aq + q][am] = p0;
            As[buf][aq + q][am + 64] = p1;
        }
    };

    const int tx = tid & 15, ty = tid >> 4;
    unsigned long long acc[8][2];
    #pragma unroll
    for (int i = 0; i < 8; i++) { acc[i][0] = 0ull; acc[i][1] = 0ull; }

    loadM(0);
    genStore(0, 0);
    __syncthreads();

    for (int s = 0; s < 8; s++) {
        const int cur = s & 1;
        if (s < 7) loadM((s + 1) << 4);
        #pragma unroll
        for (int k = 0; k < 16; k++) {
            unsigned long long aL[8], b2[2];
            #pragma unroll
            for (int ii = 0; ii < 4; ii++) {
                const unsigned long long pr = ld2(&As[cur][k][2 * ty + 32 * ii]);
                aL[2 * ii]     = dup2(lo32(pr));
                aL[2 * ii + 1] = dup2(hi32(pr));
            }
            b2[0] = ld2(&Ws[(s * 16 + k) * 68 + 2 * tx]);
            b2[1] = ld2(&Ws[(s * 16 + k) * 68 + 2 * tx + 32]);
            #pragma unroll
            for (int i = 0; i < 8; i++) {
                FMA2(acc[i][0], aL[i], b2[0]);
                FMA2(acc[i][1], aL[i], b2[1]);
            }
        }
        if (s < 7) genStore((s + 1) << 4, cur ^ 1);
        __syncthreads();
    }

    atomicAdd(&rsum[am], rs0);
    atomicAdd(&rsum[am + 64], rs1);
    __syncthreads();

    #pragma unroll
    for (int i = 0; i < 8; i++) {
        const int r = 2 * ty + 32 * (i >> 1) + (i & 1);
        const float inv = 1.f / rsum[r];
        __nv_bfloat16* rowp = g_hpk + (size_t)(b * Nn + r) * K3T + h * NHID;
        #pragma unroll
        for (int jj = 0; jj < 2; jj++) {
            const int c = 2 * (tx + 16 * jj);
            float v0 = lo32(acc[i][jj]) * inv;
            float v1 = hi32(acc[i][jj]) * inv;
            v0 = (v0 > 0.f) ? v0 : expm1f(v0);
            v1 = (v1 > 0.f) ? v1 : expm1f(v1);
            __nv_bfloat16 h0 = __float2bfloat16(v0);
            __nv_bfloat16 h1 = __float2bfloat16(v1);
            __nv_bfloat16 l0 = __float2bfloat16(v0 - __bfloat162float(h0));
            __nv_bfloat16 l1 = __float2bfloat16(v1 - __bfloat162float(h1));
            unsigned hp = (unsigned)__bfloat16_as_ushort(h0) | ((unsigned)__bfloat16_as_ushort(h1) << 16);
            unsigned lp = (unsigned)__bfloat16_as_ushort(l0) | ((unsigned)__bfloat16_as_ushort(l1) << 16);
            *reinterpret_cast<unsigned*>(rowp + c)           = hp;
            *reinterpret_cast<unsigned*>(rowp + HD + c)      = hp;
            *reinterpret_cast<unsigned*>(rowp + 2 * HD + c)  = lp;
        }
    }
}

// ---------------- score2 ----------------------------------------------------------
__global__ __launch_bounds__(256) void score2_kernel(const float* __restrict__ a_out)
{
    const int b = blockIdx.x;
    const int tid = threadIdx.x, warp = tid >> 5, lane = tid & 31;
    const float* W = g_Wh2 + (size_t)b * Nn * HID;
    for (int j = warp; j < 128; j += 8) {
        float s1 = 0.f, s2 = 0.f;
        #pragma unroll
        for (int t = 0; t < 10; t++) {
            int d = lane + 32 * t;
            if (d < HID) {
                float w = W[(size_t)j * HID + d];
                s1 = fmaf(w, a_out[d], s1);
                s2 = fmaf(w, a_out[HID + d], s2);
            }
        }
        s1 = warp_sum(s1); s2 = warp_sum(s2);
        if (lane == 0) { g_ss2[b * Nn + j] = s1; g_dd2[b * Nn + j] = s2; }
    }
}

// ============ av2f: gat2 on-the-fly probs + AV GEMM + elu ========================
__global__ __launch_bounds__(256) void av2f(const int* __restrict__ adj)
{
    __shared__ __align__(16) float As[2][16][132];
    __shared__ __align__(16) float Bs[2][16][132];
    __shared__ float ss[128], dd[128], rsum[128];

    const int b = blockIdx.z;
    const int col0 = blockIdx.x * 128;
    const int tid = threadIdx.x;
    const int tx = tid & 15, ty = tid >> 4;
    const int am = tid >> 2, aq = (tid & 3) << 2;
    const int bk = tid >> 4, bn4 = (tid & 15) << 2;

    if (tid < 128) {
        ss[tid] = g_ss2[b * Nn + tid];
        dd[tid] = g_dd2[b * Nn + tid];
        rsum[tid] = 0.f;
    }
    __syncthreads();

    const float* Bp = g_Wh2 + (size_t)b * Nn * HID;
    const int* adjb = adj + (size_t)b * Nn * Nn;
    const float sm0 = ss[am], sm1 = ss[am + 64];
    float rs0 = 0.f, rs1 = 0.f;
    int mm0[4], mm1[4];
    float4 rb[2];

    auto loadM = [&](int k0) {
        *reinterpret_cast<int4*>(mm0) = *reinterpret_cast<const int4*>(adjb + am * Nn + k0 + aq);
        *reinterpret_cast<int4*>(mm1) = *reinterpret_cast<const int4*>(adjb + (am + 64) * Nn + k0 + aq);
    };
    auto loadB = [&](int k0) {
        #pragma unroll
        for (int jj2 = 0; jj2 < 2; jj2++) {
            const int gc = col0 + bn4 + 64 * jj2;
            if (gc + 4 <= HID) {
                rb[jj2] = *reinterpret_cast<const float4*>(Bp + (size_t)(k0 + bk) * HID + gc);
            } else {
                rb[jj2].x = (gc + 0 < HID) ? Bp[(size_t)(k0 + bk) * HID + gc + 0] : 0.f;
                rb[jj2].y = (gc + 1 < HID) ? Bp[(size_t)(k0 + bk) * HID + gc + 1] : 0.f;
                rb[jj2].z = (gc + 2 < HID) ? Bp[(size_t)(k0 + bk) * HID + gc + 2] : 0.f;
                rb[jj2].w = (gc + 3 < HID) ? Bp[(size_t)(k0 + bk) * HID + gc + 3] : 0.f;
            }
        }
    };
    auto genStore = [&](int k0, int buf) {
        #pragma unroll
        for (int q = 0; q < 4; q++) {
            const float dv = dd[k0 + aq + q];
            float e0 = sm0 + dv; e0 = (e0 > 0.f) ? e0 : ALPHA * e0;
            float e1 = sm1 + dv; e1 = (e1 > 0.f) ? e1 : ALPHA * e1;
            float p0 = (mm0[q] > 0) ? __expf(e0) : 0.f;
            float p1 = (mm1[q] > 0) ? __expf(e1) : 0.f;
            rs0 += p0; rs1 += p1;
            As[buf][aq + q][am] = p0;
            As[buf][aq + q][am + 64] = p1;
        }
    };
    auto storeB = [&](int buf) {
        #pragma unroll
        for (int jj2 = 0; jj2 < 2; jj2++)
            *reinterpret_cast<float4*>(&Bs[buf][bk][bn4 + 64 * jj2]) = rb[jj2];
    };

    unsigned long long acc[8][4];
    #pragma unroll
    for (int i = 0; i < 8; i++)
        #pragma unroll
        for (int j = 0; j < 4; j++) acc[i][j] = 0ull;

    loadM(0); loadB(0);
    genStore(0, 0); storeB(0);
    __syncthreads();

    for (int s = 0; s < 8; s++) {
        const int cur = s & 1;
        if (s < 7) { loadM((s + 1) << 4); loadB((s + 1) << 4); }
        #pragma unroll
        for (int k = 0; k < 16; k++) {
            unsigned long long aL[8], b2[4];
            #pragma unroll
            for (int ii = 0; ii < 4; ii++) {
                const unsigned long long pr = ld2(&As[cur][k][2 * ty + 32 * ii]);
                aL[2 * ii]     = dup2(lo32(pr));
                aL[2 * ii + 1] = dup2(hi32(pr));
            }
            #pragma unroll
            for (int jj = 0; jj < 4; jj++) b2[jj] = ld2(&Bs[cur][k][2 * (tx + 16 * jj)]);
            #pragma unroll
            for (int i = 0; i < 8; i++)
                #pragma unroll
                for (int jj = 0; jj < 4; jj++)
                    FMA2(acc[i][jj], aL[i], b2[jj]);
        }
        if (s < 7) { genStore((s + 1) << 4, cur ^ 1); storeB(cur ^ 1); }
        __syncthreads();
    }

    atomicAdd(&rsum[am], rs0);
    atomicAdd(&rsum[am + 64], rs1);
    __syncthreads();

    float* Cb = g_O + (size_t)b * Nn * HID;
    #pragma unroll
    for (int i = 0; i < 8; i++) {
        const int r = 2 * ty + 32 * (i >> 1) + (i & 1);
        const float inv = 1.f / rsum[r];
        #pragma unroll
        for (int jj = 0; jj < 4; jj++) {
            const int c = col0 + 2 * (tx + 16 * jj);
            if (c < HID) {
                float v0 = lo32(acc[i][jj]) * inv;
                float v1 = hi32(acc[i][jj]) * inv;
                v0 = (v0 > 0.f) ? v0 : expm1f(v0);
                v1 = (v1 > 0.f) ? v1 : expm1f(v1);
                *reinterpret_cast<float2*>(Cb + (size_t)r * HID + c) = make_float2(v0, v1);
            }
        }
    }
}

// ---------------- ls2 -------------------------------------------------------------
__global__ __launch_bounds__(256) void ls2_kernel()
{
    __shared__ float acc[8 * HID];
    const int b = blockIdx.x;
    const int tid = threadIdx.x, warp = tid >> 5, lane = tid & 31;
    for (int t = tid; t < 8 * HID; t += 256) acc[t] = 0.f;
    __syncthreads();

    const float* O = g_O + (size_t)b * Nn * HID;
    float* accw = acc + warp * HID;
    for (int i = warp; i < 128; i += 8) {
        float o[10];
        #pragma unroll
        for (int t = 0; t < 10; t++) {
            int d = lane + 32 * t;
            o[t] = (d < HID) ? O[(size_t)i * HID + d] : -1e30f;
        }
        float m = o[0];
        #pragma unroll
        for (int t = 1; t < 10; t++) m = fmaxf(m, o[t]);
        m = warp_max(m);
        m = __shfl_sync(0xffffffffu, m, 0);
        float se = 0.f;
        #pragma unroll
        for (int t = 0; t < 10; t++) se += __expf(o[t] - m);
        se = warp_sum(se);
        se = __shfl_sync(0xffffffffu, se, 0);
        const float lse = m + logf(se);
        #pragma unroll
        for (int t = 0; t < 10; t++) {
            int d = lane + 32 * t;
            if (d < HID) accw[d] += o[t] - lse;
        }
    }
    __syncthreads();
    for (int d = tid; d < HID; d += 256) {
        float s = 0.f;
        #pragma unroll
        for (int w = 0; w < 8; w++) s += acc[w * HID + d];
        g_gat[b * HID + d] = s * (1.f / 128.f);
    }
}

// ---------------- head ------------------------------------------------------------
#define HB 4
__global__ __launch_bounds__(256) void head_fused(
    const float* __restrict__ fc2_w, const float* __restrict__ fc2_b,
    const float* __restrict__ Wg,    const float* __restrict__ bg,
    const float* __restrict__ Wf,    const float* __restrict__ bf,
    const float* __restrict__ W1,    const float* __restrict__ b1,
    const float* __restrict__ w2,    const float* __restrict__ b2,
    float* __restrict__ out)
{
    __shared__ float t1s [HB][512];
    __shared__ float gats[HB][HID];
    __shared__ float fpns[HB][HID];
    __shared__ float us  [HB][HID];
    __shared__ float vs  [HB][HID];
    __shared__ float ys  [HB][HID];

    const int b0 = blockIdx.x * HB;
    const int tid = threadIdx.x;

    for (int t = tid; t < HB * 512; t += 256) {
        int r = t >> 9;
        t1s[r][t & 511] = g_t1[(size_t)(b0 + r) * FP2 + (t & 511)];
    }
    for (int t = tid; t < HB * HID; t += 256) {
        int r = t / HID, c = t - r * HID;
        gats[r][c] = g_gat[(size_t)(b0 + r) * HID + c];
    }
    __syncthreads();

    for (int c = tid; c < HID; c += 256) {
        float a[HB] = {};
        #pragma unroll 4
        for (int k = 0; k < 512; k++) {
            float w = fc2_w[(size_t)k * HID + c];
            #pragma unroll
            for (int r = 0; r < HB; r++) a[r] = fmaf(t1s[r][k], w, a[r]);
        }
        float bb = fc2_b[c];
        #pragma unroll
        for (int r = 0; r < HB; r++) fpns[r][c] = a[r] + bb;
    }
    __syncthreads();

    for (int c = tid; c < HID; c += 256) {
        float a[HB] = {}, e[HB] = {};
        #pragma unroll 4
        for (int k = 0; k < HID; k++) {
            float wg = Wg[(size_t)k * HID + c];
            float wf = Wf[(size_t)k * HID + c];
            #pragma unroll
            for (int r = 0; r < HB; r++) {
                a[r] = fmaf(gats[r][k], wg, a[r]);
                e[r] = fmaf(fpns[r][k], wf, e[r]);
            }
        }
        float bbg = bg[c], bbf = bf[c];
        #pragma unroll
        for (int r = 0; r < HB; r++) {
            us[r][c] = fmaxf(a[r] + bbg, 0.f);
            vs[r][c] = fmaxf(e[r] + bbf, 0.f);
        }
    }
    __syncthreads();

    for (int c = tid; c < HID; c += 256) {
        float a[HB] = {};
        #pragma unroll 4
        for (int k = 0; k < HID; k++) {
            float w = W1[(size_t)k * HID + c];
            #pragma unroll
            for (int r = 0; r < HB; r++) a[r] = fmaf(us[r][k], w, a[r]);
        }
        #pragma unroll 4
        for (int k = 0; k < HID; k++) {
            float w = W1[(size_t)(k + HID) * HID + c];
            #pragma unroll
            for (int r = 0; r < HB; r++) a[r] = fmaf(vs[r][k], w, a[r]);
        }
        float bb = b1[c];
        #pragma unroll
        for (int r = 0; r < HB; r++) ys[r][c] = fmaxf(a[r] + bb, 0.f);
    }
    __syncthreads();

    const int warp = tid >> 5, lane = tid & 31;
    if (warp < HB) {
        float s = 0.f;
        for (int k = lane; k < HID; k += 32) s = fmaf(ys[warp][k], w2[k], s);
        s = warp_sum(s);
        if (lane == 0) out[b0 + warp] = 1.f / (1.f + expf(-(s + b2[0])));
    }
}

// ---------------- launch ----------------
extern "C" void kernel_launch(void* const* d_in, const int* in_sizes, int n_in,
                              void* d_out, int out_size)
{
    const float* atom_feats = (const float*)d_in[0];
    const float* fp         = (const float*)d_in[1];
    const float* W_heads    = (const float*)d_in[2];
    const float* a_heads    = (const float*)d_in[3];
    const float* W_out      = (const float*)d_in[4];
    const float* a_out      = (const float*)d_in[5];
    const float* fc1_w      = (const float*)d_in[6];
    const float* fc1_b      = (const float*)d_in[7];
    const float* fc2_w      = (const float*)d_in[8];
    const float* fc2_b      = (const float*)d_in[9];
    const float* fc_gat_w   = (const float*)d_in[10];
    const float* fc_gat_b   = (const float*)d_in[11];
    const float* fc_fpn_w   = (const float*)d_in[12];
    const float* fc_fpn_b   = (const float*)d_in[13];
    const float* ffn_w1     = (const float*)d_in[14];
    const float* ffn_b1     = (const float*)d_in[15];
    const float* ffn_w2     = (const float*)d_in[16];
    const float* ffn_b2     = (const float*)d_in[17];
    const int*   adj        = (const int*)  d_in[18];
    float* out = (float*)d_out;

    __nv_bfloat16 *pApk, *pBpk1, *pHpk, *pBpk3;
    float *pWh, *pWh2, *pFp, *pW1, *pPart;
    cudaGetSymbolAddress((void**)&pApk,  g_Apk);
    cudaGetSymbolAddress((void**)&pBpk1, g_Bpk1);
    cudaGetSymbolAddress((void**)&pWh,   g_Wh);
    cudaGetSymbolAddress((void**)&pHpk,  g_hpk);
    cudaGetSymbolAddress((void**)&pBpk3, g_Bpk3);
    cudaGetSymbolAddress((void**)&pWh2,  g_Wh2);
    cudaGetSymbolAddress((void**)&pFp,   g_fppad);
    cudaGetSymbolAddress((void**)&pW1,   g_w1pad);
    cudaGetSymbolAddress((void**)&pPart, g_part);

    // 1-3: packing / padding
    pack_atoms<<<(Bsz * Nn * K1P + 255) / 256, 256>>>(atom_feats);
    pack_B1<<<(HD * K1P + 255) / 256, 256>>>(W_heads);
    pad_fp<<<(Bsz * KP1 + 255) / 256, 256>>>(fp);
    // 4: K1 on HMMA tensor cores (split bf16)   <-- ncu capture target
    mma_gemm<<<dim3(HD / 128, (Bsz * Nn) / 128), 256>>>(
        pApk, pBpk1, pWh, K1T, HD, HD);
    // 5: gat1 fused (writes packed h)
    gat1_fused<<<Bsz * Hh, 256>>>(a_heads, adj);
    // 6,7: more prep
    pack_B3<<<(N3P * HD + 255) / 256, 256>>>(W_out);
    pad_w1<<<(KP1 * FP2 + 255) / 256, 256>>>(fc1_w);
    // 8,9: fc1 split-K + reduce (fp32x2 path)
    gemm_p2<4, 0><<<dim3(FP2 / 128, Bsz / 128, FSPLIT), 256>>>(
        pFp, pW1, pPart, Bsz, FP2, FCHUNK, KP1, FP2, FP2,
        (long long)FCHUNK, (long long)FCHUNK * FP2, (long long)Bsz * FP2);
    fc1_reduce<<<(Bsz * FP2 + 255) / 256, 256>>>(fc1_b);
    // 10: K3 on HMMA tensor cores (split bf16)
    mma_gemm<<<dim3(N3P / 128, (Bsz * Nn) / 128), 256>>>(
        pHpk, pBpk3, pWh2, K3T, HID, HID);
    // 11: gat2 scores
    score2_kernel<<<Bsz, 256>>>(a_out);
    // 12: gat2 fused probs + AV + elu
    av2f<<<dim3(3, 1, Bsz), 256>>>(adj);
    // 13: gat2 log_softmax + mean
    ls2_kernel<<<Bsz, 256>>>();
    // 14: fused head
    head_fused<<<Bsz / HB, 256>>>(
        fc2_w, fc2_b, fc_gat_w, fc_gat_b, fc_fpn_w, fc_fpn_b,
        ffn_w1, ffn_b1, ffn_w2, ffn_b2, out);
}

// round 11
// speedup vs baseline: 2.1524x; 1.0784x over previous
#include <cuda_runtime.h>
#include <cuda_bf16.h>
#include <math.h>

// Problem constants
#define Bsz 256
#define Nn  128
#define Ff  133
#define Hh  8
#define NHID 64
#define HID 300
#define FP_DIM 1489
#define FP2 512
#define HD (Hh*NHID)     // 512
#define ALPHA 0.2f
#define NEGV (-9e15f)

#define K1P   160        // Ff padded so 3*K1P % 32 == 0
#define K1T   (3*K1P)    // 480
#define K3T   (3*HD)     // 1536
#define N3P   384        // HID padded to 3 tiles of 128
#define KF    1536       // FP_DIM padded
#define KFT   (3*KF)     // 4608
#define FS1   4          // fc1 split-K
#define KC1   (KFT/FS1)  // 1152

// ---------------- scratch (device globals) ----------------------------------------
__device__ __nv_bfloat16 g_Apk [(size_t)Bsz*Nn * K1T];
__device__ __nv_bfloat16 g_Bpk1[(size_t)HD * K1T];
__device__ float         g_Wh  [(size_t)Bsz*Nn * HD];
__device__ __nv_bfloat16 g_hpk [(size_t)Bsz*Nn * K3T];
__device__ __nv_bfloat16 g_Bpk3[(size_t)N3P * K3T];
__device__ float g_Wh2 [(size_t)Bsz*Nn * HID];
__device__ float g_ss2 [Bsz * Nn];
__device__ float g_dd2 [Bsz * Nn];
__device__ float g_O   [(size_t)Bsz*Nn * HID];
__device__ float g_gat [Bsz * HID];
__device__ __nv_bfloat16 g_fpk [(size_t)Bsz * KFT];
__device__ __nv_bfloat16 g_w1k [(size_t)FP2 * KFT];
__device__ float g_part[(size_t)FS1 * Bsz * FP2];
__device__ float g_t1  [Bsz * FP2];

// ---------------- helpers ----------------
#define FMA2(acc, a, b) \
    asm("fma.rn.f32x2 %0, %1, %2, %0;" : "+l"(acc) : "l"(a), "l"(b))

__device__ __forceinline__ unsigned long long ld2(const float* p) {
    return *reinterpret_cast<const unsigned long long*>(p);
}
__device__ __forceinline__ unsigned long long dup2(float x) {
    unsigned long long r;
    asm("mov.b64 %0, {%1, %1};" : "=l"(r) : "r"(__float_as_uint(x)));
    return r;
}
__device__ __forceinline__ float lo32(unsigned long long v) {
    return __uint_as_float((unsigned)v);
}
__device__ __forceinline__ float hi32(unsigned long long v) {
    return __uint_as_float((unsigned)(v >> 32));
}
__device__ __forceinline__ float warp_sum(float v) {
    #pragma unroll
    for (int o = 16; o; o >>= 1) v += __shfl_down_sync(0xffffffffu, v, o);
    return v;
}
__device__ __forceinline__ float warp_max(float v) {
    #pragma unroll
    for (int o = 16; o; o >>= 1) v = fmaxf(v, __shfl_down_sync(0xffffffffu, v, o));
    return v;
}
__device__ __forceinline__ unsigned smem_u32(const void* p) {
    unsigned a;
    asm("{ .reg .u64 t; cvta.to.shared.u64 t, %1; cvt.u32.u64 %0, t; }" : "=r"(a) : "l"(p));
    return a;
}
__device__ __forceinline__ void ldsm4(const __nv_bfloat16* p,
                                      unsigned& r0, unsigned& r1, unsigned& r2, unsigned& r3) {
    unsigned a = smem_u32(p);
    asm volatile("ldmatrix.sync.aligned.m8n8.x4.shared.b16 {%0,%1,%2,%3}, [%4];"
                 : "=r"(r0), "=r"(r1), "=r"(r2), "=r"(r3) : "r"(a));
}

// ================= mma_gemm: bf16 HMMA GEMM, 128x128 tile, KC=32, ldmatrix ======
// C(f32 [..][ldc]) = A(bf16 [M][lda]) @ B(bf16 [Ncover][ldb])^T over KC*? columns.
// KC (=Ktot arg) % 32 == 0. Batched via blockIdx.z with element offsets bA/bB/bC.
#define MSTR 40   // smem row stride in bf16 (80B, 16B aligned, conflict-free ldmatrix)
__global__ __launch_bounds__(256) void mma_gemm(
    const __nv_bfloat16* __restrict__ A, const __nv_bfloat16* __restrict__ B,
    float* __restrict__ C, int Ktot, int lda, int ldb, int Nreal, int ldc,
    long long bA, long long bB, long long bC)
{
    __shared__ __align__(16) __nv_bfloat16 As[2][128][MSTR];
    __shared__ __align__(16) __nv_bfloat16 Bs[2][128][MSTR];

    A += (long long)blockIdx.z * bA;
    B += (long long)blockIdx.z * bB;
    C += (long long)blockIdx.z * bC;

    const int tid = threadIdx.x;
    const int wid = tid >> 5, lane = tid & 31;
    const int wy = wid & 3, wx = wid >> 2;        // warp tile rows wy*32, cols wx*64
    const int gid = lane >> 3 ? 0 : 0;            // (unused)
    const int lq = lane & 7, lg8 = (lane >> 3) & 1, lg16 = lane >> 4;
    const int fgid = lane >> 2, ftig = lane & 3;  // fragment row/col within matrices
    const int row0 = blockIdx.y * 128, col0 = blockIdx.x * 128;

    const int lr0 = tid >> 2;                     // 0..63
    const int lcq = (tid & 3) << 3;               // 0,8,16,24

    uint4 va0, va1, vb0, vb1;
    auto load_g = [&](int k0) {
        va0 = *reinterpret_cast<const uint4*>(A + (size_t)(row0 + lr0) * lda + k0 + lcq);
        va1 = *reinterpret_cast<const uint4*>(A + (size_t)(row0 + lr0 + 64) * lda + k0 + lcq);
        vb0 = *reinterpret_cast<const uint4*>(B + (size_t)(col0 + lr0) * ldb + k0 + lcq);
        vb1 = *reinterpret_cast<const uint4*>(B + (size_t)(col0 + lr0 + 64) * ldb + k0 + lcq);
    };
    auto store_s = [&](int buf) {
        *reinterpret_cast<uint4*>(&As[buf][lr0][lcq])      = va0;
        *reinterpret_cast<uint4*>(&As[buf][lr0 + 64][lcq]) = va1;
        *reinterpret_cast<uint4*>(&Bs[buf][lr0][lcq])      = vb0;
        *reinterpret_cast<uint4*>(&Bs[buf][lr0 + 64][lcq]) = vb1;
    };

    float acc[2][8][4];
    #pragma unroll
    for (int mt = 0; mt < 2; mt++)
        #pragma unroll
        for (int nt = 0; nt < 8; nt++)
            #pragma unroll
            for (int q = 0; q < 4; q++) acc[mt][nt][q] = 0.f;

    const int nsteps = Ktot >> 5;
    load_g(0);
    store_s(0);
    __syncthreads();

    for (int s = 0; s < nsteps; s++) {
        const int cur = s & 1;
        if (s + 1 < nsteps) load_g((s + 1) << 5);

        #pragma unroll
        for (int kk = 0; kk < 32; kk += 16) {
            unsigned af[2][4], bfr[8][2];
            #pragma unroll
            for (int mt = 0; mt < 2; mt++) {
                const int r = wy * 32 + mt * 16 + lq + 8 * lg8;
                ldsm4(&As[cur][r][kk + 8 * lg16],
                      af[mt][0], af[mt][1], af[mt][2], af[mt][3]);
            }
            #pragma unroll
            for (int p = 0; p < 4; p++) {
                const int r = wx * 64 + p * 16 + lq + 8 * lg8;
                unsigned r0, r1, r2, r3;
                ldsm4(&Bs[cur][r][kk + 8 * lg16], r0, r1, r2, r3);
                bfr[2 * p][0] = r0; bfr[2 * p + 1][0] = r1;
                bfr[2 * p][1] = r2; bfr[2 * p + 1][1] = r3;
            }
            #pragma unroll
            for (int mt = 0; mt < 2; mt++)
                #pragma unroll
                for (int nt = 0; nt < 8; nt++)
                    asm volatile(
                        "mma.sync.aligned.m16n8k16.row.col.f32.bf16.bf16.f32 "
                        "{%0,%1,%2,%3}, {%4,%5,%6,%7}, {%8,%9}, {%0,%1,%2,%3};"
                        : "+f"(acc[mt][nt][0]), "+f"(acc[mt][nt][1]),
                          "+f"(acc[mt][nt][2]), "+f"(acc[mt][nt][3])
                        : "r"(af[mt][0]), "r"(af[mt][1]), "r"(af[mt][2]), "r"(af[mt][3]),
                          "r"(bfr[nt][0]), "r"(bfr[nt][1]));
        }

        if (s + 1 < nsteps) store_s(cur ^ 1);
        __syncthreads();
    }

    #pragma unroll
    for (int mt = 0; mt < 2; mt++) {
        const int r0 = row0 + wy * 32 + mt * 16 + fgid;
        #pragma unroll
        for (int nt = 0; nt < 8; nt++) {
            const int c = col0 + wx * 64 + nt * 8 + 2 * ftig;
            if (c < Nreal) {
                *reinterpret_cast<float2*>(C + (size_t)r0 * ldc + c) =
                    make_float2(acc[mt][nt][0], acc[mt][nt][1]);
                *reinterpret_cast<float2*>(C + (size_t)(r0 + 8) * ldc + c) =
                    make_float2(acc[mt][nt][2], acc[mt][nt][3]);
            }
        }
    }
}

// ---------------- packing kernels ------------------------------------------------
__global__ void pack_atoms(const float* __restrict__ src) {
    int t = blockIdx.x * blockDim.x + threadIdx.x;
    if (t >= Bsz * Nn * K1P) return;
    int k = t % K1P, r = t / K1P;
    float x = (k < Ff) ? src[(size_t)r * Ff + k] : 0.f;
    __nv_bfloat16 hi = __float2bfloat16(x);
    __nv_bfloat16 lo = __float2bfloat16(x - __bfloat162float(hi));
    __nv_bfloat16* row = g_Apk + (size_t)r * K1T;
    row[k] = hi; row[K1P + k] = hi; row[2 * K1P + k] = lo;
}
__global__ void pack_B1(const float* __restrict__ W_heads) {
    int t = blockIdx.x * blockDim.x + threadIdx.x;
    if (t >= HD * K1P) return;
    int k = t % K1P, n = t / K1P;
    int h = n >> 6, d = n & 63;
    float x = (k < Ff) ? W_heads[((size_t)h * Ff + k) * NHID + d] : 0.f;
    __nv_bfloat16 hi = __float2bfloat16(x);
    __nv_bfloat16 lo = __float2bfloat16(x - __bfloat162float(hi));
    __nv_bfloat16* row = g_Bpk1 + (size_t)n * K1T;
    row[k] = hi; row[K1P + k] = lo; row[2 * K1P + k] = hi;
}
__global__ void pack_B3(const float* __restrict__ W_out) {
    int t = blockIdx.x * blockDim.x + threadIdx.x;
    if (t >= N3P * HD) return;
    int k = t % HD, n = t / HD;
    float x = (n < HID) ? W_out[(size_t)k * HID + n] : 0.f;
    __nv_bfloat16 hi = __float2bfloat16(x);
    __nv_bfloat16 lo = __float2bfloat16(x - __bfloat162float(hi));
    __nv_bfloat16* row = g_Bpk3 + (size_t)n * K3T;
    row[k] = hi; row[HD + k] = lo; row[2 * HD + k] = hi;
}
__global__ void pack_fp(const float* __restrict__ fp) {
    int t = blockIdx.x * blockDim.x + threadIdx.x;
    if (t >= Bsz * KF) return;
    int k = t % KF, r = t / KF;
    float x = (k < FP_DIM) ? fp[(size_t)r * FP_DIM + k] : 0.f;
    __nv_bfloat16 hi = __float2bfloat16(x);
    __nv_bfloat16 lo = __float2bfloat16(x - __bfloat162float(hi));
    __nv_bfloat16* row = g_fpk + (size_t)r * KFT;
    row[k] = hi; row[KF + k] = hi; row[2 * KF + k] = lo;
}
__global__ void pack_w1k(const float* __restrict__ w) {
    int t = blockIdx.x * blockDim.x + threadIdx.x;
    if (t >= FP2 * KF) return;
    int k = t % KF, n = t / KF;
    float x = (k < FP_DIM) ? w[(size_t)k * FP2 + n] : 0.f;
    __nv_bfloat16 hi = __float2bfloat16(x);
    __nv_bfloat16 lo = __float2bfloat16(x - __bfloat162float(hi));
    __nv_bfloat16* row = g_w1k + (size_t)n * KFT;
    row[k] = hi; row[KF + k] = lo; row[2 * KF + k] = hi;
}

// ---------------- fc1 reduce ------------------------------------------------------
__global__ void fc1_reduce(const float* __restrict__ fc1_b) {
    int t = blockIdx.x * blockDim.x + threadIdx.x;
    if (t >= Bsz * FP2) return;
    float s = 0.f;
    #pragma unroll
    for (int z = 0; z < FS1; z++) s += g_part[(size_t)z * Bsz * FP2 + t];
    g_t1[t] = fmaxf(s + fc1_b[t & (FP2 - 1)], 0.f);
}

// ============ gat1_fused: scores + on-the-fly probs + AV GEMM + elu ==============
__global__ __launch_bounds__(256) void gat1_fused(const float* __restrict__ a_heads,
                                                  const int* __restrict__ adj)
{
    __shared__ __align__(16) float Ws[128 * 68];
    __shared__ __align__(16) float As[2][16][132];
    __shared__ float ss[128], dd[128], rsum[128];

    const int z = blockIdx.x;
    const int b = z >> 3, h = z & 7;
    const int tid = threadIdx.x, warp = tid >> 5, lane = tid & 31;
    const float* whbase = g_Wh + ((size_t)b * Nn) * HD + h * NHID;

    for (int s = tid; s < 2048; s += 256) {
        int j = s >> 4, q = (s & 15) << 2;
        float4 v = *reinterpret_cast<const float4*>(whbase + (size_t)j * HD + q);
        *reinterpret_cast<float4*>(&Ws[j * 68 + q]) = v;
    }
    if (tid < 128) rsum[tid] = 0.f;
    __syncthreads();

    const float* a1 = a_heads + h * (2 * NHID);
    const float* a2v = a1 + NHID;
    for (int j = warp; j < 128; j += 8) {
        const float w0 = Ws[j * 68 + lane];
        const float w1 = Ws[j * 68 + lane + 32];
        float s1 = fmaf(w0, a1[lane], w1 * a1[lane + 32]);
        float s2 = fmaf(w0, a2v[lane], w1 * a2v[lane + 32]);
        s1 = warp_sum(s1); s2 = warp_sum(s2);
        if (lane == 0) { ss[j] = s1; dd[j] = s2; }
    }
    __syncthreads();

    const int* adjb = adj + (size_t)b * Nn * Nn;
    const int am = tid >> 2;
    const int aq = (tid & 3) << 2;
    const float sm0 = ss[am], sm1 = ss[am + 64];
    float rs0 = 0.f, rs1 = 0.f;
    int mm0[4], mm1[4];

    auto loadM = [&](int k0) {
        *reinterpret_cast<int4*>(mm0) = *reinterpret_cast<const int4*>(adjb + am * Nn + k0 + aq);
        *reinterpret_cast<int4*>(mm1) = *reinterpret_cast<const int4*>(adjb + (am + 64) * Nn + k0 + aq);
    };
    auto genStore = [&](int k0, int buf) {
        #pragma unroll
        for (int q = 0; q < 4; q++) {
            const float dv = dd[k0 + aq + q];
            float e0 = sm0 + dv; e0 = (e0 > 0.f) ? e0 : ALPHA * e0;
            float e1 = sm1 + dv; e1 = (e1 > 0.f) ? e1 : ALPHA * e1;
            float p0 = (mm0[q] > 0) ? __expf(e0) : 0.f;
            float p1 = (mm1[q] > 0) ? __expf(e1) : 0.f;
            rs0 += p0; rs1 += p1;
            As[buf][aq + q][am] = p0;
            As[buf][aq + q][am + 64] = p1;
        }
    };

    const int tx = tid & 15, ty = tid >> 4;
    unsigned long long acc[8][2];
    #pragma unroll
    for (int i = 0; i < 8; i++) { acc[i][0] = 0ull; acc[i][1] = 0ull; }

    loadM(0);
    genStore(0, 0);
    __syncthreads();

    for (int s = 0; s < 8; s++) {
        const int cur = s & 1;
        if (s < 7) loadM((s + 1) << 4);
        #pragma unroll
        for (int k = 0; k < 16; k++) {
            unsigned long long aL[8], b2[2];
            #pragma unroll
            for (int ii = 0; ii < 4; ii++) {
                const unsigned long long pr = ld2(&As[cur][k][2 * ty + 32 * ii]);
                aL[2 * ii]     = dup2(lo32(pr));
                aL[2 * ii + 1] = dup2(hi32(pr));
            }
            b2[0] = ld2(&Ws[(s * 16 + k) * 68 + 2 * tx]);
            b2[1] = ld2(&Ws[(s * 16 + k) * 68 + 2 * tx + 32]);
            #pragma unroll
            for (int i = 0; i < 8; i++) {
                FMA2(acc[i][0], aL[i], b2[0]);
                FMA2(acc[i][1], aL[i], b2[1]);
            }
        }
        if (s < 7) genStore((s + 1) << 4, cur ^ 1);
        __syncthreads();
    }

    atomicAdd(&rsum[am], rs0);
    atomicAdd(&rsum[am + 64], rs1);
    __syncthreads();

    #pragma unroll
    for (int i = 0; i < 8; i++) {
        const int r = 2 * ty + 32 * (i >> 1) + (i & 1);
        const float inv = 1.f / rsum[r];
        __nv_bfloat16* rowp = g_hpk + (size_t)(b * Nn + r) * K3T + h * NHID;
        #pragma unroll
        for (int jj = 0; jj < 2; jj++) {
            const int c = 2 * (tx + 16 * jj);
            float v0 = lo32(acc[i][jj]) * inv;
            float v1 = hi32(acc[i][jj]) * inv;
            v0 = (v0 > 0.f) ? v0 : expm1f(v0);
            v1 = (v1 > 0.f) ? v1 : expm1f(v1);
            __nv_bfloat16 h0 = __float2bfloat16(v0);
            __nv_bfloat16 h1 = __float2bfloat16(v1);
            __nv_bfloat16 l0 = __float2bfloat16(v0 - __bfloat162float(h0));
            __nv_bfloat16 l1 = __float2bfloat16(v1 - __bfloat162float(h1));
            unsigned hp = (unsigned)__bfloat16_as_ushort(h0) | ((unsigned)__bfloat16_as_ushort(h1) << 16);
            unsigned lp = (unsigned)__bfloat16_as_ushort(l0) | ((unsigned)__bfloat16_as_ushort(l1) << 16);
            *reinterpret_cast<unsigned*>(rowp + c)           = hp;
            *reinterpret_cast<unsigned*>(rowp + HD + c)      = hp;
            *reinterpret_cast<unsigned*>(rowp + 2 * HD + c)  = lp;
        }
    }
}

// ---------------- score2 ----------------------------------------------------------
__global__ __launch_bounds__(256) void score2_kernel(const float* __restrict__ a_out)
{
    const int b = blockIdx.x;
    const int tid = threadIdx.x, warp = tid >> 5, lane = tid & 31;
    const float* W = g_Wh2 + (size_t)b * Nn * HID;
    for (int j = warp; j < 128; j += 8) {
        float s1 = 0.f, s2 = 0.f;
        #pragma unroll
        for (int t = 0; t < 10; t++) {
            int d = lane + 32 * t;
            if (d < HID) {
                float w = W[(size_t)j * HID + d];
                s1 = fmaf(w, a_out[d], s1);
                s2 = fmaf(w, a_out[HID + d], s2);
            }
        }
        s1 = warp_sum(s1); s2 = warp_sum(s2);
        if (lane == 0) { g_ss2[b * Nn + j] = s1; g_dd2[b * Nn + j] = s2; }
    }
}

// ============ av2f: gat2 on-the-fly probs + AV GEMM + elu ========================
__global__ __launch_bounds__(256) void av2f(const int* __restrict__ adj)
{
    __shared__ __align__(16) float As[2][16][132];
    __shared__ __align__(16) float Bs[2][16][132];
    __shared__ float ss[128], dd[128], rsum[128];

    const int b = blockIdx.z;
    const int col0 = blockIdx.x * 128;
    const int tid = threadIdx.x;
    const int tx = tid & 15, ty = tid >> 4;
    const int am = tid >> 2, aq = (tid & 3) << 2;
    const int bk = tid >> 4, bn4 = (tid & 15) << 2;

    if (tid < 128) {
        ss[tid] = g_ss2[b * Nn + tid];
        dd[tid] = g_dd2[b * Nn + tid];
        rsum[tid] = 0.f;
    }
    __syncthreads();

    const float* Bp = g_Wh2 + (size_t)b * Nn * HID;
    const int* adjb = adj + (size_t)b * Nn * Nn;
    const float sm0 = ss[am], sm1 = ss[am + 64];
    float rs0 = 0.f, rs1 = 0.f;
    int mm0[4], mm1[4];
    float4 rb[2];

    auto loadM = [&](int k0) {
        *reinterpret_cast<int4*>(mm0) = *reinterpret_cast<const int4*>(adjb + am * Nn + k0 + aq);
        *reinterpret_cast<int4*>(mm1) = *reinterpret_cast<const int4*>(adjb + (am + 64) * Nn + k0 + aq);
    };
    auto loadB = [&](int k0) {
        #pragma unroll
        for (int jj2 = 0; jj2 < 2; jj2++) {
            const int gc = col0 + bn4 + 64 * jj2;
            if (gc + 4 <= HID) {
                rb[jj2] = *reinterpret_cast<const float4*>(Bp + (size_t)(k0 + bk) * HID + gc);
            } else {
                rb[jj2].x = (gc + 0 < HID) ? Bp[(size_t)(k0 + bk) * HID + gc + 0] : 0.f;
                rb[jj2].y = (gc + 1 < HID) ? Bp[(size_t)(k0 + bk) * HID + gc + 1] : 0.f;
                rb[jj2].z = (gc + 2 < HID) ? Bp[(size_t)(k0 + bk) * HID + gc + 2] : 0.f;
                rb[jj2].w = (gc + 3 < HID) ? Bp[(size_t)(k0 + bk) * HID + gc + 3] : 0.f;
            }
        }
    };
    auto genStore = [&](int k0, int buf) {
        #pragma unroll
        for (int q = 0; q < 4; q++) {
            const float dv = dd[k0 + aq + q];
            float e0 = sm0 + dv; e0 = (e0 > 0.f) ? e0 : ALPHA * e0;
            float e1 = sm1 + dv; e1 = (e1 > 0.f) ? e1 : ALPHA * e1;
            float p0 = (mm0[q] > 0) ? __expf(e0) : 0.f;
            float p1 = (mm1[q] > 0) ? __expf(e1) : 0.f;
            rs0 += p0; rs1 += p1;
            As[buf][aq + q][am] = p0;
            As[buf][aq + q][am + 64] = p1;
        }
    };
    auto storeB = [&](int buf) {
        #pragma unroll
        for (int jj2 = 0; jj2 < 2; jj2++)
            *reinterpret_cast<float4*>(&Bs[buf][bk][bn4 + 64 * jj2]) = rb[jj2];
    };

    unsigned long long acc[8][4];
    #pragma unroll
    for (int i = 0; i < 8; i++)
        #pragma unroll
        for (int j = 0; j < 4; j++) acc[i][j] = 0ull;

    loadM(0); loadB(0);
    genStore(0, 0); storeB(0);
    __syncthreads();

    for (int s = 0; s < 8; s++) {
        const int cur = s & 1;
        if (s < 7) { loadM((s + 1) << 4); loadB((s + 1) << 4); }
        #pragma unroll
        for (int k = 0; k < 16; k++) {
            unsigned long long aL[8], b2[4];
            #pragma unroll
            for (int ii = 0; ii < 4; ii++) {
                const unsigned long long pr = ld2(&As[cur][k][2 * ty + 32 * ii]);
                aL[2 * ii]     = dup2(lo32(pr));
                aL[2 * ii + 1] = dup2(hi32(pr));
            }
            #pragma unroll
            for (int jj = 0; jj < 4; jj++) b2[jj] = ld2(&Bs[cur][k][2 * (tx + 16 * jj)]);
            #pragma unroll
            for (int i = 0; i < 8; i++)
                #pragma unroll
                for (int jj = 0; jj < 4; jj++)
                    FMA2(acc[i][jj], aL[i], b2[jj]);
        }
        if (s < 7) { genStore((s + 1) << 4, cur ^ 1); storeB(cur ^ 1); }
        __syncthreads();
    }

    atomicAdd(&rsum[am], rs0);
    atomicAdd(&rsum[am + 64], rs1);
    __syncthreads();

    float* Cb = g_O + (size_t)b * Nn * HID;
    #pragma unroll
    for (int i = 0; i < 8; i++) {
        const int r = 2 * ty + 32 * (i >> 1) + (i & 1);
        const float inv = 1.f / rsum[r];
        #pragma unroll
        for (int jj = 0; jj < 4; jj++) {
            const int c = col0 + 2 * (tx + 16 * jj);
            if (c < HID) {
                float v0 = lo32(acc[i][jj]) * inv;
                float v1 = hi32(acc[i][jj]) * inv;
                v0 = (v0 > 0.f) ? v0 : expm1f(v0);
                v1 = (v1 > 0.f) ? v1 : expm1f(v1);
                *reinterpret_cast<float2*>(Cb + (size_t)r * HID + c) = make_float2(v0, v1);
            }
        }
    }
}

// ---------------- ls2 -------------------------------------------------------------
__global__ __launch_bounds__(256) void ls2_kernel()
{
    __shared__ float acc[8 * HID];
    const int b = blockIdx.x;
    const int tid = threadIdx.x, warp = tid >> 5, lane = tid & 31;
    for (int t = tid; t < 8 * HID; t += 256) acc[t] = 0.f;
    __syncthreads();

    const float* O = g_O + (size_t)b * Nn * HID;
    float* accw = acc + warp * HID;
    for (int i = warp; i < 128; i += 8) {
        float o[10];
        #pragma unroll
        for (int t = 0; t < 10; t++) {
            int d = lane + 32 * t;
            o[t] = (d < HID) ? O[(size_t)i * HID + d] : -1e30f;
        }
        float m = o[0];
        #pragma unroll
        for (int t = 1; t < 10; t++) m = fmaxf(m, o[t]);
        m = warp_max(m);
        m = __shfl_sync(0xffffffffu, m, 0);
        float se = 0.f;
        #pragma unroll
        for (int t = 0; t < 10; t++) se += __expf(o[t] - m);
        se = warp_sum(se);
        se = __shfl_sync(0xffffffffu, se, 0);
        const float lse = m + logf(se);
        #pragma unroll
        for (int t = 0; t < 10; t++) {
            int d = lane + 32 * t;
            if (d < HID) accw[d] += o[t] - lse;
        }
    }
    __syncthreads();
    for (int d = tid; d < HID; d += 256) {
        float s = 0.f;
        #pragma unroll
        for (int w = 0; w < 8; w++) s += acc[w * HID + d];
        g_gat[b * HID + d] = s * (1.f / 128.f);
    }
}

// ---------------- head ------------------------------------------------------------
#define HB 4
__global__ __launch_bounds__(256) void head_fused(
    const float* __restrict__ fc2_w, const float* __restrict__ fc2_b,
    const float* __restrict__ Wg,    const float* __restrict__ bg,
    const float* __restrict__ Wf,    const float* __restrict__ bf,
    const float* __restrict__ W1,    const float* __restrict__ b1,
    const float* __restrict__ w2,    const float* __restrict__ b2,
    float* __restrict__ out)
{
    __shared__ float t1s [HB][512];
    __shared__ float gats[HB][HID];
    __shared__ float fpns[HB][HID];
    __shared__ float us  [HB][HID];
    __shared__ float vs  [HB][HID];
    __shared__ float ys  [HB][HID];

    const int b0 = blockIdx.x * HB;
    const int tid = threadIdx.x;

    for (int t = tid; t < HB * 512; t += 256) {
        int r = t >> 9;
        t1s[r][t & 511] = g_t1[(size_t)(b0 + r) * FP2 + (t & 511)];
    }
    for (int t = tid; t < HB * HID; t += 256) {
        int r = t / HID, c = t - r * HID;
        gats[r][c] = g_gat[(size_t)(b0 + r) * HID + c];
    }
    __syncthreads();

    for (int c = tid; c < HID; c += 256) {
        float a[HB] = {};
        #pragma unroll 4
        for (int k = 0; k < 512; k++) {
            float w = fc2_w[(size_t)k * HID + c];
            #pragma unroll
            for (int r = 0; r < HB; r++) a[r] = fmaf(t1s[r][k], w, a[r]);
        }
        float bb = fc2_b[c];
        #pragma unroll
        for (int r = 0; r < HB; r++) fpns[r][c] = a[r] + bb;
    }
    __syncthreads();

    for (int c = tid; c < HID; c += 256) {
        float a[HB] = {}, e[HB] = {};
        #pragma unroll 4
        for (int k = 0; k < HID; k++) {
            float wg = Wg[(size_t)k * HID + c];
            float wf = Wf[(size_t)k * HID + c];
            #pragma unroll
            for (int r = 0; r < HB; r++) {
                a[r] = fmaf(gats[r][k], wg, a[r]);
                e[r] = fmaf(fpns[r][k], wf, e[r]);
            }
        }
        float bbg = bg[c], bbf = bf[c];
        #pragma unroll
        for (int r = 0; r < HB; r++) {
            us[r][c] = fmaxf(a[r] + bbg, 0.f);
            vs[r][c] = fmaxf(e[r] + bbf, 0.f);
        }
    }
    __syncthreads();

    for (int c = tid; c < HID; c += 256) {
        float a[HB] = {};
        #pragma unroll 4
        for (int k = 0; k < HID; k++) {
            float w = W1[(size_t)k * HID + c];
            #pragma unroll
            for (int r = 0; r < HB; r++) a[r] = fmaf(us[r][k], w, a[r]);
        }
        #pragma unroll 4
        for (int k = 0; k < HID; k++) {
            float w = W1[(size_t)(k + HID) * HID + c];
            #pragma unroll
            for (int r = 0; r < HB; r++) a[r] = fmaf(vs[r][k], w, a[r]);
        }
        float bb = b1[c];
        #pragma unroll
        for (int r = 0; r < HB; r++) ys[r][c] = fmaxf(a[r] + bb, 0.f);
    }
    __syncthreads();

    const int warp = tid >> 5, lane = tid & 31;
    if (warp < HB) {
        float s = 0.f;
        for (int k = lane; k < HID; k += 32) s = fmaf(ys[warp][k], w2[k], s);
        s = warp_sum(s);
        if (lane == 0) out[b0 + warp] = 1.f / (1.f + expf(-(s + b2[0])));
    }
}

// ---------------- launch ----------------
extern "C" void kernel_launch(void* const* d_in, const int* in_sizes, int n_in,
                              void* d_out, int out_size)
{
    const float* atom_feats = (const float*)d_in[0];
    const float* fp         = (const float*)d_in[1];
    const float* W_heads    = (const float*)d_in[2];
    const float* a_heads    = (const float*)d_in[3];
    const float* W_out      = (const float*)d_in[4];
    const float* a_out      = (const float*)d_in[5];
    const float* fc1_w      = (const float*)d_in[6];
    const float* fc1_b      = (const float*)d_in[7];
    const float* fc2_w      = (const float*)d_in[8];
    const float* fc2_b      = (const float*)d_in[9];
    const float* fc_gat_w   = (const float*)d_in[10];
    const float* fc_gat_b   = (const float*)d_in[11];
    const float* fc_fpn_w   = (const float*)d_in[12];
    const float* fc_fpn_b   = (const float*)d_in[13];
    const float* ffn_w1     = (const float*)d_in[14];
    const float* ffn_b1     = (const float*)d_in[15];
    const float* ffn_w2     = (const float*)d_in[16];
    const float* ffn_b2     = (const float*)d_in[17];
    const int*   adj        = (const int*)  d_in[18];
    float* out = (float*)d_out;

    __nv_bfloat16 *pApk, *pBpk1, *pHpk, *pBpk3, *pFpk, *pW1k;
    float *pWh, *pWh2, *pPart;
    cudaGetSymbolAddress((void**)&pApk,  g_Apk);
    cudaGetSymbolAddress((void**)&pBpk1, g_Bpk1);
    cudaGetSymbolAddress((void**)&pWh,   g_Wh);
    cudaGetSymbolAddress((void**)&pHpk,  g_hpk);
    cudaGetSymbolAddress((void**)&pBpk3, g_Bpk3);
    cudaGetSymbolAddress((void**)&pWh2,  g_Wh2);
    cudaGetSymbolAddress((void**)&pFpk,  g_fpk);
    cudaGetSymbolAddress((void**)&pW1k,  g_w1k);
    cudaGetSymbolAddress((void**)&pPart, g_part);

    // 1-3: packing
    pack_atoms<<<(Bsz * Nn * K1P + 255) / 256, 256>>>(atom_feats);
    pack_B1<<<(HD * K1P + 255) / 256, 256>>>(W_heads);
    pack_fp<<<(Bsz * KF + 255) / 256, 256>>>(fp);
    // 4: K1 on HMMA (split bf16, ldmatrix)   <-- ncu capture target
    mma_gemm<<<dim3(HD / 128, (Bsz * Nn) / 128, 1), 256>>>(
        pApk, pBpk1, pWh, K1T, K1T, K1T, HD, HD, 0, 0, 0);
    // 5: gat1 fused (writes packed h)
    gat1_fused<<<Bsz * Hh, 256>>>(a_heads, adj);
    // 6,7: more packing
    pack_B3<<<(N3P * HD + 255) / 256, 256>>>(W_out);
    pack_w1k<<<(FP2 * KF + 255) / 256, 256>>>(fc1_w);
    // 8,9: fc1 on HMMA split-K + reduce
    mma_gemm<<<dim3(FP2 / 128, Bsz / 128, FS1), 256>>>(
        pFpk, pW1k, pPart, KC1, KFT, KFT, FP2, FP2,
        (long long)KC1, (long long)KC1, (long long)Bsz * FP2);
    fc1_reduce<<<(Bsz * FP2 + 255) / 256, 256>>>(fc1_b);
    // 10: K3 on HMMA
    mma_gemm<<<dim3(N3P / 128, (Bsz * Nn) / 128, 1), 256>>>(
        pHpk, pBpk3, pWh2, K3T, K3T, K3T, HID, HID, 0, 0, 0);
    // 11: gat2 scores
    score2_kernel<<<Bsz, 256>>>(a_out);
    // 12: gat2 fused probs + AV + elu
    av2f<<<dim3(3, 1, Bsz), 256>>>(adj);
    // 13: gat2 log_softmax + mean
    ls2_kernel<<<Bsz, 256>>>();
    // 14: fused head
    head_fused<<<Bsz / HB, 256>>>(
        fc2_w, fc2_b, fc_gat_w, fc_gat_b, fc_fpn_w, fc_fpn_b,
        ffn_w1, ffn_b1, ffn_w2, ffn_b2, out);
}